// round 2
// baseline (speedup 1.0000x reference)
#include <cuda_runtime.h>
#include <cuda_bf16.h>
#include <math.h>

#define NB 8
#define LQ 4096
#define LK 32768
#define DH 64
#define LKS 8000
#define NU 45
#define NUP 48
#define NCHUNK 32
#define CK 1024   // keys per chunk in attention phase

// ---------------- device scratch (no allocations allowed) ----------------
__device__ float g_Ksamp[NB * LKS * DH];          // gathered sampled K, 16 MB
__device__ float g_Ksum[NB * DH];                 // per-batch sum of sampled K rows
__device__ float g_M[NB * LQ];                    // sparsity measure
__device__ int   g_top[NB * NUP];                 // selected query indices (padded to 48)
__device__ float g_pm[NB * NCHUNK * NUP];         // split-softmax partial max
__device__ float g_pl[NB * NCHUNK * NUP];         // split-softmax partial sumexp
__device__ float g_pacc[NB * NCHUNK * NUP * DH];  // split-softmax partial V-acc

// ---------------- kernel 1: gather K_samp ----------------
__global__ void k_gather(const float* __restrict__ K, const int* __restrict__ idx) {
    int t = blockIdx.x * blockDim.x + threadIdx.x;   // float4 units
    const int total = NB * LKS * DH / 4;
    if (t >= total) return;
    int d4   = t & (DH / 4 - 1);          // 0..15
    int rest = t >> 4;                    // /16
    int u = rest % LKS;
    int b = rest / LKS;
    const float4* src = (const float4*)(K + ((size_t)b * LK + idx[u]) * DH);
    ((float4*)g_Ksamp)[t] = src[d4];
}

// ---------------- kernel 2: Ksum per batch ----------------
__global__ void k_ksum() {
    int b = blockIdx.x;
    int d = threadIdx.x & 63;
    int g = threadIdx.x >> 6;             // 0..3
    float s = 0.f;
    for (int u = g; u < LKS; u += 4)
        s += g_Ksamp[(b * LKS + u) * DH + d];
    __shared__ float red[4][64];
    red[g][d] = s;
    __syncthreads();
    if (g == 0)
        g_Ksum[b * DH + d] = red[0][d] + red[1][d] + red[2][d] + red[3][d];
}

// ---------------- kernel 3: M = max_u(q.k_u) - q.Ksum/LKS ----------------
// block: 128 queries x full 8000 sampled keys, 256 threads, 8m x 4n per thread
__global__ __launch_bounds__(256) void k_M(const float* __restrict__ q) {
    extern __shared__ float sm[];
    float* qsT   = sm;            // [64][132] transposed q tile
    float* ksT   = sm + 64 * 132; // [64][68]  transposed K_samp tile
    float* ksumS = sm + 64 * 132 + 64 * 68; // [64]

    const int tid = threadIdx.x;
    const int ty = tid >> 4;      // 0..15 -> m = 8*ty
    const int tx = tid & 15;      // 0..15 -> n = 4*tx
    const int b  = blockIdx.y;
    const int m0 = blockIdx.x * 128;

    // load q tile transposed: qsT[d][m]
#pragma unroll
    for (int i = 0; i < 8; ++i) {
        int fidx = tid + 256 * i;             // 0..2047
        int m    = fidx >> 4;
        int dblk = fidx & 15;
        float4 v = *(const float4*)(q + ((size_t)(b * LQ + m0 + m)) * DH + 4 * dblk);
        qsT[(4 * dblk + 0) * 132 + m] = v.x;
        qsT[(4 * dblk + 1) * 132 + m] = v.y;
        qsT[(4 * dblk + 2) * 132 + m] = v.z;
        qsT[(4 * dblk + 3) * 132 + m] = v.w;
    }
    if (tid < 64) ksumS[tid] = g_Ksum[b * DH + tid];

    float rmax[8];
#pragma unroll
    for (int i = 0; i < 8; ++i) rmax[i] = -INFINITY;

    for (int nt = 0; nt < LKS / 64; ++nt) {
        __syncthreads();
        // load K_samp tile transposed: ksT[d][n]
#pragma unroll
        for (int i = 0; i < 4; ++i) {
            int fidx = tid + 256 * i;     // 0..1023
            int n    = fidx >> 4;
            int dblk = fidx & 15;
            float4 v = *(const float4*)(g_Ksamp + ((size_t)(b * LKS + nt * 64 + n)) * DH + 4 * dblk);
            ksT[(4 * dblk + 0) * 68 + n] = v.x;
            ksT[(4 * dblk + 1) * 68 + n] = v.y;
            ksT[(4 * dblk + 2) * 68 + n] = v.z;
            ksT[(4 * dblk + 3) * 68 + n] = v.w;
        }
        __syncthreads();

        float acc[8][4];
#pragma unroll
        for (int i = 0; i < 8; ++i)
#pragma unroll
            for (int j = 0; j < 4; ++j) acc[i][j] = 0.f;

#pragma unroll 4
        for (int d = 0; d < 64; ++d) {
            const float* qr = &qsT[d * 132 + 8 * ty];
            float4 a0 = *(const float4*)qr;
            float4 a1 = *(const float4*)(qr + 4);
            float4 bv = *(const float4*)&ksT[d * 68 + 4 * tx];
            float a[8] = {a0.x, a0.y, a0.z, a0.w, a1.x, a1.y, a1.z, a1.w};
            float bb[4] = {bv.x, bv.y, bv.z, bv.w};
#pragma unroll
            for (int i = 0; i < 8; ++i)
#pragma unroll
                for (int j = 0; j < 4; ++j) acc[i][j] += a[i] * bb[j];
        }
#pragma unroll
        for (int i = 0; i < 8; ++i)
#pragma unroll
            for (int j = 0; j < 4; ++j) rmax[i] = fmaxf(rmax[i], acc[i][j]);
    }

    // reduce max across the 16 tx lanes (stay inside 16-lane groups of the warp)
#pragma unroll
    for (int i = 0; i < 8; ++i) {
#pragma unroll
        for (int off = 8; off > 0; off >>= 1)
            rmax[i] = fmaxf(rmax[i], __shfl_xor_sync(0xffffffffu, rmax[i], off));
    }
    if (tx == 0) {
#pragma unroll
        for (int i = 0; i < 8; ++i) {
            int m = 8 * ty + i;
            float dot = 0.f;
            for (int d = 0; d < 64; ++d) dot += qsT[d * 132 + m] * ksumS[d];
            g_M[b * LQ + m0 + m] = rmax[i] - dot * (1.0f / (float)LKS);
        }
    }
}

// ---------------- kernel 4: top-45 smallest M per batch ----------------
__global__ void k_topk() {
    int b = blockIdx.x;
    int tid = threadIdx.x;
    __shared__ float vals[LQ];
    __shared__ float bv[256];
    __shared__ int   bi[256];
    for (int j = tid; j < LQ; j += 256) vals[j] = g_M[b * LQ + j];
    __syncthreads();
    for (int it = 0; it < NU; ++it) {
        float best = INFINITY; int bidx = 0;
        for (int j = tid; j < LQ; j += 256) {
            float v = vals[j];
            if (v < best) { best = v; bidx = j; }   // strict < keeps lowest index
        }
        bv[tid] = best; bi[tid] = bidx;
        __syncthreads();
        for (int s = 128; s > 0; s >>= 1) {
            if (tid < s) {
                float v2 = bv[tid + s]; int i2 = bi[tid + s];
                if (v2 < bv[tid] || (v2 == bv[tid] && i2 < bi[tid])) { bv[tid] = v2; bi[tid] = i2; }
            }
            __syncthreads();
        }
        if (tid == 0) { g_top[b * NUP + it] = bi[0]; vals[bi[0]] = INFINITY; }
        __syncthreads();
    }
    if (tid < NUP - NU) g_top[b * NUP + NU + tid] = 0;  // padding rows
}

// ---------------- kernel 5: scores + flash split-softmax + PV partials ----
// grid (NCHUNK, NB), 256 threads; block owns 1024 keys for all 48 (padded) queries
__global__ __launch_bounds__(256) void k_attn(const float* __restrict__ q,
                                              const float* __restrict__ K,
                                              const float* __restrict__ V,
                                              float* __restrict__ out_s) {
    extern __shared__ float sm[];
    float* qsT   = sm;                          // [64][50]
    float* ksT   = qsT + 64 * 50;               // [64][132]
    float* Vs    = ksT + 64 * 132;              // [128][68]
    float* Ps    = Vs + 128 * 68;               // [48][132]
    float* m_run = Ps + 48 * 132;               // [48]
    float* m_new = m_run + 48;                  // [48]
    float* l_run = m_new + 48;                  // [48]

    const int tid = threadIdx.x;
    const int ty = tid >> 5;                    // 0..7  -> u = 6*ty..
    const int tx = tid & 31;                    // 0..31
    const int b = blockIdx.y;
    const int chunk = blockIdx.x;
    const int kchunk0 = chunk * CK;

    // load 48 selected q rows transposed
#pragma unroll
    for (int i = 0; i < 3; ++i) {
        int fidx = tid + 256 * i;               // 0..767
        int u    = fidx >> 4;
        int dblk = fidx & 15;
        float4 v = make_float4(0.f, 0.f, 0.f, 0.f);
        if (u < NU) {
            int qi = g_top[b * NUP + u];
            v = *(const float4*)(q + ((size_t)(b * LQ + qi)) * DH + 4 * dblk);
        }
        qsT[(4 * dblk + 0) * 50 + u] = v.x;
        qsT[(4 * dblk + 1) * 50 + u] = v.y;
        qsT[(4 * dblk + 2) * 50 + u] = v.z;
        qsT[(4 * dblk + 3) * 50 + u] = v.w;
    }
    if (tid < NUP) { m_run[tid] = -INFINITY; l_run[tid] = 0.f; }

    float acc[6][2];
#pragma unroll
    for (int i = 0; i < 6; ++i) { acc[i][0] = 0.f; acc[i][1] = 0.f; }

    for (int kt = 0; kt < CK / 128; ++kt) {
        const int kg0 = kchunk0 + kt * 128;
        __syncthreads();
        // load K tile transposed + V tile row-major
#pragma unroll
        for (int i = 0; i < 8; ++i) {
            int fidx = tid + 256 * i;           // 0..2047
            int k    = fidx >> 4;
            int dblk = fidx & 15;
            float4 kv = *(const float4*)(K + ((size_t)(b * LK + kg0 + k)) * DH + 4 * dblk);
            ksT[(4 * dblk + 0) * 132 + k] = kv.x;
            ksT[(4 * dblk + 1) * 132 + k] = kv.y;
            ksT[(4 * dblk + 2) * 132 + k] = kv.z;
            ksT[(4 * dblk + 3) * 132 + k] = kv.w;
            float4 vv = *(const float4*)(V + ((size_t)(b * LK + kg0 + k)) * DH + 4 * dblk);
            *(float4*)&Vs[k * 68 + 4 * dblk] = vv;
        }
        __syncthreads();

        // s tile: 6u x 4k per thread
        float s[6][4];
#pragma unroll
        for (int i = 0; i < 6; ++i)
#pragma unroll
            for (int j = 0; j < 4; ++j) s[i][j] = 0.f;

#pragma unroll 4
        for (int d = 0; d < 64; ++d) {
            const float* qr = &qsT[d * 50 + 6 * ty];
            float2 q01 = *(const float2*)(qr);
            float2 q23 = *(const float2*)(qr + 2);
            float2 q45 = *(const float2*)(qr + 4);
            float4 kv  = *(const float4*)&ksT[d * 132 + 4 * tx];
            float qa[6] = {q01.x, q01.y, q23.x, q23.y, q45.x, q45.y};
            float kb[4] = {kv.x, kv.y, kv.z, kv.w};
#pragma unroll
            for (int i = 0; i < 6; ++i)
#pragma unroll
                for (int j = 0; j < 4; ++j) s[i][j] += qa[i] * kb[j];
        }
#pragma unroll
        for (int i = 0; i < 6; ++i)
#pragma unroll
            for (int j = 0; j < 4; ++j) s[i][j] *= 0.125f;   // 1/sqrt(64)

        // write raw scores
#pragma unroll
        for (int i = 0; i < 6; ++i) {
            int u = 6 * ty + i;
            if (u < NU) {
                float4 w = make_float4(s[i][0], s[i][1], s[i][2], s[i][3]);
                *(float4*)(out_s + ((size_t)(b * NU + u)) * LK + kg0 + 4 * tx) = w;
            }
        }

        // per-u subtile max (whole warp owns rows 6*ty..6*ty+5)
#pragma unroll
        for (int i = 0; i < 6; ++i) {
            float mx = fmaxf(fmaxf(s[i][0], s[i][1]), fmaxf(s[i][2], s[i][3]));
#pragma unroll
            for (int off = 16; off > 0; off >>= 1)
                mx = fmaxf(mx, __shfl_xor_sync(0xffffffffu, mx, off));
            if (tx == 0) {
                int u = 6 * ty + i;
                m_new[u] = fmaxf(m_run[u], mx);
            }
        }
        __syncthreads();

#pragma unroll
        for (int i = 0; i < 6; ++i) {
            int u = 6 * ty + i;
            float mn = m_new[u];
            float f  = __expf(m_run[u] - mn);
            float p0 = __expf(s[i][0] - mn);
            float p1 = __expf(s[i][1] - mn);
            float p2 = __expf(s[i][2] - mn);
            float p3 = __expf(s[i][3] - mn);
            float ps = p0 + p1 + p2 + p3;
#pragma unroll
            for (int off = 16; off > 0; off >>= 1)
                ps += __shfl_xor_sync(0xffffffffu, ps, off);
            if (tx == 0) {
                l_run[u] = l_run[u] * f + ps;
                m_run[u] = mn;
            }
            *(float4*)&Ps[u * 132 + 4 * tx] = make_float4(p0, p1, p2, p3);
            acc[i][0] *= f;
            acc[i][1] *= f;
        }
        __syncthreads();

        // PV: acc[u][d] += P[u][k] * V[k][d], d = 2*tx..2*tx+1
#pragma unroll 2
        for (int k = 0; k < 128; k += 2) {
            float2 va = *(const float2*)&Vs[k * 68 + 2 * tx];
            float2 vb = *(const float2*)&Vs[(k + 1) * 68 + 2 * tx];
#pragma unroll
            for (int i = 0; i < 6; ++i) {
                float2 pp = *(const float2*)&Ps[(6 * ty + i) * 132 + k];
                acc[i][0] += pp.x * va.x;
                acc[i][0] += pp.y * vb.x;
                acc[i][1] += pp.x * va.y;
                acc[i][1] += pp.y * vb.y;
            }
        }
    }
    __syncthreads();

    // write partials
    if (tid < NUP) {
        g_pm[(b * NCHUNK + chunk) * NUP + tid] = m_run[tid];
        g_pl[(b * NCHUNK + chunk) * NUP + tid] = l_run[tid];
    }
#pragma unroll
    for (int i = 0; i < 6; ++i) {
        int u = 6 * ty + i;
        *(float2*)&g_pacc[((size_t)(b * NCHUNK + chunk) * NUP + u) * DH + 2 * tx] =
            make_float2(acc[i][0], acc[i][1]);
    }
}

// ---------------- kernel 6: combine split-softmax partials ----------------
__global__ void k_combine(float* __restrict__ out_o) {
    int u = blockIdx.x;
    int b = blockIdx.y;
    int d = threadIdx.x;
    float gm = -INFINITY;
    for (int c = 0; c < NCHUNK; ++c)
        gm = fmaxf(gm, g_pm[(b * NCHUNK + c) * NUP + u]);
    float L = 0.f, a = 0.f;
    for (int c = 0; c < NCHUNK; ++c) {
        float w = __expf(g_pm[(b * NCHUNK + c) * NUP + u] - gm);
        L += g_pl[(b * NCHUNK + c) * NUP + u] * w;
        a += g_pacc[((size_t)(b * NCHUNK + c) * NUP + u) * DH + d] * w;
    }
    out_o[(b * NU + u) * DH + d] = a / L;
}

// ---------------- launch ----------------
extern "C" void kernel_launch(void* const* d_in, const int* in_sizes, int n_in,
                              void* d_out, int out_size) {
    const float* q  = (const float*)d_in[0];
    const float* K  = (const float*)d_in[1];
    const float* V  = (const float*)d_in[2];
    const int* idx  = (const int*)d_in[3];
    float* out_o = (float*)d_out;                  // attn_output [8,45,64]
    float* out_s = out_o + NB * NU * DH;           // attn_scores [8,45,32768]

    (void)in_sizes; (void)n_in; (void)out_size;

    const int smem_M    = (64 * 132 + 64 * 68 + 64) * 4;                         // 51456
    const int smem_attn = (64 * 50 + 64 * 132 + 128 * 68 + 48 * 132 + 144) * 4;  // 107328
    cudaFuncSetAttribute(k_M,    cudaFuncAttributeMaxDynamicSharedMemorySize, smem_M);
    cudaFuncSetAttribute(k_attn, cudaFuncAttributeMaxDynamicSharedMemorySize, smem_attn);

    k_gather<<<(NB * LKS * DH / 4 + 255) / 256, 256>>>(K, idx);
    k_ksum<<<NB, 256>>>();
    k_M<<<dim3(LQ / 128, NB), 256, smem_M>>>(q);
    k_topk<<<NB, 256>>>();
    k_attn<<<dim3(NCHUNK, NB), 256, smem_attn>>>(q, K, V, out_s);
    k_combine<<<dim3(NU, NB), 64>>>(out_o);
}

// round 3
// speedup vs baseline: 1.2809x; 1.2809x over previous
#include <cuda_runtime.h>
#include <cuda_bf16.h>
#include <math.h>

#define NB 8
#define LQ 4096
#define LK 32768
#define DH 64
#define LKS 8000
#define NU 45
#define NUP 48
#define NCHUNK 32
#define CK 1024
#define CANDMAX 512

// ---------------- device scratch (no allocations allowed) ----------------
__device__ float g_Ksamp[NB * LKS * DH];          // gathered sampled K, 16 MB
__device__ float g_Ksum[NB * DH];                 // per-batch sum of sampled K rows
__device__ float g_M[NB * LQ];                    // approx sparsity measure (tf32)
__device__ int   g_top[NB * NUP];                 // selected query indices (padded)
__device__ int   g_cand[NB * CANDMAX];            // candidate query indices
__device__ float g_candM[NB * CANDMAX];           // exact M for candidates
__device__ int   g_ccount[NB];                    // candidate counts
__device__ float g_pm[NB * NCHUNK * NUP];         // split-softmax partial max
__device__ float g_pl[NB * NCHUNK * NUP];         // split-softmax partial sumexp
__device__ float g_pacc[NB * NCHUNK * NUP * DH];  // split-softmax partial V-acc

// ---------------- tf32 mma helper ----------------
__device__ __forceinline__ void mma_tf32(float c[4], const float a[4], float b0, float b1) {
    asm volatile(
        "mma.sync.aligned.m16n8k8.row.col.f32.tf32.tf32.f32 "
        "{%0,%1,%2,%3}, {%4,%5,%6,%7}, {%8,%9}, {%0,%1,%2,%3};"
        : "+f"(c[0]), "+f"(c[1]), "+f"(c[2]), "+f"(c[3])
        : "r"(__float_as_uint(a[0])), "r"(__float_as_uint(a[1])),
          "r"(__float_as_uint(a[2])), "r"(__float_as_uint(a[3])),
          "r"(__float_as_uint(b0)),   "r"(__float_as_uint(b1)));
}

// ---------------- kernel 1: gather K_samp ----------------
__global__ void k_gather(const float* __restrict__ K, const int* __restrict__ idx) {
    int t = blockIdx.x * blockDim.x + threadIdx.x;   // float4 units
    const int total = NB * LKS * DH / 4;
    if (t >= total) return;
    int d4   = t & (DH / 4 - 1);
    int rest = t >> 4;
    int u = rest % LKS;
    int b = rest / LKS;
    const float4* src = (const float4*)(K + ((size_t)b * LK + idx[u]) * DH);
    ((float4*)g_Ksamp)[t] = src[d4];
}

// ---------------- kernel 2: Ksum per batch ----------------
__global__ void k_ksum() {
    int b = blockIdx.x;
    int d = threadIdx.x & 63;
    int g = threadIdx.x >> 6;
    float s = 0.f;
    for (int u = g; u < LKS; u += 4)
        s += g_Ksamp[(b * LKS + u) * DH + d];
    __shared__ float red[4][64];
    red[g][d] = s;
    __syncthreads();
    if (g == 0)
        g_Ksum[b * DH + d] = red[0][d] + red[1][d] + red[2][d] + red[3][d];
}

// ---------------- kernel 3: approx M via tf32 tensor-core GEMM ----------------
// block = 256 threads (8 warps), covers 128 queries; each warp owns 16 rows.
__global__ __launch_bounds__(256) void k_M_mma(const float* __restrict__ q) {
    __shared__ float Bs[64 * 68];
    __shared__ float ksumS[64];
    __shared__ float rowmax[128];

    const int tid  = threadIdx.x;
    const int w    = tid >> 5;
    const int lane = tid & 31;
    const int gid  = lane >> 2;
    const int tig  = lane & 3;
    const int b    = blockIdx.y;
    const int m0   = blockIdx.x * 128;
    const int r0   = m0 + w * 16 + gid;
    const int r1   = r0 + 8;

    // preload A fragments for all 8 k-steps (q tile persists for whole loop)
    float a[8][4];
#pragma unroll
    for (int kk = 0; kk < 8; ++kk) {
        int c0 = kk * 8 + tig, c1 = c0 + 4;
        a[kk][0] = q[((size_t)(b * LQ) + r0) * DH + c0];
        a[kk][1] = q[((size_t)(b * LQ) + r1) * DH + c0];
        a[kk][2] = q[((size_t)(b * LQ) + r0) * DH + c1];
        a[kk][3] = q[((size_t)(b * LQ) + r1) * DH + c1];
    }
    if (tid < 64) ksumS[tid] = g_Ksum[b * DH + tid];

    float rmax0 = -INFINITY, rmax1 = -INFINITY;

    for (int kt = 0; kt < LKS / 64; ++kt) {       // 125 tiles of 64 keys
        __syncthreads();
#pragma unroll
        for (int i = 0; i < 4; ++i) {
            int fidx = tid + 256 * i;             // 0..1023
            int n    = fidx >> 4;
            int d4   = fidx & 15;
            float4 v = *(const float4*)(g_Ksamp + ((size_t)(b * LKS) + kt * 64 + n) * DH + 4 * d4);
            *(float4*)&Bs[n * 68 + 4 * d4] = v;
        }
        __syncthreads();

#pragma unroll
        for (int nc = 0; nc < 8; nc += 2) {
            float acc0[4] = {0.f, 0.f, 0.f, 0.f};
            float acc1[4] = {0.f, 0.f, 0.f, 0.f};
            const float* br0 = &Bs[(nc * 8 + gid) * 68];
            const float* br1 = &Bs[((nc + 1) * 8 + gid) * 68];
#pragma unroll
            for (int kk = 0; kk < 8; ++kk) {
                mma_tf32(acc0, a[kk], br0[kk * 8 + tig], br0[kk * 8 + tig + 4]);
                mma_tf32(acc1, a[kk], br1[kk * 8 + tig], br1[kk * 8 + tig + 4]);
            }
            rmax0 = fmaxf(rmax0, fmaxf(fmaxf(acc0[0], acc0[1]), fmaxf(acc1[0], acc1[1])));
            rmax1 = fmaxf(rmax1, fmaxf(fmaxf(acc0[2], acc0[3]), fmaxf(acc1[2], acc1[3])));
        }
    }

    // reduce max over the 4 tig lanes of each group
#pragma unroll
    for (int off = 1; off <= 2; off <<= 1) {
        rmax0 = fmaxf(rmax0, __shfl_xor_sync(0xffffffffu, rmax0, off));
        rmax1 = fmaxf(rmax1, __shfl_xor_sync(0xffffffffu, rmax1, off));
    }
    if (tig == 0) {
        rowmax[w * 16 + gid]     = rmax0;
        rowmax[w * 16 + gid + 8] = rmax1;
    }
    __syncwarp();

    if (lane < 16) {
        int m = m0 + w * 16 + lane;
        const float* qp = q + ((size_t)(b * LQ) + m) * DH;
        float d0 = 0.f, d1 = 0.f, d2 = 0.f, d3 = 0.f;
#pragma unroll
        for (int d = 0; d < 64; d += 4) {
            d0 += qp[d]     * ksumS[d];
            d1 += qp[d + 1] * ksumS[d + 1];
            d2 += qp[d + 2] * ksumS[d + 2];
            d3 += qp[d + 3] * ksumS[d + 3];
        }
        g_M[b * LQ + m] = rowmax[w * 16 + lane] - ((d0 + d1) + (d2 + d3)) * (1.0f / (float)LKS);
    }
}

// ---------------- kernel 4: 45th-smallest approx value + candidate collect ----
__global__ __launch_bounds__(512) void k_thresh() {
    const int b = blockIdx.x;
    const int tid = threadIdx.x;
    __shared__ float vals[LQ];
    __shared__ float wv[16];
    __shared__ int   wi[16];
    __shared__ float s_T45;
    __shared__ int   s_cnt;

    for (int j = tid; j < LQ; j += 512) vals[j] = g_M[b * LQ + j];
    if (tid == 0) s_cnt = 0;
    __syncthreads();

    for (int it = 0; it < NU; ++it) {
        float best = INFINITY; int bi = 1 << 30;
        for (int j = tid; j < LQ; j += 512) {
            float v = vals[j];
            if (v < best || (v == best && j < bi)) { best = v; bi = j; }
        }
#pragma unroll
        for (int off = 16; off > 0; off >>= 1) {
            float v2 = __shfl_xor_sync(0xffffffffu, best, off);
            int   i2 = __shfl_xor_sync(0xffffffffu, bi,   off);
            if (v2 < best || (v2 == best && i2 < bi)) { best = v2; bi = i2; }
        }
        if ((tid & 31) == 0) { wv[tid >> 5] = best; wi[tid >> 5] = bi; }
        __syncthreads();
        if (tid == 0) {
            float bb = wv[0]; int bj = wi[0];
            for (int g = 1; g < 16; ++g)
                if (wv[g] < bb || (wv[g] == bb && wi[g] < bj)) { bb = wv[g]; bj = wi[g]; }
            vals[bj] = INFINITY;
            if (it == NU - 1) s_T45 = bb;
        }
        __syncthreads();
    }

    const float thresh = s_T45 + 0.5f;   // covers tf32-vs-fp32 |dM| <= ~0.16 with 3x margin
    for (int j = tid; j < LQ; j += 512) {
        if (g_M[b * LQ + j] <= thresh) {
            int p = atomicAdd(&s_cnt, 1);
            if (p < CANDMAX) g_cand[b * CANDMAX + p] = j;
        }
    }
    __syncthreads();
    if (tid == 0) g_ccount[b] = min(s_cnt, CANDMAX);
}

// ---------------- kernel 5: exact fp32 M for candidates only ----------------
__global__ __launch_bounds__(128) void k_M_exact(const float* __restrict__ q) {
    const int b = blockIdx.y;
    const int c = blockIdx.x;
    if (c >= g_ccount[b]) return;
    const int qi = g_cand[b * CANDMAX + c];
    const int tid = threadIdx.x;

    __shared__ float qrow[64];
    __shared__ float red[4];
    if (tid < 64) qrow[tid] = q[((size_t)(b * LQ) + qi) * DH + tid];
    __syncthreads();

    float mx = -INFINITY;
    for (int k = tid; k < LKS; k += 128) {
        const float4* kr = (const float4*)(g_Ksamp + ((size_t)(b * LKS) + k) * DH);
        float a0 = 0.f, a1 = 0.f, a2 = 0.f, a3 = 0.f;
#pragma unroll
        for (int d4 = 0; d4 < 16; ++d4) {
            float4 kv = kr[d4];
            a0 += qrow[4 * d4 + 0] * kv.x;
            a1 += qrow[4 * d4 + 1] * kv.y;
            a2 += qrow[4 * d4 + 2] * kv.z;
            a3 += qrow[4 * d4 + 3] * kv.w;
        }
        mx = fmaxf(mx, (a0 + a1) + (a2 + a3));
    }
#pragma unroll
    for (int off = 16; off > 0; off >>= 1)
        mx = fmaxf(mx, __shfl_xor_sync(0xffffffffu, mx, off));
    if ((tid & 31) == 0) red[tid >> 5] = mx;
    __syncthreads();
    if (tid == 0) {
        float m = fmaxf(fmaxf(red[0], red[1]), fmaxf(red[2], red[3]));
        float dot = 0.f;
        for (int d = 0; d < 64; ++d) dot += qrow[d] * g_Ksum[b * DH + d];
        g_candM[b * CANDMAX + c] = m - dot * (1.0f / (float)LKS);
    }
}

// ---------------- kernel 6: final top-45 among candidates (exact, tie=low idx) ----
__global__ void k_select() {
    const int b = blockIdx.x;
    const int lane = threadIdx.x;   // 32 threads, one warp
    __shared__ float cv[CANDMAX];
    __shared__ int   ci[CANDMAX];
    const int cnt = g_ccount[b];
    for (int j = lane; j < CANDMAX; j += 32) {
        cv[j] = (j < cnt) ? g_candM[b * CANDMAX + j] : INFINITY;
        ci[j] = (j < cnt) ? g_cand[b * CANDMAX + j]  : (1 << 30);
    }
    __syncwarp();
    for (int it = 0; it < NU; ++it) {
        float best = INFINITY; int bidx = 1 << 30; int bslot = 0;
        for (int j = lane; j < CANDMAX; j += 32) {
            float v = cv[j]; int qi2 = ci[j];
            if (v < best || (v == best && qi2 < bidx)) { best = v; bidx = qi2; bslot = j; }
        }
#pragma unroll
        for (int off = 16; off > 0; off >>= 1) {
            float v2 = __shfl_xor_sync(0xffffffffu, best, off);
            int   i2 = __shfl_xor_sync(0xffffffffu, bidx, off);
            int   s2 = __shfl_xor_sync(0xffffffffu, bslot, off);
            if (v2 < best || (v2 == best && i2 < bidx)) { best = v2; bidx = i2; bslot = s2; }
        }
        if (lane == 0) { g_top[b * NUP + it] = bidx; cv[bslot] = INFINITY; }
        __syncwarp();
    }
    if (lane < NUP - NU) g_top[b * NUP + NU + lane] = 0;   // padding rows
}

// ---------------- kernel 7: scores + flash split-softmax + PV partials ----
__global__ __launch_bounds__(256) void k_attn(const float* __restrict__ q,
                                              const float* __restrict__ K,
                                              const float* __restrict__ V,
                                              float* __restrict__ out_s) {
    extern __shared__ float sm[];
    float* qsT   = sm;                          // [64][50]
    float* ksT   = qsT + 64 * 50;               // [64][132]
    float* Vs    = ksT + 64 * 132;              // [128][68]
    float* Ps    = Vs + 128 * 68;               // [48][132]
    float* m_run = Ps + 48 * 132;               // [48]
    float* m_new = m_run + 48;                  // [48]
    float* l_run = m_new + 48;                  // [48]

    const int tid = threadIdx.x;
    const int ty = tid >> 5;
    const int tx = tid & 31;
    const int b = blockIdx.y;
    const int chunk = blockIdx.x;
    const int kchunk0 = chunk * CK;

#pragma unroll
    for (int i = 0; i < 3; ++i) {
        int fidx = tid + 256 * i;
        int u    = fidx >> 4;
        int dblk = fidx & 15;
        float4 v = make_float4(0.f, 0.f, 0.f, 0.f);
        if (u < NU) {
            int qi = g_top[b * NUP + u];
            v = *(const float4*)(q + ((size_t)(b * LQ + qi)) * DH + 4 * dblk);
        }
        qsT[(4 * dblk + 0) * 50 + u] = v.x;
        qsT[(4 * dblk + 1) * 50 + u] = v.y;
        qsT[(4 * dblk + 2) * 50 + u] = v.z;
        qsT[(4 * dblk + 3) * 50 + u] = v.w;
    }
    if (tid < NUP) { m_run[tid] = -INFINITY; l_run[tid] = 0.f; }

    float acc[6][2];
#pragma unroll
    for (int i = 0; i < 6; ++i) { acc[i][0] = 0.f; acc[i][1] = 0.f; }

    for (int kt = 0; kt < CK / 128; ++kt) {
        const int kg0 = kchunk0 + kt * 128;
        __syncthreads();
#pragma unroll
        for (int i = 0; i < 8; ++i) {
            int fidx = tid + 256 * i;
            int k    = fidx >> 4;
            int dblk = fidx & 15;
            float4 kv = *(const float4*)(K + ((size_t)(b * LK + kg0 + k)) * DH + 4 * dblk);
            ksT[(4 * dblk + 0) * 132 + k] = kv.x;
            ksT[(4 * dblk + 1) * 132 + k] = kv.y;
            ksT[(4 * dblk + 2) * 132 + k] = kv.z;
            ksT[(4 * dblk + 3) * 132 + k] = kv.w;
            float4 vv = *(const float4*)(V + ((size_t)(b * LK + kg0 + k)) * DH + 4 * dblk);
            *(float4*)&Vs[k * 68 + 4 * dblk] = vv;
        }
        __syncthreads();

        float s[6][4];
#pragma unroll
        for (int i = 0; i < 6; ++i)
#pragma unroll
            for (int j = 0; j < 4; ++j) s[i][j] = 0.f;

#pragma unroll 4
        for (int d = 0; d < 64; ++d) {
            const float* qr = &qsT[d * 50 + 6 * ty];
            float2 q01 = *(const float2*)(qr);
            float2 q23 = *(const float2*)(qr + 2);
            float2 q45 = *(const float2*)(qr + 4);
            float4 kv  = *(const float4*)&ksT[d * 132 + 4 * tx];
            float qa[6] = {q01.x, q01.y, q23.x, q23.y, q45.x, q45.y};
            float kb[4] = {kv.x, kv.y, kv.z, kv.w};
#pragma unroll
            for (int i = 0; i < 6; ++i)
#pragma unroll
                for (int j = 0; j < 4; ++j) s[i][j] += qa[i] * kb[j];
        }
#pragma unroll
        for (int i = 0; i < 6; ++i)
#pragma unroll
            for (int j = 0; j < 4; ++j) s[i][j] *= 0.125f;

#pragma unroll
        for (int i = 0; i < 6; ++i) {
            int u = 6 * ty + i;
            if (u < NU) {
                float4 w = make_float4(s[i][0], s[i][1], s[i][2], s[i][3]);
                *(float4*)(out_s + ((size_t)(b * NU + u)) * LK + kg0 + 4 * tx) = w;
            }
        }

#pragma unroll
        for (int i = 0; i < 6; ++i) {
            float mx = fmaxf(fmaxf(s[i][0], s[i][1]), fmaxf(s[i][2], s[i][3]));
#pragma unroll
            for (int off = 16; off > 0; off >>= 1)
                mx = fmaxf(mx, __shfl_xor_sync(0xffffffffu, mx, off));
            if (tx == 0) {
                int u = 6 * ty + i;
                m_new[u] = fmaxf(m_run[u], mx);
            }
        }
        __syncthreads();

#pragma unroll
        for (int i = 0; i < 6; ++i) {
            int u = 6 * ty + i;
            float mn = m_new[u];
            float f  = __expf(m_run[u] - mn);
            float p0 = __expf(s[i][0] - mn);
            float p1 = __expf(s[i][1] - mn);
            float p2 = __expf(s[i][2] - mn);
            float p3 = __expf(s[i][3] - mn);
            float ps = p0 + p1 + p2 + p3;
#pragma unroll
            for (int off = 16; off > 0; off >>= 1)
                ps += __shfl_xor_sync(0xffffffffu, ps, off);
            if (tx == 0) {
                l_run[u] = l_run[u] * f + ps;
                m_run[u] = mn;
            }
            *(float4*)&Ps[u * 132 + 4 * tx] = make_float4(p0, p1, p2, p3);
            acc[i][0] *= f;
            acc[i][1] *= f;
        }
        __syncthreads();

#pragma unroll 2
        for (int k = 0; k < 128; k += 2) {
            float2 va = *(const float2*)&Vs[k * 68 + 2 * tx];
            float2 vb = *(const float2*)&Vs[(k + 1) * 68 + 2 * tx];
#pragma unroll
            for (int i = 0; i < 6; ++i) {
                float2 pp = *(const float2*)&Ps[(6 * ty + i) * 132 + k];
                acc[i][0] += pp.x * va.x;
                acc[i][0] += pp.y * vb.x;
                acc[i][1] += pp.x * va.y;
                acc[i][1] += pp.y * vb.y;
            }
        }
    }
    __syncthreads();

    if (tid < NUP) {
        g_pm[(b * NCHUNK + chunk) * NUP + tid] = m_run[tid];
        g_pl[(b * NCHUNK + chunk) * NUP + tid] = l_run[tid];
    }
#pragma unroll
    for (int i = 0; i < 6; ++i) {
        int u = 6 * ty + i;
        *(float2*)&g_pacc[((size_t)(b * NCHUNK + chunk) * NUP + u) * DH + 2 * tx] =
            make_float2(acc[i][0], acc[i][1]);
    }
}

// ---------------- kernel 8: combine split-softmax partials ----------------
__global__ void k_combine(float* __restrict__ out_o) {
    int u = blockIdx.x;
    int b = blockIdx.y;
    int d = threadIdx.x;
    float gm = -INFINITY;
    for (int c = 0; c < NCHUNK; ++c)
        gm = fmaxf(gm, g_pm[(b * NCHUNK + c) * NUP + u]);
    float L = 0.f, a = 0.f;
    for (int c = 0; c < NCHUNK; ++c) {
        float w = __expf(g_pm[(b * NCHUNK + c) * NUP + u] - gm);
        L += g_pl[(b * NCHUNK + c) * NUP + u] * w;
        a += g_pacc[((size_t)(b * NCHUNK + c) * NUP + u) * DH + d] * w;
    }
    out_o[(b * NU + u) * DH + d] = a / L;
}

// ---------------- launch ----------------
extern "C" void kernel_launch(void* const* d_in, const int* in_sizes, int n_in,
                              void* d_out, int out_size) {
    const float* q  = (const float*)d_in[0];
    const float* K  = (const float*)d_in[1];
    const float* V  = (const float*)d_in[2];
    const int* idx  = (const int*)d_in[3];
    float* out_o = (float*)d_out;                  // attn_output [8,45,64]
    float* out_s = out_o + NB * NU * DH;           // attn_scores [8,45,32768]

    (void)in_sizes; (void)n_in; (void)out_size;

    const int smem_attn = (64 * 50 + 64 * 132 + 128 * 68 + 48 * 132 + 144) * 4;  // 107328
    cudaFuncSetAttribute(k_attn, cudaFuncAttributeMaxDynamicSharedMemorySize, smem_attn);

    k_gather<<<(NB * LKS * DH / 4 + 255) / 256, 256>>>(K, idx);
    k_ksum<<<NB, 256>>>();
    k_M_mma<<<dim3(LQ / 128, NB), 256>>>(q);
    k_thresh<<<NB, 512>>>();
    k_M_exact<<<dim3(CANDMAX, NB), 128>>>(q);
    k_select<<<NB, 32>>>();
    k_attn<<<dim3(NCHUNK, NB), 256, smem_attn>>>(q, K, V, out_s);
    k_combine<<<dim3(NU, NB), 64>>>(out_o);
}

// round 4
// speedup vs baseline: 2.4291x; 1.8964x over previous
#include <cuda_runtime.h>
#include <cuda_bf16.h>
#include <math.h>
#include <stdint.h>

#define NB 8
#define LQ 4096
#define LK 32768
#define DH 64
#define LKS 8000
#define NU 45
#define NUP 48
#define NCHUNK 32
#define CK 1024
#define CANDMAX 1024
#define NSPLIT 32
#define MARGIN 1.0f

// ---------------- device scratch ----------------
__device__ __nv_bfloat16 g_KsampH[NB * LKS * DH]; // unique-gathered K, bf16
__device__ int   g_uniq[LKS];                     // unique sampled indices (sorted)
__device__ int   g_ucount;                        // # unique
__device__ int   g_upad;                          // padded to mult of 64
__device__ float g_Ksum[NB * DH];                 // per-batch sum over full multiset
__device__ float g_M[NB * LQ];                    // approx sparsity measure (bf16 mma)
__device__ int   g_top[NB * NUP];
__device__ int   g_cand[NB * CANDMAX];
__device__ float g_candP[NB * CANDMAX * NSPLIT];  // exact partial maxes
__device__ int   g_ccount[NB];
__device__ float g_pm[NB * NCHUNK * NUP];
__device__ float g_pl[NB * NCHUNK * NUP];
__device__ float g_pacc[NB * NCHUNK * NUP * DH];

// ---------------- helpers ----------------
__device__ __forceinline__ void mma_bf16(float c[4], const uint32_t a[4],
                                         uint32_t b0, uint32_t b1) {
    asm volatile(
        "mma.sync.aligned.m16n8k16.row.col.f32.bf16.bf16.f32 "
        "{%0,%1,%2,%3}, {%4,%5,%6,%7}, {%8,%9}, {%0,%1,%2,%3};"
        : "+f"(c[0]), "+f"(c[1]), "+f"(c[2]), "+f"(c[3])
        : "r"(a[0]), "r"(a[1]), "r"(a[2]), "r"(a[3]), "r"(b0), "r"(b1));
}
__device__ __forceinline__ uint32_t packbf(float x, float y) {
    __nv_bfloat162 h = __floats2bfloat162_rn(x, y);
    return *(uint32_t*)&h;
}
__device__ __forceinline__ void cp16(uint32_t dst, const void* src) {
    asm volatile("cp.async.ca.shared.global [%0], [%1], 16;\n" :: "r"(dst), "l"(src));
}

// ---------------- kernel 0: dedupe sampled indices ----------------
__global__ void k_dedup(const int* __restrict__ idx) {
    __shared__ unsigned bm[250];
    __shared__ int wo[251];
    int tid = threadIdx.x;
    for (int i = tid; i < 250; i += 1024) bm[i] = 0u;
    __syncthreads();
    for (int i = tid; i < LKS; i += 1024) {
        int v = idx[i];
        atomicOr(&bm[v >> 5], 1u << (v & 31));
    }
    __syncthreads();
    if (tid == 0) {
        int acc = 0;
        for (int w = 0; w < 250; ++w) { wo[w] = acc; acc += __popc(bm[w]); }
        wo[250] = acc;
        g_ucount = acc;
        g_upad = (acc + 63) & ~63;
    }
    __syncthreads();
    for (int w = tid; w < 250; w += 1024) {
        unsigned m = bm[w];
        int o = wo[w];
        while (m) {
            int b = __ffs(m) - 1;
            g_uniq[o++] = w * 32 + b;
            m &= m - 1;
        }
    }
    __syncthreads();
    if (tid < 64) {
        int uc = wo[250];
        int up = (uc + 63) & ~63;
        if (uc + tid < up) g_uniq[uc + tid] = g_uniq[0];   // pad with duplicate
    }
}

// ---------------- kernel 1: gather unique K rows -> bf16 ----------------
__global__ void k_gather(const float* __restrict__ K) {
    int t = blockIdx.x * blockDim.x + threadIdx.x;   // 8 bf16 per thread
    int chunk = t & 7;
    int rest = t >> 3;
    int j = rest % LKS;
    int b = rest / LKS;
    if (b >= NB) return;
    if (j >= g_upad) return;
    int src = g_uniq[j];
    const float4* p = (const float4*)(K + ((size_t)b * LK + src) * DH + chunk * 8);
    float4 v0 = p[0], v1 = p[1];
    uint32_t o0 = packbf(v0.x, v0.y);
    uint32_t o1 = packbf(v0.z, v0.w);
    uint32_t o2 = packbf(v1.x, v1.y);
    uint32_t o3 = packbf(v1.z, v1.w);
    uint4 w = make_uint4(o0, o1, o2, o3);
    *(uint4*)(g_KsampH + ((size_t)(b * LKS) + j) * DH + chunk * 8) = w;
}

// ---------------- kernel 2: Ksum over full multiset ----------------
__global__ void k_ksum(const float* __restrict__ K, const int* __restrict__ idx) {
    int b = blockIdx.x;
    int d = threadIdx.x & 63;
    int g = threadIdx.x >> 6;
    float s = 0.f;
    for (int u = g; u < LKS; u += 4)
        s += K[((size_t)b * LK + idx[u]) * DH + d];
    __shared__ float red[4][64];
    red[g][d] = s;
    __syncthreads();
    if (g == 0)
        g_Ksum[b * DH + d] = red[0][d] + red[1][d] + red[2][d] + red[3][d];
}

// ---------------- kernel 3: approx M via bf16 mma, cp.async pipelined ------
// block 256 thr = 8 warps; m-tile 128, n-tile 64; warp: m32 x n32
__global__ __launch_bounds__(256) void k_M_mma(const float* __restrict__ q) {
    __shared__ __nv_bfloat16 Bs[2][64 * 72];    // row pad 72 bf16 = 144B
    __shared__ float rowmaxS[2][128];
    __shared__ float ksumS[64];

    const int tid  = threadIdx.x;
    const int wid  = tid >> 5;
    const int lane = tid & 31;
    const int gid  = lane >> 2;
    const int tig  = lane & 3;
    const int b    = blockIdx.y;
    const int m0   = blockIdx.x * 128;
    const int mwarp = (wid & 3) * 32;
    const int nhalf = wid >> 2;

    if (tid < 64) ksumS[tid] = g_Ksum[b * DH + tid];

    // A fragments (q persists across whole loop)
    uint32_t a[2][4][4];
#pragma unroll
    for (int mblk = 0; mblk < 2; ++mblk) {
        int r0 = m0 + mwarp + mblk * 16 + gid;
        int r1 = r0 + 8;
        const float* q0 = q + ((size_t)(b * LQ) + r0) * DH;
        const float* q1 = q + ((size_t)(b * LQ) + r1) * DH;
#pragma unroll
        for (int kk = 0; kk < 4; ++kk) {
            int c = kk * 16 + 2 * tig;
            float2 x0 = *(const float2*)(q0 + c);
            float2 x1 = *(const float2*)(q1 + c);
            float2 x2 = *(const float2*)(q0 + c + 8);
            float2 x3 = *(const float2*)(q1 + c + 8);
            a[mblk][kk][0] = packbf(x0.x, x0.y);
            a[mblk][kk][1] = packbf(x1.x, x1.y);
            a[mblk][kk][2] = packbf(x2.x, x2.y);
            a[mblk][kk][3] = packbf(x3.x, x3.y);
        }
    }

    const int niter = g_upad >> 6;
    const int prow = tid >> 2, pseg = tid & 3;
    uint32_t sBase = (uint32_t)__cvta_generic_to_shared(&Bs[0][0]);

    // prologue: prefetch tile 0
    {
        const __nv_bfloat16* src = g_KsampH + ((size_t)(b * LKS) + prow) * DH + pseg * 16;
        uint32_t dst = sBase + prow * 144 + pseg * 32;
        cp16(dst, src);
        cp16(dst + 16, src + 8);
    }
    asm volatile("cp.async.commit_group;\n");

    float rmax[2][2];
    rmax[0][0] = rmax[0][1] = rmax[1][0] = rmax[1][1] = -INFINITY;

    for (int t = 0; t < niter; ++t) {
        asm volatile("cp.async.wait_group 0;\n");
        __syncthreads();
        if (t + 1 < niter) {
            const __nv_bfloat16* src =
                g_KsampH + ((size_t)(b * LKS) + (t + 1) * 64 + prow) * DH + pseg * 16;
            uint32_t dst = sBase + ((t + 1) & 1) * 9216 + prow * 144 + pseg * 32;
            cp16(dst, src);
            cp16(dst + 16, src + 8);
        }
        asm volatile("cp.async.commit_group;\n");

        const __nv_bfloat16* B = &Bs[t & 1][0];
        float acc[2][4][4];
#pragma unroll
        for (int mb = 0; mb < 2; ++mb)
#pragma unroll
            for (int nc = 0; nc < 4; ++nc)
#pragma unroll
                for (int i = 0; i < 4; ++i) acc[mb][nc][i] = 0.f;

#pragma unroll
        for (int nc = 0; nc < 4; ++nc) {
            const __nv_bfloat16* bp = B + (nhalf * 32 + nc * 8 + gid) * 72 + 2 * tig;
#pragma unroll
            for (int kk = 0; kk < 4; ++kk) {
                uint32_t b0 = *(const uint32_t*)(bp + kk * 16);
                uint32_t b1 = *(const uint32_t*)(bp + kk * 16 + 8);
                mma_bf16(acc[0][nc], a[0][kk], b0, b1);
                mma_bf16(acc[1][nc], a[1][kk], b0, b1);
            }
        }
#pragma unroll
        for (int mb = 0; mb < 2; ++mb)
#pragma unroll
            for (int nc = 0; nc < 4; ++nc) {
                rmax[mb][0] = fmaxf(rmax[mb][0], fmaxf(acc[mb][nc][0], acc[mb][nc][1]));
                rmax[mb][1] = fmaxf(rmax[mb][1], fmaxf(acc[mb][nc][2], acc[mb][nc][3]));
            }
    }

    // reduce over tig lanes
#pragma unroll
    for (int mb = 0; mb < 2; ++mb)
#pragma unroll
        for (int h = 0; h < 2; ++h) {
            rmax[mb][h] = fmaxf(rmax[mb][h], __shfl_xor_sync(0xffffffffu, rmax[mb][h], 1));
            rmax[mb][h] = fmaxf(rmax[mb][h], __shfl_xor_sync(0xffffffffu, rmax[mb][h], 2));
        }
    if (tig == 0) {
        rowmaxS[nhalf][mwarp + gid]      = rmax[0][0];
        rowmaxS[nhalf][mwarp + gid + 8]  = rmax[0][1];
        rowmaxS[nhalf][mwarp + 16 + gid] = rmax[1][0];
        rowmaxS[nhalf][mwarp + 24 + gid] = rmax[1][1];
    }
    __syncthreads();

    if (tid < 128) {
        int m = m0 + tid;
        float mx = fmaxf(rowmaxS[0][tid], rowmaxS[1][tid]);
        const float* qp = q + ((size_t)(b * LQ) + m) * DH;
        float d0 = 0.f, d1 = 0.f, d2 = 0.f, d3 = 0.f;
#pragma unroll
        for (int d = 0; d < 64; d += 4) {
            d0 += qp[d]     * ksumS[d];
            d1 += qp[d + 1] * ksumS[d + 1];
            d2 += qp[d + 2] * ksumS[d + 2];
            d3 += qp[d + 3] * ksumS[d + 3];
        }
        g_M[b * LQ + m] = mx - ((d0 + d1) + (d2 + d3)) * (1.0f / (float)LKS);
    }
}

// ---------------- kernel 4: histogram threshold + candidate collect --------
__global__ __launch_bounds__(512) void k_thresh() {
    const int b = blockIdx.x;
    const int tid = threadIdx.x;
    __shared__ float sv[LQ];
    __shared__ int hist[512];
    __shared__ float wmn[16], wmx[16];
    __shared__ float s_mn, s_range, s_thresh;
    __shared__ int s_cnt;

    float mn = INFINITY, mx = -INFINITY;
    for (int j = tid; j < LQ; j += 512) {
        float v = g_M[b * LQ + j];
        sv[j] = v;
        mn = fminf(mn, v);
        mx = fmaxf(mx, v);
    }
#pragma unroll
    for (int off = 16; off > 0; off >>= 1) {
        mn = fminf(mn, __shfl_xor_sync(0xffffffffu, mn, off));
        mx = fmaxf(mx, __shfl_xor_sync(0xffffffffu, mx, off));
    }
    if ((tid & 31) == 0) { wmn[tid >> 5] = mn; wmx[tid >> 5] = mx; }
    if (tid < 512) hist[tid] = 0;
    if (tid == 0) s_cnt = 0;
    __syncthreads();
    if (tid == 0) {
        float a = INFINITY, z = -INFINITY;
        for (int g = 0; g < 16; ++g) { a = fminf(a, wmn[g]); z = fmaxf(z, wmx[g]); }
        s_mn = a;
        s_range = z - a + 1e-6f;
    }
    __syncthreads();
    const float scale = 511.0f / s_range;
    for (int j = tid; j < LQ; j += 512) {
        int bin = (int)((sv[j] - s_mn) * scale);
        bin = max(0, min(511, bin));
        atomicAdd(&hist[bin], 1);
    }
    __syncthreads();
    if (tid == 0) {
        int cum = 0, bsel = 511;
        for (int i = 0; i < 512; ++i) {
            cum += hist[i];
            if (cum >= NU) { bsel = i; break; }
        }
        s_thresh = s_mn + (float)(bsel + 1) * (s_range / 511.0f) + MARGIN;
    }
    __syncthreads();
    const float th = s_thresh;
    for (int j = tid; j < LQ; j += 512) {
        if (sv[j] <= th) {
            int p = atomicAdd(&s_cnt, 1);
            if (p < CANDMAX) g_cand[b * CANDMAX + p] = j;
        }
    }
    __syncthreads();
    if (tid == 0) g_ccount[b] = min(s_cnt, CANDMAX);
}

// ---------------- kernel 5: exact fp32 max (split-K over unique keys) ------
__global__ __launch_bounds__(256) void k_M_exact(const float* __restrict__ q,
                                                 const float* __restrict__ K) {
    extern __shared__ float sh[];
    float* Kc = sh;                 // [<=250][68]
    float* Qc = sh + 250 * 68;      // [128][68]

    const int b = blockIdx.y;
    const int sp = blockIdx.x;
    const int tid = threadIdx.x;
    const int wid = tid >> 5;
    const int lane = tid & 31;

    const int uc = g_ucount;
    const int j0 = (sp * uc) / NSPLIT;
    const int j1 = ((sp + 1) * uc) / NSPLIT;
    const int nr = j1 - j0;

    for (int i = tid; i < nr * 16; i += 256) {
        int r = i >> 4, d4 = i & 15;
        int src = g_uniq[j0 + r];
        *(float4*)&Kc[r * 68 + 4 * d4] =
            *(const float4*)(K + ((size_t)b * LK + src) * DH + 4 * d4);
    }
    const int cnt = g_ccount[b];

    for (int cg = 0; cg < cnt; cg += 128) {
        int ncg = min(128, cnt - cg);
        __syncthreads();
        for (int i = tid; i < ncg * 16; i += 256) {
            int c = i >> 4, d4 = i & 15;
            int qi = g_cand[b * CANDMAX + cg + c];
            *(float4*)&Qc[c * 68 + 4 * d4] =
                *(const float4*)(q + ((size_t)(b * LQ) + qi) * DH + 4 * d4);
        }
        __syncthreads();
        for (int c = wid; c < ncg; c += 8) {
            const float* qr = &Qc[c * 68];
            float mx = -INFINITY;
            for (int r = lane; r < nr; r += 32) {
                const float* kr = &Kc[r * 68];
                float a0 = 0.f, a1 = 0.f, a2 = 0.f, a3 = 0.f;
#pragma unroll
                for (int d4 = 0; d4 < 16; ++d4) {
                    float4 kv = *(const float4*)&kr[4 * d4];
                    float4 qv = *(const float4*)&qr[4 * d4];
                    a0 += qv.x * kv.x;
                    a1 += qv.y * kv.y;
                    a2 += qv.z * kv.z;
                    a3 += qv.w * kv.w;
                }
                mx = fmaxf(mx, (a0 + a1) + (a2 + a3));
            }
#pragma unroll
            for (int off = 16; off > 0; off >>= 1)
                mx = fmaxf(mx, __shfl_xor_sync(0xffffffffu, mx, off));
            if (lane == 0)
                g_candP[((size_t)(b * CANDMAX) + cg + c) * NSPLIT + sp] = mx;
        }
    }
}

// ---------------- kernel 6: finalize exact M + top-45 selection ------------
__global__ __launch_bounds__(256) void k_select(const float* __restrict__ q) {
    const int b = blockIdx.x;
    const int tid = threadIdx.x;
    __shared__ float cv[CANDMAX];
    __shared__ int   ci[CANDMAX];
    const int cnt = g_ccount[b];

    for (int c = tid; c < CANDMAX; c += 256) {
        if (c < cnt) {
            float mx = -INFINITY;
#pragma unroll
            for (int s = 0; s < NSPLIT; ++s)
                mx = fmaxf(mx, g_candP[((size_t)(b * CANDMAX) + c) * NSPLIT + s]);
            int qi = g_cand[b * CANDMAX + c];
            const float* qp = q + ((size_t)(b * LQ) + qi) * DH;
            float dot = 0.f;
            for (int d = 0; d < 64; ++d) dot += qp[d] * g_Ksum[b * DH + d];
            cv[c] = mx - dot * (1.0f / (float)LKS);
            ci[c] = qi;
        } else {
            cv[c] = INFINITY;
            ci[c] = 1 << 30;
        }
    }
    __syncthreads();

    if (tid < 32) {
        for (int it = 0; it < NU; ++it) {
            float best = INFINITY; int bidx = 1 << 30; int bslot = 0;
            for (int j = tid; j < CANDMAX; j += 32) {
                float v = cv[j]; int qi2 = ci[j];
                if (v < best || (v == best && qi2 < bidx)) { best = v; bidx = qi2; bslot = j; }
            }
#pragma unroll
            for (int off = 16; off > 0; off >>= 1) {
                float v2 = __shfl_xor_sync(0xffffffffu, best, off);
                int   i2 = __shfl_xor_sync(0xffffffffu, bidx, off);
                int   s2 = __shfl_xor_sync(0xffffffffu, bslot, off);
                if (v2 < best || (v2 == best && i2 < bidx)) { best = v2; bidx = i2; bslot = s2; }
            }
            if (tid == 0) { g_top[b * NUP + it] = bidx; cv[bslot] = INFINITY; }
            __syncwarp();
        }
        if (tid < NUP - NU) g_top[b * NUP + NU + tid] = 0;
    }
}

// ---------------- kernel 7: scores + flash split-softmax + PV partials -----
__global__ __launch_bounds__(256) void k_attn(const float* __restrict__ q,
                                              const float* __restrict__ K,
                                              const float* __restrict__ V,
                                              float* __restrict__ out_s) {
    extern __shared__ float sm[];
    float* qsT   = sm;                          // [64][50]
    float* ksT   = qsT + 64 * 50;               // [64][132]
    float* Vs    = ksT + 64 * 132;              // [128][68]
    float* Ps    = Vs + 128 * 68;               // [48][132]
    float* m_run = Ps + 48 * 132;               // [48]
    float* m_new = m_run + 48;                  // [48]
    float* l_run = m_new + 48;                  // [48]

    const int tid = threadIdx.x;
    const int ty = tid >> 5;
    const int tx = tid & 31;
    const int b = blockIdx.y;
    const int chunk = blockIdx.x;
    const int kchunk0 = chunk * CK;

#pragma unroll
    for (int i = 0; i < 3; ++i) {
        int fidx = tid + 256 * i;
        int u    = fidx >> 4;
        int dblk = fidx & 15;
        float4 v = make_float4(0.f, 0.f, 0.f, 0.f);
        if (u < NU) {
            int qi = g_top[b * NUP + u];
            v = *(const float4*)(q + ((size_t)(b * LQ + qi)) * DH + 4 * dblk);
        }
        qsT[(4 * dblk + 0) * 50 + u] = v.x;
        qsT[(4 * dblk + 1) * 50 + u] = v.y;
        qsT[(4 * dblk + 2) * 50 + u] = v.z;
        qsT[(4 * dblk + 3) * 50 + u] = v.w;
    }
    if (tid < NUP) { m_run[tid] = -INFINITY; l_run[tid] = 0.f; }

    float acc[6][2];
#pragma unroll
    for (int i = 0; i < 6; ++i) { acc[i][0] = 0.f; acc[i][1] = 0.f; }

    for (int kt = 0; kt < CK / 128; ++kt) {
        const int kg0 = kchunk0 + kt * 128;
        __syncthreads();
#pragma unroll
        for (int i = 0; i < 8; ++i) {
            int fidx = tid + 256 * i;
            int k    = fidx >> 4;
            int dblk = fidx & 15;
            float4 kv = *(const float4*)(K + ((size_t)(b * LK + kg0 + k)) * DH + 4 * dblk);
            ksT[(4 * dblk + 0) * 132 + k] = kv.x;
            ksT[(4 * dblk + 1) * 132 + k] = kv.y;
            ksT[(4 * dblk + 2) * 132 + k] = kv.z;
            ksT[(4 * dblk + 3) * 132 + k] = kv.w;
            float4 vv = *(const float4*)(V + ((size_t)(b * LK + kg0 + k)) * DH + 4 * dblk);
            *(float4*)&Vs[k * 68 + 4 * dblk] = vv;
        }
        __syncthreads();

        float s[6][4];
#pragma unroll
        for (int i = 0; i < 6; ++i)
#pragma unroll
            for (int j = 0; j < 4; ++j) s[i][j] = 0.f;

#pragma unroll 4
        for (int d = 0; d < 64; ++d) {
            const float* qr = &qsT[d * 50 + 6 * ty];
            float2 q01 = *(const float2*)(qr);
            float2 q23 = *(const float2*)(qr + 2);
            float2 q45 = *(const float2*)(qr + 4);
            float4 kv  = *(const float4*)&ksT[d * 132 + 4 * tx];
            float qa[6] = {q01.x, q01.y, q23.x, q23.y, q45.x, q45.y};
            float kb[4] = {kv.x, kv.y, kv.z, kv.w};
#pragma unroll
            for (int i = 0; i < 6; ++i)
#pragma unroll
                for (int j = 0; j < 4; ++j) s[i][j] += qa[i] * kb[j];
        }
#pragma unroll
        for (int i = 0; i < 6; ++i)
#pragma unroll
            for (int j = 0; j < 4; ++j) s[i][j] *= 0.125f;

#pragma unroll
        for (int i = 0; i < 6; ++i) {
            int u = 6 * ty + i;
            if (u < NU) {
                float4 w = make_float4(s[i][0], s[i][1], s[i][2], s[i][3]);
                *(float4*)(out_s + ((size_t)(b * NU + u)) * LK + kg0 + 4 * tx) = w;
            }
        }

#pragma unroll
        for (int i = 0; i < 6; ++i) {
            float mx = fmaxf(fmaxf(s[i][0], s[i][1]), fmaxf(s[i][2], s[i][3]));
#pragma unroll
            for (int off = 16; off > 0; off >>= 1)
                mx = fmaxf(mx, __shfl_xor_sync(0xffffffffu, mx, off));
            if (tx == 0) {
                int u = 6 * ty + i;
                m_new[u] = fmaxf(m_run[u], mx);
            }
        }
        __syncthreads();

#pragma unroll
        for (int i = 0; i < 6; ++i) {
            int u = 6 * ty + i;
            float mn = m_new[u];
            float f  = __expf(m_run[u] - mn);
            float p0 = __expf(s[i][0] - mn);
            float p1 = __expf(s[i][1] - mn);
            float p2 = __expf(s[i][2] - mn);
            float p3 = __expf(s[i][3] - mn);
            float ps = p0 + p1 + p2 + p3;
#pragma unroll
            for (int off = 16; off > 0; off >>= 1)
                ps += __shfl_xor_sync(0xffffffffu, ps, off);
            if (tx == 0) {
                l_run[u] = l_run[u] * f + ps;
                m_run[u] = mn;
            }
            *(float4*)&Ps[u * 132 + 4 * tx] = make_float4(p0, p1, p2, p3);
            acc[i][0] *= f;
            acc[i][1] *= f;
        }
        __syncthreads();

#pragma unroll 2
        for (int k = 0; k < 128; k += 2) {
            float2 va = *(const float2*)&Vs[k * 68 + 2 * tx];
            float2 vb = *(const float2*)&Vs[(k + 1) * 68 + 2 * tx];
#pragma unroll
            for (int i = 0; i < 6; ++i) {
                float2 pp = *(const float2*)&Ps[(6 * ty + i) * 132 + k];
                acc[i][0] += pp.x * va.x;
                acc[i][0] += pp.y * vb.x;
                acc[i][1] += pp.x * va.y;
                acc[i][1] += pp.y * vb.y;
            }
        }
    }
    __syncthreads();

    if (tid < NUP) {
        g_pm[(b * NCHUNK + chunk) * NUP + tid] = m_run[tid];
        g_pl[(b * NCHUNK + chunk) * NUP + tid] = l_run[tid];
    }
#pragma unroll
    for (int i = 0; i < 6; ++i) {
        int u = 6 * ty + i;
        *(float2*)&g_pacc[((size_t)(b * NCHUNK + chunk) * NUP + u) * DH + 2 * tx] =
            make_float2(acc[i][0], acc[i][1]);
    }
}

// ---------------- kernel 8: combine split-softmax partials ----------------
__global__ void k_combine(float* __restrict__ out_o) {
    int u = blockIdx.x;
    int b = blockIdx.y;
    int d = threadIdx.x;
    float gm = -INFINITY;
    for (int c = 0; c < NCHUNK; ++c)
        gm = fmaxf(gm, g_pm[(b * NCHUNK + c) * NUP + u]);
    float L = 0.f, a = 0.f;
    for (int c = 0; c < NCHUNK; ++c) {
        float w = __expf(g_pm[(b * NCHUNK + c) * NUP + u] - gm);
        L += g_pl[(b * NCHUNK + c) * NUP + u] * w;
        a += g_pacc[((size_t)(b * NCHUNK + c) * NUP + u) * DH + d] * w;
    }
    out_o[(b * NU + u) * DH + d] = a / L;
}

// ---------------- launch ----------------
extern "C" void kernel_launch(void* const* d_in, const int* in_sizes, int n_in,
                              void* d_out, int out_size) {
    const float* q  = (const float*)d_in[0];
    const float* K  = (const float*)d_in[1];
    const float* V  = (const float*)d_in[2];
    const int* idx  = (const int*)d_in[3];
    float* out_o = (float*)d_out;                  // attn_output [8,45,64]
    float* out_s = out_o + NB * NU * DH;           // attn_scores [8,45,32768]

    (void)in_sizes; (void)n_in; (void)out_size;

    const int smem_attn  = (64 * 50 + 64 * 132 + 128 * 68 + 48 * 132 + 144) * 4;  // 107328
    const int smem_exact = (250 * 68 + 128 * 68) * 4;                              // 102816
    cudaFuncSetAttribute(k_attn,    cudaFuncAttributeMaxDynamicSharedMemorySize, smem_attn);
    cudaFuncSetAttribute(k_M_exact, cudaFuncAttributeMaxDynamicSharedMemorySize, smem_exact);

    k_dedup<<<1, 1024>>>(idx);
    k_gather<<<(NB * LKS * 8 + 255) / 256, 256>>>(K);
    k_ksum<<<NB, 256>>>(K, idx);
    k_M_mma<<<dim3(LQ / 128, NB), 256>>>(q);
    k_thresh<<<NB, 512>>>();
    k_M_exact<<<dim3(NSPLIT, NB), 256, smem_exact>>>(q, K);
    k_select<<<NB, 256>>>(q);
    k_attn<<<dim3(NCHUNK, NB), 256, smem_attn>>>(q, K, V, out_s);
    k_combine<<<dim3(NU, NB), 64>>>(out_o);
}

// round 5
// speedup vs baseline: 3.2841x; 1.3520x over previous
#include <cuda_runtime.h>
#include <cuda_bf16.h>
#include <math.h>
#include <stdint.h>

#define NB 8
#define LQ 4096
#define LK 32768
#define DH 64
#define LKS 8000
#define NU 45
#define NUP 48
#define NCHUNK 64
#define CK 512
#define CANDMAX 1024
#define NSPLIT 32
#define MARGIN 1.0f

// ---------------- device scratch ----------------
__device__ __nv_bfloat16 g_KsampH[NB * LKS * DH];
__device__ int   g_uniq[LKS];
__device__ int   g_ucount;
__device__ int   g_upad;
__device__ float g_KsumP[NB * 8 * DH];
__device__ float g_Ksum[NB * DH];
__device__ float g_M[NB * LQ];
__device__ int   g_top[NB * NUP];
__device__ int   g_cand[NB * CANDMAX];
__device__ float g_candP[NB * CANDMAX * NSPLIT];
__device__ int   g_ccount[NB];
__device__ float g_pm[NB * NCHUNK * NUP];
__device__ float g_pl[NB * NCHUNK * NUP];
__device__ float g_pacc[NB * NCHUNK * NUP * DH];

// ---------------- helpers ----------------
__device__ __forceinline__ void mma_bf16(float c[4], const uint32_t a[4],
                                         uint32_t b0, uint32_t b1) {
    asm volatile(
        "mma.sync.aligned.m16n8k16.row.col.f32.bf16.bf16.f32 "
        "{%0,%1,%2,%3}, {%4,%5,%6,%7}, {%8,%9}, {%0,%1,%2,%3};"
        : "+f"(c[0]), "+f"(c[1]), "+f"(c[2]), "+f"(c[3])
        : "r"(a[0]), "r"(a[1]), "r"(a[2]), "r"(a[3]), "r"(b0), "r"(b1));
}
__device__ __forceinline__ uint32_t packbf(float x, float y) {
    __nv_bfloat162 h = __floats2bfloat162_rn(x, y);
    return *(uint32_t*)&h;
}
__device__ __forceinline__ void cp16(uint32_t dst, const void* src) {
    asm volatile("cp.async.ca.shared.global [%0], [%1], 16;\n" :: "r"(dst), "l"(src));
}
__device__ __forceinline__ void ldsm_x4(uint32_t r[4], uint32_t addr) {
    asm volatile("ldmatrix.sync.aligned.m8n8.x4.shared.b16 {%0,%1,%2,%3}, [%4];"
                 : "=r"(r[0]), "=r"(r[1]), "=r"(r[2]), "=r"(r[3]) : "r"(addr));
}

// ---------------- kernel 0: dedupe sampled indices ----------------
__global__ void k_dedup(const int* __restrict__ idx) {
    __shared__ unsigned bm[250];
    __shared__ int wo[251];
    int tid = threadIdx.x;
    for (int i = tid; i < 250; i += 1024) bm[i] = 0u;
    __syncthreads();
    for (int i = tid; i < LKS; i += 1024) {
        int v = idx[i];
        atomicOr(&bm[v >> 5], 1u << (v & 31));
    }
    __syncthreads();
    if (tid == 0) {
        int acc = 0;
        for (int w = 0; w < 250; ++w) { wo[w] = acc; acc += __popc(bm[w]); }
        wo[250] = acc;
        g_ucount = acc;
        g_upad = (acc + 63) & ~63;
    }
    __syncthreads();
    for (int w = tid; w < 250; w += 1024) {
        unsigned m = bm[w];
        int o = wo[w];
        while (m) {
            int b = __ffs(m) - 1;
            g_uniq[o++] = w * 32 + b;
            m &= m - 1;
        }
    }
    __syncthreads();
    if (tid < 64) {
        int uc = wo[250];
        int up = (uc + 63) & ~63;
        if (uc + tid < up) g_uniq[uc + tid] = g_uniq[0];
    }
}

// ---------------- kernel 1: gather unique K rows -> bf16 ----------------
__global__ void k_gather(const float* __restrict__ K) {
    int t = blockIdx.x * blockDim.x + threadIdx.x;
    int chunk = t & 7;
    int rest = t >> 3;
    int j = rest % LKS;
    int b = rest / LKS;
    if (b >= NB) return;
    if (j >= g_upad) return;
    int src = g_uniq[j];
    const float4* p = (const float4*)(K + ((size_t)b * LK + src) * DH + chunk * 8);
    float4 v0 = p[0], v1 = p[1];
    uint4 w = make_uint4(packbf(v0.x, v0.y), packbf(v0.z, v0.w),
                         packbf(v1.x, v1.y), packbf(v1.z, v1.w));
    *(uint4*)(g_KsampH + ((size_t)(b * LKS) + j) * DH + chunk * 8) = w;
}

// ---------------- kernel 2a/2b: Ksum over full multiset, two-stage ----------
__global__ void k_ksum1(const float* __restrict__ K, const int* __restrict__ idx) {
    int b = blockIdx.y;
    int sp = blockIdx.x;                  // 0..7
    int d = threadIdx.x & 63;
    int g = threadIdx.x >> 6;
    float s = 0.f;
    for (int u = sp * 1000 + g; u < (sp + 1) * 1000; u += 4)
        s += K[((size_t)b * LK + idx[u]) * DH + d];
    __shared__ float red[4][64];
    red[g][d] = s;
    __syncthreads();
    if (g == 0)
        g_KsumP[(b * 8 + sp) * DH + d] = red[0][d] + red[1][d] + red[2][d] + red[3][d];
}
__global__ void k_ksum2() {
    int b = blockIdx.x;
    int d = threadIdx.x;
    float s = 0.f;
#pragma unroll
    for (int sp = 0; sp < 8; ++sp) s += g_KsumP[(b * 8 + sp) * DH + d];
    g_Ksum[b * DH + d] = s;
}

// ---------------- kernel 3: approx M via bf16 mma + ldmatrix ---------------
// block 256 thr = 8 warps; m-tile 64, n-tile 64; warp: m32 x n16
__global__ __launch_bounds__(256) void k_M_mma(const float* __restrict__ q) {
    __shared__ __nv_bfloat16 Bs[2][64 * 72];
    __shared__ float rowmaxS[4][64];
    __shared__ float ksumS[64];

    const int tid  = threadIdx.x;
    const int wid  = tid >> 5;
    const int lane = tid & 31;
    const int gid  = lane >> 2;
    const int tig  = lane & 3;
    const int b    = blockIdx.y;
    const int m0   = blockIdx.x * 64;
    const int mwarp = (wid & 1) * 32;
    const int nquad = wid >> 1;           // 0..3 -> n = nquad*16

    if (tid < 64) ksumS[tid] = g_Ksum[b * DH + tid];

    // A fragments (persist)
    uint32_t a[2][4][4];
#pragma unroll
    for (int mb = 0; mb < 2; ++mb) {
        int r0 = m0 + mwarp + mb * 16 + gid;
        int r1 = r0 + 8;
        const float* q0 = q + ((size_t)(b * LQ) + r0) * DH;
        const float* q1 = q + ((size_t)(b * LQ) + r1) * DH;
#pragma unroll
        for (int kk = 0; kk < 4; ++kk) {
            int c = kk * 16 + 2 * tig;
            float2 x0 = *(const float2*)(q0 + c);
            float2 x1 = *(const float2*)(q1 + c);
            float2 x2 = *(const float2*)(q0 + c + 8);
            float2 x3 = *(const float2*)(q1 + c + 8);
            a[mb][kk][0] = packbf(x0.x, x0.y);
            a[mb][kk][1] = packbf(x1.x, x1.y);
            a[mb][kk][2] = packbf(x2.x, x2.y);
            a[mb][kk][3] = packbf(x3.x, x3.y);
        }
    }

    const int niter = g_upad >> 6;
    const int prow = tid >> 2, pseg = tid & 3;
    uint32_t sBase = (uint32_t)__cvta_generic_to_shared(&Bs[0][0]);

    {   // prologue: tile 0
        const __nv_bfloat16* src = g_KsampH + ((size_t)(b * LKS) + prow) * DH + pseg * 16;
        uint32_t dst = sBase + prow * 144 + pseg * 32;
        cp16(dst, src);
        cp16(dst + 16, src + 8);
    }
    asm volatile("cp.async.commit_group;\n");

    float rmax[2][2];
    rmax[0][0] = rmax[0][1] = rmax[1][0] = rmax[1][1] = -INFINITY;

    for (int t = 0; t < niter; ++t) {
        asm volatile("cp.async.wait_group 0;\n");
        __syncthreads();
        if (t + 1 < niter) {
            const __nv_bfloat16* src =
                g_KsampH + ((size_t)(b * LKS) + (t + 1) * 64 + prow) * DH + pseg * 16;
            uint32_t dst = sBase + ((t + 1) & 1) * 9216 + prow * 144 + pseg * 32;
            cp16(dst, src);
            cp16(dst + 16, src + 8);
        }
        asm volatile("cp.async.commit_group;\n");

        uint32_t bufBase = sBase + (t & 1) * 9216;
#pragma unroll
        for (int nc = 0; nc < 2; ++nc) {
            int nb = nquad * 16 + nc * 8;
            int row = nb + (lane & 7);
            uint32_t addr0 = bufBase + (uint32_t)(row * 144 + (lane >> 3) * 16);
            uint32_t bk[4], bk2[4];
            ldsm_x4(bk,  addr0);          // k 0..31
            ldsm_x4(bk2, addr0 + 64);     // k 32..63
            float acc0[4] = {0.f, 0.f, 0.f, 0.f};
            float acc1[4] = {0.f, 0.f, 0.f, 0.f};
            mma_bf16(acc0, a[0][0], bk[0],  bk[1]);
            mma_bf16(acc1, a[1][0], bk[0],  bk[1]);
            mma_bf16(acc0, a[0][1], bk[2],  bk[3]);
            mma_bf16(acc1, a[1][1], bk[2],  bk[3]);
            mma_bf16(acc0, a[0][2], bk2[0], bk2[1]);
            mma_bf16(acc1, a[1][2], bk2[0], bk2[1]);
            mma_bf16(acc0, a[0][3], bk2[2], bk2[3]);
            mma_bf16(acc1, a[1][3], bk2[2], bk2[3]);
            rmax[0][0] = fmaxf(rmax[0][0], fmaxf(acc0[0], acc0[1]));
            rmax[0][1] = fmaxf(rmax[0][1], fmaxf(acc0[2], acc0[3]));
            rmax[1][0] = fmaxf(rmax[1][0], fmaxf(acc1[0], acc1[1]));
            rmax[1][1] = fmaxf(rmax[1][1], fmaxf(acc1[2], acc1[3]));
        }
    }

#pragma unroll
    for (int mb = 0; mb < 2; ++mb)
#pragma unroll
        for (int h = 0; h < 2; ++h) {
            rmax[mb][h] = fmaxf(rmax[mb][h], __shfl_xor_sync(0xffffffffu, rmax[mb][h], 1));
            rmax[mb][h] = fmaxf(rmax[mb][h], __shfl_xor_sync(0xffffffffu, rmax[mb][h], 2));
        }
    if (tig == 0) {
        rowmaxS[nquad][mwarp + gid]      = rmax[0][0];
        rowmaxS[nquad][mwarp + gid + 8]  = rmax[0][1];
        rowmaxS[nquad][mwarp + 16 + gid] = rmax[1][0];
        rowmaxS[nquad][mwarp + 24 + gid] = rmax[1][1];
    }
    __syncthreads();

    if (tid < 64) {
        int m = m0 + tid;
        float mx = fmaxf(fmaxf(rowmaxS[0][tid], rowmaxS[1][tid]),
                         fmaxf(rowmaxS[2][tid], rowmaxS[3][tid]));
        const float* qp = q + ((size_t)(b * LQ) + m) * DH;
        float d0 = 0.f, d1 = 0.f, d2 = 0.f, d3 = 0.f;
#pragma unroll
        for (int d = 0; d < 64; d += 4) {
            d0 += qp[d]     * ksumS[d];
            d1 += qp[d + 1] * ksumS[d + 1];
            d2 += qp[d + 2] * ksumS[d + 2];
            d3 += qp[d + 3] * ksumS[d + 3];
        }
        g_M[b * LQ + m] = mx - ((d0 + d1) + (d2 + d3)) * (1.0f / (float)LKS);
    }
}

// ---------------- kernel 4: histogram threshold + candidate collect --------
__global__ __launch_bounds__(512) void k_thresh() {
    const int b = blockIdx.x;
    const int tid = threadIdx.x;
    __shared__ float sv[LQ];
    __shared__ int hist[512];
    __shared__ float wmn[16], wmx[16];
    __shared__ float s_mn, s_range, s_thresh;
    __shared__ int s_cnt;

    float mn = INFINITY, mx = -INFINITY;
    for (int j = tid; j < LQ; j += 512) {
        float v = g_M[b * LQ + j];
        sv[j] = v;
        mn = fminf(mn, v);
        mx = fmaxf(mx, v);
    }
#pragma unroll
    for (int off = 16; off > 0; off >>= 1) {
        mn = fminf(mn, __shfl_xor_sync(0xffffffffu, mn, off));
        mx = fmaxf(mx, __shfl_xor_sync(0xffffffffu, mx, off));
    }
    if ((tid & 31) == 0) { wmn[tid >> 5] = mn; wmx[tid >> 5] = mx; }
    if (tid < 512) hist[tid] = 0;
    if (tid == 0) s_cnt = 0;
    __syncthreads();
    if (tid == 0) {
        float a = INFINITY, z = -INFINITY;
        for (int g = 0; g < 16; ++g) { a = fminf(a, wmn[g]); z = fmaxf(z, wmx[g]); }
        s_mn = a;
        s_range = z - a + 1e-6f;
    }
    __syncthreads();
    const float scale = 511.0f / s_range;
    for (int j = tid; j < LQ; j += 512) {
        int bin = (int)((sv[j] - s_mn) * scale);
        bin = max(0, min(511, bin));
        atomicAdd(&hist[bin], 1);
    }
    __syncthreads();
    if (tid == 0) {
        int cum = 0, bsel = 511;
        for (int i = 0; i < 512; ++i) {
            cum += hist[i];
            if (cum >= NU) { bsel = i; break; }
        }
        s_thresh = s_mn + (float)(bsel + 1) * (s_range / 511.0f) + MARGIN;
    }
    __syncthreads();
    const float th = s_thresh;
    for (int j = tid; j < LQ; j += 512) {
        if (sv[j] <= th) {
            int p = atomicAdd(&s_cnt, 1);
            if (p < CANDMAX) g_cand[b * CANDMAX + p] = j;
        }
    }
    __syncthreads();
    if (tid == 0) g_ccount[b] = min(s_cnt, CANDMAX);
}

// ---------------- kernel 5: exact fp32 max (split-K over unique keys) ------
__global__ __launch_bounds__(256) void k_M_exact(const float* __restrict__ q,
                                                 const float* __restrict__ K) {
    extern __shared__ float sh[];
    float* Kc = sh;                 // [<=250][68]
    float* Qc = sh + 250 * 68;      // [128][68]

    const int b = blockIdx.y;
    const int sp = blockIdx.x;
    const int tid = threadIdx.x;
    const int wid = tid >> 5;
    const int lane = tid & 31;

    const int uc = g_ucount;
    const int j0 = (sp * uc) / NSPLIT;
    const int j1 = ((sp + 1) * uc) / NSPLIT;
    const int nr = j1 - j0;

    for (int i = tid; i < nr * 16; i += 256) {
        int r = i >> 4, d4 = i & 15;
        int src = g_uniq[j0 + r];
        *(float4*)&Kc[r * 68 + 4 * d4] =
            *(const float4*)(K + ((size_t)b * LK + src) * DH + 4 * d4);
    }
    const int cnt = g_ccount[b];

    for (int cg = 0; cg < cnt; cg += 128) {
        int ncg = min(128, cnt - cg);
        __syncthreads();
        for (int i = tid; i < ncg * 16; i += 256) {
            int c = i >> 4, d4 = i & 15;
            int qi = g_cand[b * CANDMAX + cg + c];
            *(float4*)&Qc[c * 68 + 4 * d4] =
                *(const float4*)(q + ((size_t)(b * LQ) + qi) * DH + 4 * d4);
        }
        __syncthreads();
        for (int c = wid; c < ncg; c += 8) {
            const float* qr = &Qc[c * 68];
            float mx = -INFINITY;
            for (int r = lane; r < nr; r += 32) {
                const float* kr = &Kc[r * 68];
                float a0 = 0.f, a1 = 0.f, a2 = 0.f, a3 = 0.f;
#pragma unroll
                for (int d4 = 0; d4 < 16; ++d4) {
                    float4 kv = *(const float4*)&kr[4 * d4];
                    float4 qv = *(const float4*)&qr[4 * d4];
                    a0 += qv.x * kv.x;
                    a1 += qv.y * kv.y;
                    a2 += qv.z * kv.z;
                    a3 += qv.w * kv.w;
                }
                mx = fmaxf(mx, (a0 + a1) + (a2 + a3));
            }
#pragma unroll
            for (int off = 16; off > 0; off >>= 1)
                mx = fmaxf(mx, __shfl_xor_sync(0xffffffffu, mx, off));
            if (lane == 0)
                g_candP[((size_t)(b * CANDMAX) + cg + c) * NSPLIT + sp] = mx;
        }
    }
}

// ---------------- kernel 6: finalize exact M + top-45 selection ------------
__global__ __launch_bounds__(256) void k_select(const float* __restrict__ q) {
    const int b = blockIdx.x;
    const int tid = threadIdx.x;
    __shared__ float cv[CANDMAX];
    __shared__ int   ci[CANDMAX];
    const int cnt = g_ccount[b];

    for (int c = tid; c < CANDMAX; c += 256) {
        if (c < cnt) {
            float mx = -INFINITY;
#pragma unroll
            for (int s = 0; s < NSPLIT; ++s)
                mx = fmaxf(mx, g_candP[((size_t)(b * CANDMAX) + c) * NSPLIT + s]);
            int qi = g_cand[b * CANDMAX + c];
            const float* qp = q + ((size_t)(b * LQ) + qi) * DH;
            float dot = 0.f;
            for (int d = 0; d < 64; ++d) dot += qp[d] * g_Ksum[b * DH + d];
            cv[c] = mx - dot * (1.0f / (float)LKS);
            ci[c] = qi;
        } else {
            cv[c] = INFINITY;
            ci[c] = 1 << 30;
        }
    }
    __syncthreads();

    if (tid < 32) {
        for (int it = 0; it < NU; ++it) {
            float best = INFINITY; int bidx = 1 << 30; int bslot = 0;
            for (int j = tid; j < CANDMAX; j += 32) {
                float v = cv[j]; int qi2 = ci[j];
                if (v < best || (v == best && qi2 < bidx)) { best = v; bidx = qi2; bslot = j; }
            }
#pragma unroll
            for (int off = 16; off > 0; off >>= 1) {
                float v2 = __shfl_xor_sync(0xffffffffu, best, off);
                int   i2 = __shfl_xor_sync(0xffffffffu, bidx, off);
                int   s2 = __shfl_xor_sync(0xffffffffu, bslot, off);
                if (v2 < best || (v2 == best && i2 < bidx)) { best = v2; bidx = i2; bslot = s2; }
            }
            if (tid == 0) { g_top[b * NUP + it] = bidx; cv[bslot] = INFINITY; }
            __syncwarp();
        }
        if (tid < NUP - NU) g_top[b * NUP + NU + tid] = 0;
    }
}

// ---------------- kernel 7: scores + flash softmax (warp-private) ----------
__global__ __launch_bounds__(256) void k_attn(const float* __restrict__ q,
                                              const float* __restrict__ K,
                                              const float* __restrict__ V,
                                              float* __restrict__ out_s) {
    extern __shared__ float sm[];
    float* qsT = sm;                          // [64][50]
    float* ksT = qsT + 64 * 50;               // [64][132]
    float* Vs  = ksT + 64 * 132;              // [128][68]
    float* Ps  = Vs + 128 * 68;               // [48][132]

    const int tid = threadIdx.x;
    const int ty = tid >> 5;
    const int tx = tid & 31;
    const int b = blockIdx.y;
    const int chunk = blockIdx.x;
    const int kchunk0 = chunk * CK;

#pragma unroll
    for (int i = 0; i < 3; ++i) {
        int fidx = tid + 256 * i;
        int u    = fidx >> 4;
        int dblk = fidx & 15;
        float4 v = make_float4(0.f, 0.f, 0.f, 0.f);
        if (u < NU) {
            int qi = g_top[b * NUP + u];
            v = *(const float4*)(q + ((size_t)(b * LQ + qi)) * DH + 4 * dblk);
        }
        qsT[(4 * dblk + 0) * 50 + u] = v.x;
        qsT[(4 * dblk + 1) * 50 + u] = v.y;
        qsT[(4 * dblk + 2) * 50 + u] = v.z;
        qsT[(4 * dblk + 3) * 50 + u] = v.w;
    }

    float mrun[6], lrun[6];
#pragma unroll
    for (int i = 0; i < 6; ++i) { mrun[i] = -INFINITY; lrun[i] = 0.f; }
    float acc[6][2];
#pragma unroll
    for (int i = 0; i < 6; ++i) { acc[i][0] = 0.f; acc[i][1] = 0.f; }

    for (int kt = 0; kt < CK / 128; ++kt) {
        const int kg0 = kchunk0 + kt * 128;
        __syncthreads();
#pragma unroll
        for (int i = 0; i < 8; ++i) {
            int fidx = tid + 256 * i;
            int k    = fidx >> 4;
            int dblk = fidx & 15;
            float4 kv = *(const float4*)(K + ((size_t)(b * LK + kg0 + k)) * DH + 4 * dblk);
            ksT[(4 * dblk + 0) * 132 + k] = kv.x;
            ksT[(4 * dblk + 1) * 132 + k] = kv.y;
            ksT[(4 * dblk + 2) * 132 + k] = kv.z;
            ksT[(4 * dblk + 3) * 132 + k] = kv.w;
            float4 vv = *(const float4*)(V + ((size_t)(b * LK + kg0 + k)) * DH + 4 * dblk);
            *(float4*)&Vs[k * 68 + 4 * dblk] = vv;
        }
        __syncthreads();

        float s[6][4];
#pragma unroll
        for (int i = 0; i < 6; ++i)
#pragma unroll
            for (int j = 0; j < 4; ++j) s[i][j] = 0.f;

#pragma unroll 4
        for (int d = 0; d < 64; ++d) {
            const float* qr = &qsT[d * 50 + 6 * ty];
            float2 q01 = *(const float2*)(qr);
            float2 q23 = *(const float2*)(qr + 2);
            float2 q45 = *(const float2*)(qr + 4);
            float4 kv  = *(const float4*)&ksT[d * 132 + 4 * tx];
            float qa[6] = {q01.x, q01.y, q23.x, q23.y, q45.x, q45.y};
            float kb[4] = {kv.x, kv.y, kv.z, kv.w};
#pragma unroll
            for (int i = 0; i < 6; ++i)
#pragma unroll
                for (int j = 0; j < 4; ++j) s[i][j] += qa[i] * kb[j];
        }
#pragma unroll
        for (int i = 0; i < 6; ++i)
#pragma unroll
            for (int j = 0; j < 4; ++j) s[i][j] *= 0.125f;

#pragma unroll
        for (int i = 0; i < 6; ++i) {
            int u = 6 * ty + i;
            if (u < NU) {
                float4 w = make_float4(s[i][0], s[i][1], s[i][2], s[i][3]);
                *(float4*)(out_s + ((size_t)(b * NU + u)) * LK + kg0 + 4 * tx) = w;
            }
        }

        // warp-private online softmax (each warp owns rows 6*ty..6*ty+5)
#pragma unroll
        for (int i = 0; i < 6; ++i) {
            float mx = fmaxf(fmaxf(s[i][0], s[i][1]), fmaxf(s[i][2], s[i][3]));
#pragma unroll
            for (int off = 16; off > 0; off >>= 1)
                mx = fmaxf(mx, __shfl_xor_sync(0xffffffffu, mx, off));
            float mn = fmaxf(mrun[i], mx);
            float f  = __expf(mrun[i] - mn);
            float p0 = __expf(s[i][0] - mn);
            float p1 = __expf(s[i][1] - mn);
            float p2 = __expf(s[i][2] - mn);
            float p3 = __expf(s[i][3] - mn);
            float ps = p0 + p1 + p2 + p3;
#pragma unroll
            for (int off = 16; off > 0; off >>= 1)
                ps += __shfl_xor_sync(0xffffffffu, ps, off);
            lrun[i] = lrun[i] * f + ps;
            mrun[i] = mn;
            *(float4*)&Ps[(6 * ty + i) * 132 + 4 * tx] = make_float4(p0, p1, p2, p3);
            acc[i][0] *= f;
            acc[i][1] *= f;
        }
        __syncwarp();

#pragma unroll 2
        for (int k = 0; k < 128; k += 2) {
            float2 va = *(const float2*)&Vs[k * 68 + 2 * tx];
            float2 vb = *(const float2*)&Vs[(k + 1) * 68 + 2 * tx];
#pragma unroll
            for (int i = 0; i < 6; ++i) {
                float2 pp = *(const float2*)&Ps[(6 * ty + i) * 132 + k];
                acc[i][0] += pp.x * va.x;
                acc[i][0] += pp.y * vb.x;
                acc[i][1] += pp.x * va.y;
                acc[i][1] += pp.y * vb.y;
            }
        }
    }

    if (tx == 0) {
#pragma unroll
        for (int i = 0; i < 6; ++i) {
            int u = 6 * ty + i;
            g_pm[(b * NCHUNK + chunk) * NUP + u] = mrun[i];
            g_pl[(b * NCHUNK + chunk) * NUP + u] = lrun[i];
        }
    }
#pragma unroll
    for (int i = 0; i < 6; ++i) {
        int u = 6 * ty + i;
        *(float2*)&g_pacc[((size_t)(b * NCHUNK + chunk) * NUP + u) * DH + 2 * tx] =
            make_float2(acc[i][0], acc[i][1]);
    }
}

// ---------------- kernel 8: combine split-softmax partials ----------------
__global__ void k_combine(float* __restrict__ out_o) {
    int u = blockIdx.x;
    int b = blockIdx.y;
    int d = threadIdx.x;
    float gm = -INFINITY;
    for (int c = 0; c < NCHUNK; ++c)
        gm = fmaxf(gm, g_pm[(b * NCHUNK + c) * NUP + u]);
    float L = 0.f, a = 0.f;
    for (int c = 0; c < NCHUNK; ++c) {
        float w = __expf(g_pm[(b * NCHUNK + c) * NUP + u] - gm);
        L += g_pl[(b * NCHUNK + c) * NUP + u] * w;
        a += g_pacc[((size_t)(b * NCHUNK + c) * NUP + u) * DH + d] * w;
    }
    out_o[(b * NU + u) * DH + d] = a / L;
}

// ---------------- launch ----------------
extern "C" void kernel_launch(void* const* d_in, const int* in_sizes, int n_in,
                              void* d_out, int out_size) {
    const float* q  = (const float*)d_in[0];
    const float* K  = (const float*)d_in[1];
    const float* V  = (const float*)d_in[2];
    const int* idx  = (const int*)d_in[3];
    float* out_o = (float*)d_out;                  // attn_output [8,45,64]
    float* out_s = out_o + NB * NU * DH;           // attn_scores [8,45,32768]

    (void)in_sizes; (void)n_in; (void)out_size;

    const int smem_attn  = (64 * 50 + 64 * 132 + 128 * 68 + 48 * 132) * 4;  // 106752
    const int smem_exact = (250 * 68 + 128 * 68) * 4;                        // 102816
    cudaFuncSetAttribute(k_attn,    cudaFuncAttributeMaxDynamicSharedMemorySize, smem_attn);
    cudaFuncSetAttribute(k_M_exact, cudaFuncAttributeMaxDynamicSharedMemorySize, smem_exact);

    k_dedup<<<1, 1024>>>(idx);
    k_gather<<<(NB * LKS * 8 + 255) / 256, 256>>>(K);
    k_ksum1<<<dim3(8, NB), 256>>>(K, idx);
    k_ksum2<<<NB, 64>>>();
    k_M_mma<<<dim3(LQ / 64, NB), 256>>>(q);
    k_thresh<<<NB, 512>>>();
    k_M_exact<<<dim3(NSPLIT, NB), 256, smem_exact>>>(q, K);
    k_select<<<NB, 256>>>(q);
    k_attn<<<dim3(NCHUNK, NB), 256, smem_attn>>>(q, K, V, out_s);
    k_combine<<<dim3(NU, NB), 64>>>(out_o);
}

// round 6
// speedup vs baseline: 3.3488x; 1.0197x over previous
#include <cuda_runtime.h>
#include <cuda_bf16.h>
#include <math.h>
#include <stdint.h>

#define NB 8
#define LQ 4096
#define LK 32768
#define DH 64
#define LKS 8000
#define NU 45
#define NUP 48
#define NCHUNK 64
#define CK 512
#define KT 64
#define CANDMAX 1024
#define NSPLIT 32
#define MARGIN 1.0f

// ---------------- device scratch ----------------
__device__ __nv_bfloat16 g_KsampH[NB * LKS * DH];
__device__ int   g_uniq[LKS];
__device__ int   g_ucount;
__device__ int   g_upad;
__device__ float g_KsumP[NB * 8 * DH];
__device__ float g_Ksum[NB * DH];
__device__ float g_M[NB * LQ];
__device__ int   g_top[NB * NUP];
__device__ int   g_cand[NB * CANDMAX];
__device__ float g_candP[NB * CANDMAX * NSPLIT];
__device__ int   g_ccount[NB];
__device__ float g_pm[NB * NCHUNK * NUP];
__device__ float g_pl[NB * NCHUNK * NUP];
__device__ float g_pacc[NB * NCHUNK * NUP * DH];

// ---------------- helpers ----------------
__device__ __forceinline__ void mma_bf16(float c[4], const uint32_t a[4],
                                         uint32_t b0, uint32_t b1) {
    asm volatile(
        "mma.sync.aligned.m16n8k16.row.col.f32.bf16.bf16.f32 "
        "{%0,%1,%2,%3}, {%4,%5,%6,%7}, {%8,%9}, {%0,%1,%2,%3};"
        : "+f"(c[0]), "+f"(c[1]), "+f"(c[2]), "+f"(c[3])
        : "r"(a[0]), "r"(a[1]), "r"(a[2]), "r"(a[3]), "r"(b0), "r"(b1));
}
__device__ __forceinline__ void mma_tf32(float c[4], const uint32_t a[4],
                                         uint32_t b0, uint32_t b1) {
    asm volatile(
        "mma.sync.aligned.m16n8k8.row.col.f32.tf32.tf32.f32 "
        "{%0,%1,%2,%3}, {%4,%5,%6,%7}, {%8,%9}, {%0,%1,%2,%3};"
        : "+f"(c[0]), "+f"(c[1]), "+f"(c[2]), "+f"(c[3])
        : "r"(a[0]), "r"(a[1]), "r"(a[2]), "r"(a[3]), "r"(b0), "r"(b1));
}
__device__ __forceinline__ uint32_t packbf(float x, float y) {
    __nv_bfloat162 h = __floats2bfloat162_rn(x, y);
    return *(uint32_t*)&h;
}
__device__ __forceinline__ void cp16(uint32_t dst, const void* src) {
    asm volatile("cp.async.ca.shared.global [%0], [%1], 16;\n" :: "r"(dst), "l"(src));
}
__device__ __forceinline__ void ldsm_x4(uint32_t r[4], uint32_t addr) {
    asm volatile("ldmatrix.sync.aligned.m8n8.x4.shared.b16 {%0,%1,%2,%3}, [%4];"
                 : "=r"(r[0]), "=r"(r[1]), "=r"(r[2]), "=r"(r[3]) : "r"(addr));
}
__device__ __forceinline__ void tf32split(float x, uint32_t& hi, uint32_t& lo) {
    uint32_t h;
    asm("cvt.rna.tf32.f32 %0, %1;" : "=r"(h) : "f"(x));
    float rem = x - __uint_as_float(h);
    asm("cvt.rna.tf32.f32 %0, %1;" : "=r"(lo) : "f"(rem));
    hi = h;
}

// ---------------- kernel 0: dedupe sampled indices ----------------
__global__ void k_dedup(const int* __restrict__ idx) {
    __shared__ unsigned bm[250];
    __shared__ int wo[251];
    int tid = threadIdx.x;
    for (int i = tid; i < 250; i += 1024) bm[i] = 0u;
    __syncthreads();
    for (int i = tid; i < LKS; i += 1024) {
        int v = idx[i];
        atomicOr(&bm[v >> 5], 1u << (v & 31));
    }
    __syncthreads();
    if (tid == 0) {
        int acc = 0;
        for (int w = 0; w < 250; ++w) { wo[w] = acc; acc += __popc(bm[w]); }
        wo[250] = acc;
        g_ucount = acc;
        g_upad = (acc + 63) & ~63;
    }
    __syncthreads();
    for (int w = tid; w < 250; w += 1024) {
        unsigned m = bm[w];
        int o = wo[w];
        while (m) {
            int b = __ffs(m) - 1;
            g_uniq[o++] = w * 32 + b;
            m &= m - 1;
        }
    }
    __syncthreads();
    if (tid < 64) {
        int uc = wo[250];
        int up = (uc + 63) & ~63;
        if (uc + tid < up) g_uniq[uc + tid] = g_uniq[0];
    }
}

// ---------------- kernel 1: gather unique K rows -> bf16 ----------------
__global__ void k_gather(const float* __restrict__ K) {
    int t = blockIdx.x * blockDim.x + threadIdx.x;
    int chunk = t & 7;
    int rest = t >> 3;
    int j = rest % LKS;
    int b = rest / LKS;
    if (b >= NB) return;
    if (j >= g_upad) return;
    int src = g_uniq[j];
    const float4* p = (const float4*)(K + ((size_t)b * LK + src) * DH + chunk * 8);
    float4 v0 = p[0], v1 = p[1];
    uint4 w = make_uint4(packbf(v0.x, v0.y), packbf(v0.z, v0.w),
                         packbf(v1.x, v1.y), packbf(v1.z, v1.w));
    *(uint4*)(g_KsampH + ((size_t)(b * LKS) + j) * DH + chunk * 8) = w;
}

// ---------------- kernel 2a/2b: Ksum, two-stage ----------------
__global__ void k_ksum1(const float* __restrict__ K, const int* __restrict__ idx) {
    int b = blockIdx.y;
    int sp = blockIdx.x;
    int d = threadIdx.x & 63;
    int g = threadIdx.x >> 6;
    float s = 0.f;
    for (int u = sp * 1000 + g; u < (sp + 1) * 1000; u += 4)
        s += K[((size_t)b * LK + idx[u]) * DH + d];
    __shared__ float red[4][64];
    red[g][d] = s;
    __syncthreads();
    if (g == 0)
        g_KsumP[(b * 8 + sp) * DH + d] = red[0][d] + red[1][d] + red[2][d] + red[3][d];
}
__global__ void k_ksum2() {
    int b = blockIdx.x;
    int d = threadIdx.x;
    float s = 0.f;
#pragma unroll
    for (int sp = 0; sp < 8; ++sp) s += g_KsumP[(b * 8 + sp) * DH + d];
    g_Ksum[b * DH + d] = s;
}

// ---------------- kernel 3: approx M via bf16 mma + ldmatrix ---------------
__global__ __launch_bounds__(256) void k_M_mma(const float* __restrict__ q) {
    __shared__ __nv_bfloat16 Bs[2][64 * 72];
    __shared__ float rowmaxS[4][64];
    __shared__ float ksumS[64];

    const int tid  = threadIdx.x;
    const int wid  = tid >> 5;
    const int lane = tid & 31;
    const int gid  = lane >> 2;
    const int tig  = lane & 3;
    const int b    = blockIdx.y;
    const int m0   = blockIdx.x * 64;
    const int mwarp = (wid & 1) * 32;
    const int nquad = wid >> 1;

    if (tid < 64) ksumS[tid] = g_Ksum[b * DH + tid];

    uint32_t a[2][4][4];
#pragma unroll
    for (int mb = 0; mb < 2; ++mb) {
        int r0 = m0 + mwarp + mb * 16 + gid;
        int r1 = r0 + 8;
        const float* q0 = q + ((size_t)(b * LQ) + r0) * DH;
        const float* q1 = q + ((size_t)(b * LQ) + r1) * DH;
#pragma unroll
        for (int kk = 0; kk < 4; ++kk) {
            int c = kk * 16 + 2 * tig;
            float2 x0 = *(const float2*)(q0 + c);
            float2 x1 = *(const float2*)(q1 + c);
            float2 x2 = *(const float2*)(q0 + c + 8);
            float2 x3 = *(const float2*)(q1 + c + 8);
            a[mb][kk][0] = packbf(x0.x, x0.y);
            a[mb][kk][1] = packbf(x1.x, x1.y);
            a[mb][kk][2] = packbf(x2.x, x2.y);
            a[mb][kk][3] = packbf(x3.x, x3.y);
        }
    }

    const int niter = g_upad >> 6;
    const int prow = tid >> 2, pseg = tid & 3;
    uint32_t sBase = (uint32_t)__cvta_generic_to_shared(&Bs[0][0]);

    {
        const __nv_bfloat16* src = g_KsampH + ((size_t)(b * LKS) + prow) * DH + pseg * 16;
        uint32_t dst = sBase + prow * 144 + pseg * 32;
        cp16(dst, src);
        cp16(dst + 16, src + 8);
    }
    asm volatile("cp.async.commit_group;\n");

    float rmax[2][2];
    rmax[0][0] = rmax[0][1] = rmax[1][0] = rmax[1][1] = -INFINITY;

    for (int t = 0; t < niter; ++t) {
        asm volatile("cp.async.wait_group 0;\n");
        __syncthreads();
        if (t + 1 < niter) {
            const __nv_bfloat16* src =
                g_KsampH + ((size_t)(b * LKS) + (t + 1) * 64 + prow) * DH + pseg * 16;
            uint32_t dst = sBase + ((t + 1) & 1) * 9216 + prow * 144 + pseg * 32;
            cp16(dst, src);
            cp16(dst + 16, src + 8);
        }
        asm volatile("cp.async.commit_group;\n");

        uint32_t bufBase = sBase + (t & 1) * 9216;
#pragma unroll
        for (int nc = 0; nc < 2; ++nc) {
            int nb = nquad * 16 + nc * 8;
            int row = nb + (lane & 7);
            uint32_t addr0 = bufBase + (uint32_t)(row * 144 + (lane >> 3) * 16);
            uint32_t bk[4], bk2[4];
            ldsm_x4(bk,  addr0);
            ldsm_x4(bk2, addr0 + 64);
            float acc0[4] = {0.f, 0.f, 0.f, 0.f};
            float acc1[4] = {0.f, 0.f, 0.f, 0.f};
            mma_bf16(acc0, a[0][0], bk[0],  bk[1]);
            mma_bf16(acc1, a[1][0], bk[0],  bk[1]);
            mma_bf16(acc0, a[0][1], bk[2],  bk[3]);
            mma_bf16(acc1, a[1][1], bk[2],  bk[3]);
            mma_bf16(acc0, a[0][2], bk2[0], bk2[1]);
            mma_bf16(acc1, a[1][2], bk2[0], bk2[1]);
            mma_bf16(acc0, a[0][3], bk2[2], bk2[3]);
            mma_bf16(acc1, a[1][3], bk2[2], bk2[3]);
            rmax[0][0] = fmaxf(rmax[0][0], fmaxf(acc0[0], acc0[1]));
            rmax[0][1] = fmaxf(rmax[0][1], fmaxf(acc0[2], acc0[3]));
            rmax[1][0] = fmaxf(rmax[1][0], fmaxf(acc1[0], acc1[1]));
            rmax[1][1] = fmaxf(rmax[1][1], fmaxf(acc1[2], acc1[3]));
        }
    }

#pragma unroll
    for (int mb = 0; mb < 2; ++mb)
#pragma unroll
        for (int h = 0; h < 2; ++h) {
            rmax[mb][h] = fmaxf(rmax[mb][h], __shfl_xor_sync(0xffffffffu, rmax[mb][h], 1));
            rmax[mb][h] = fmaxf(rmax[mb][h], __shfl_xor_sync(0xffffffffu, rmax[mb][h], 2));
        }
    if (tig == 0) {
        rowmaxS[nquad][mwarp + gid]      = rmax[0][0];
        rowmaxS[nquad][mwarp + gid + 8]  = rmax[0][1];
        rowmaxS[nquad][mwarp + 16 + gid] = rmax[1][0];
        rowmaxS[nquad][mwarp + 24 + gid] = rmax[1][1];
    }
    __syncthreads();

    if (tid < 64) {
        int m = m0 + tid;
        float mx = fmaxf(fmaxf(rowmaxS[0][tid], rowmaxS[1][tid]),
                         fmaxf(rowmaxS[2][tid], rowmaxS[3][tid]));
        const float* qp = q + ((size_t)(b * LQ) + m) * DH;
        float d0 = 0.f, d1 = 0.f, d2 = 0.f, d3 = 0.f;
#pragma unroll
        for (int d = 0; d < 64; d += 4) {
            d0 += qp[d]     * ksumS[d];
            d1 += qp[d + 1] * ksumS[d + 1];
            d2 += qp[d + 2] * ksumS[d + 2];
            d3 += qp[d + 3] * ksumS[d + 3];
        }
        g_M[b * LQ + m] = mx - ((d0 + d1) + (d2 + d3)) * (1.0f / (float)LKS);
    }
}

// ---------------- kernel 4: histogram threshold + candidate collect --------
__global__ __launch_bounds__(512) void k_thresh() {
    const int b = blockIdx.x;
    const int tid = threadIdx.x;
    __shared__ float sv[LQ];
    __shared__ int hist[512];
    __shared__ float wmn[16], wmx[16];
    __shared__ float s_mn, s_range, s_thresh;
    __shared__ int s_cnt;

    float mn = INFINITY, mx = -INFINITY;
    for (int j = tid; j < LQ; j += 512) {
        float v = g_M[b * LQ + j];
        sv[j] = v;
        mn = fminf(mn, v);
        mx = fmaxf(mx, v);
    }
#pragma unroll
    for (int off = 16; off > 0; off >>= 1) {
        mn = fminf(mn, __shfl_xor_sync(0xffffffffu, mn, off));
        mx = fmaxf(mx, __shfl_xor_sync(0xffffffffu, mx, off));
    }
    if ((tid & 31) == 0) { wmn[tid >> 5] = mn; wmx[tid >> 5] = mx; }
    if (tid < 512) hist[tid] = 0;
    if (tid == 0) s_cnt = 0;
    __syncthreads();
    if (tid == 0) {
        float a = INFINITY, z = -INFINITY;
        for (int g = 0; g < 16; ++g) { a = fminf(a, wmn[g]); z = fmaxf(z, wmx[g]); }
        s_mn = a;
        s_range = z - a + 1e-6f;
    }
    __syncthreads();
    const float scale = 511.0f / s_range;
    for (int j = tid; j < LQ; j += 512) {
        int bin = (int)((sv[j] - s_mn) * scale);
        bin = max(0, min(511, bin));
        atomicAdd(&hist[bin], 1);
    }
    __syncthreads();
    if (tid == 0) {
        int cum = 0, bsel = 511;
        for (int i = 0; i < 512; ++i) {
            cum += hist[i];
            if (cum >= NU) { bsel = i; break; }
        }
        s_thresh = s_mn + (float)(bsel + 1) * (s_range / 511.0f) + MARGIN;
    }
    __syncthreads();
    const float th = s_thresh;
    for (int j = tid; j < LQ; j += 512) {
        if (sv[j] <= th) {
            int p = atomicAdd(&s_cnt, 1);
            if (p < CANDMAX) g_cand[b * CANDMAX + p] = j;
        }
    }
    __syncthreads();
    if (tid == 0) g_ccount[b] = min(s_cnt, CANDMAX);
}

// ---------------- kernel 5: exact fp32 max (split-K over unique keys) ------
__global__ __launch_bounds__(256) void k_M_exact(const float* __restrict__ q,
                                                 const float* __restrict__ K) {
    extern __shared__ float sh[];
    float* Kc = sh;
    float* Qc = sh + 250 * 68;

    const int b = blockIdx.y;
    const int sp = blockIdx.x;
    const int tid = threadIdx.x;
    const int wid = tid >> 5;
    const int lane = tid & 31;

    const int uc = g_ucount;
    const int j0 = (sp * uc) / NSPLIT;
    const int j1 = ((sp + 1) * uc) / NSPLIT;
    const int nr = j1 - j0;

    for (int i = tid; i < nr * 16; i += 256) {
        int r = i >> 4, d4 = i & 15;
        int src = g_uniq[j0 + r];
        *(float4*)&Kc[r * 68 + 4 * d4] =
            *(const float4*)(K + ((size_t)b * LK + src) * DH + 4 * d4);
    }
    const int cnt = g_ccount[b];

    for (int cg = 0; cg < cnt; cg += 128) {
        int ncg = min(128, cnt - cg);
        __syncthreads();
        for (int i = tid; i < ncg * 16; i += 256) {
            int c = i >> 4, d4 = i & 15;
            int qi = g_cand[b * CANDMAX + cg + c];
            *(float4*)&Qc[c * 68 + 4 * d4] =
                *(const float4*)(q + ((size_t)(b * LQ) + qi) * DH + 4 * d4);
        }
        __syncthreads();
        for (int c = wid; c < ncg; c += 8) {
            const float* qr = &Qc[c * 68];
            float mx = -INFINITY;
            for (int r = lane; r < nr; r += 32) {
                const float* kr = &Kc[r * 68];
                float a0 = 0.f, a1 = 0.f, a2 = 0.f, a3 = 0.f;
#pragma unroll
                for (int d4 = 0; d4 < 16; ++d4) {
                    float4 kv = *(const float4*)&kr[4 * d4];
                    float4 qv = *(const float4*)&qr[4 * d4];
                    a0 += qv.x * kv.x;
                    a1 += qv.y * kv.y;
                    a2 += qv.z * kv.z;
                    a3 += qv.w * kv.w;
                }
                mx = fmaxf(mx, (a0 + a1) + (a2 + a3));
            }
#pragma unroll
            for (int off = 16; off > 0; off >>= 1)
                mx = fmaxf(mx, __shfl_xor_sync(0xffffffffu, mx, off));
            if (lane == 0)
                g_candP[((size_t)(b * CANDMAX) + cg + c) * NSPLIT + sp] = mx;
        }
    }
}

// ---------------- kernel 6: finalize exact M + top-45 selection ------------
__global__ __launch_bounds__(256) void k_select(const float* __restrict__ q) {
    const int b = blockIdx.x;
    const int tid = threadIdx.x;
    __shared__ float cv[CANDMAX];
    __shared__ int   ci[CANDMAX];
    const int cnt = g_ccount[b];

    for (int c = tid; c < CANDMAX; c += 256) {
        if (c < cnt) {
            float mx = -INFINITY;
#pragma unroll
            for (int s = 0; s < NSPLIT; ++s)
                mx = fmaxf(mx, g_candP[((size_t)(b * CANDMAX) + c) * NSPLIT + s]);
            int qi = g_cand[b * CANDMAX + c];
            const float* qp = q + ((size_t)(b * LQ) + qi) * DH;
            float dot = 0.f;
            for (int d = 0; d < 64; ++d) dot += qp[d] * g_Ksum[b * DH + d];
            cv[c] = mx - dot * (1.0f / (float)LKS);
            ci[c] = qi;
        } else {
            cv[c] = INFINITY;
            ci[c] = 1 << 30;
        }
    }
    __syncthreads();

    if (tid < 32) {
        for (int it = 0; it < NU; ++it) {
            float best = INFINITY; int bidx = 1 << 30; int bslot = 0;
            for (int j = tid; j < CANDMAX; j += 32) {
                float v = cv[j]; int qi2 = ci[j];
                if (v < best || (v == best && qi2 < bidx)) { best = v; bidx = qi2; bslot = j; }
            }
#pragma unroll
            for (int off = 16; off > 0; off >>= 1) {
                float v2 = __shfl_xor_sync(0xffffffffu, best, off);
                int   i2 = __shfl_xor_sync(0xffffffffu, bidx, off);
                int   s2 = __shfl_xor_sync(0xffffffffu, bslot, off);
                if (v2 < best || (v2 == best && i2 < bidx)) { best = v2; bidx = i2; bslot = s2; }
            }
            if (tid == 0) { g_top[b * NUP + it] = bidx; cv[bslot] = INFINITY; }
            __syncwarp();
        }
        if (tid < NUP - NU) g_top[b * NUP + NU + tid] = 0;
    }
}

// ---------------- kernel 7: 3xTF32 mma attention ----------
// smem: Qb[48*68] Qs[48*68] Ks[64*68] Vs[64*72] SP[48*68] fS[48]
__global__ __launch_bounds__(256, 3) void k_attn(const float* __restrict__ q,
                                                 const float* __restrict__ K,
                                                 const float* __restrict__ V,
                                                 float* __restrict__ out_s) {
    extern __shared__ float sm[];
    float* Qb = sm;                  // 48*68
    float* Qs = Qb + 48 * 68;        // 48*68
    float* Ks = Qs + 48 * 68;        // 64*68
    float* Vs = Ks + 64 * 68;        // 64*72
    float* SP = Vs + 64 * 72;        // 48*68 (scores, then probs, in place)
    float* fS = SP + 48 * 68;        // 48

    const int tid = threadIdx.x;
    const int ty = tid >> 5;          // warp id 0..7
    const int tx = tid & 31;
    const int gid = tx >> 2;          // 0..7
    const int tig = tx & 3;           // 0..3
    const int b = blockIdx.y;
    const int chunk = blockIdx.x;
    const int kchunk0 = chunk * CK;

    // load 48 selected q rows, split into tf32 hi/lo
#pragma unroll
    for (int i = 0; i < 3; ++i) {
        int fidx = tid + 256 * i;        // 0..767
        int u    = fidx >> 4;
        int dblk = fidx & 15;
        float4 v = make_float4(0.f, 0.f, 0.f, 0.f);
        if (u < NU) {
            int qi = g_top[b * NUP + u];
            v = *(const float4*)(q + ((size_t)(b * LQ + qi)) * DH + 4 * dblk);
        }
        uint32_t h, l;
        tf32split(v.x, h, l);
        Qb[u * 68 + 4 * dblk + 0] = __uint_as_float(h);
        Qs[u * 68 + 4 * dblk + 0] = __uint_as_float(l);
        tf32split(v.y, h, l);
        Qb[u * 68 + 4 * dblk + 1] = __uint_as_float(h);
        Qs[u * 68 + 4 * dblk + 1] = __uint_as_float(l);
        tf32split(v.z, h, l);
        Qb[u * 68 + 4 * dblk + 2] = __uint_as_float(h);
        Qs[u * 68 + 4 * dblk + 2] = __uint_as_float(l);
        tf32split(v.w, h, l);
        Qb[u * 68 + 4 * dblk + 3] = __uint_as_float(h);
        Qs[u * 68 + 4 * dblk + 3] = __uint_as_float(l);
    }

    float mrun[6], lrun[6];
#pragma unroll
    for (int i = 0; i < 6; ++i) { mrun[i] = -INFINITY; lrun[i] = 0.f; }
    float oc[3][4];                   // O accumulator: warp owns cols 8*ty..8*ty+7
#pragma unroll
    for (int mt = 0; mt < 3; ++mt)
#pragma unroll
        for (int i = 0; i < 4; ++i) oc[mt][i] = 0.f;

    for (int kt = 0; kt < CK / KT; ++kt) {
        const int kg0 = kchunk0 + kt * KT;
        __syncthreads();
        // load K,V tile (64 keys x 64 dims), raw fp32
#pragma unroll
        for (int i = 0; i < 4; ++i) {
            int fidx = tid + 256 * i;     // 0..1023
            int k    = fidx >> 4;
            int d4   = fidx & 15;
            *(float4*)&Ks[k * 68 + 4 * d4] =
                *(const float4*)(K + ((size_t)(b * LK + kg0 + k)) * DH + 4 * d4);
            *(float4*)&Vs[k * 72 + 4 * d4] =
                *(const float4*)(V + ((size_t)(b * LK + kg0 + k)) * DH + 4 * d4);
        }
        __syncthreads();

        // ---- S phase: S = Q @ K^T via 3xtf32. warp ty owns key cols 8*ty..+7
        {
            float accS[3][4];
#pragma unroll
            for (int mt = 0; mt < 3; ++mt)
#pragma unroll
                for (int i = 0; i < 4; ++i) accS[mt][i] = 0.f;

#pragma unroll
            for (int ks = 0; ks < 8; ++ks) {
                float k0 = Ks[(8 * ty + gid) * 68 + ks * 8 + tig];
                float k1 = Ks[(8 * ty + gid) * 68 + ks * 8 + tig + 4];
                uint32_t kb0, ks0, kb1, ks1;
                tf32split(k0, kb0, ks0);
                tf32split(k1, kb1, ks1);
#pragma unroll
                for (int mt = 0; mt < 3; ++mt) {
                    int ra = (mt * 16 + gid) * 68 + ks * 8 + tig;
                    int rb = (mt * 16 + gid + 8) * 68 + ks * 8 + tig;
                    uint32_t ab[4], al[4];
                    ab[0] = __float_as_uint(Qb[ra]);
                    ab[1] = __float_as_uint(Qb[rb]);
                    ab[2] = __float_as_uint(Qb[ra + 4]);
                    ab[3] = __float_as_uint(Qb[rb + 4]);
                    al[0] = __float_as_uint(Qs[ra]);
                    al[1] = __float_as_uint(Qs[rb]);
                    al[2] = __float_as_uint(Qs[ra + 4]);
                    al[3] = __float_as_uint(Qs[rb + 4]);
                    mma_tf32(accS[mt], ab, kb0, kb1);
                    mma_tf32(accS[mt], ab, ks0, ks1);
                    mma_tf32(accS[mt], al, kb0, kb1);
                }
            }
            // write scaled scores to SP
#pragma unroll
            for (int mt = 0; mt < 3; ++mt) {
                int r0 = mt * 16 + gid;
                *(float2*)&SP[r0 * 68 + 8 * ty + 2 * tig] =
                    make_float2(accS[mt][0] * 0.125f, accS[mt][1] * 0.125f);
                *(float2*)&SP[(r0 + 8) * 68 + 8 * ty + 2 * tig] =
                    make_float2(accS[mt][2] * 0.125f, accS[mt][3] * 0.125f);
            }
        }
        __syncthreads();

        // ---- softmax phase: warp ty owns rows 6*ty..6*ty+5
#pragma unroll
        for (int i = 0; i < 6; ++i) {
            int u = 6 * ty + i;
            float2 sv = *(const float2*)&SP[u * 68 + 2 * tx];
            float mx = fmaxf(sv.x, sv.y);
#pragma unroll
            for (int off = 16; off > 0; off >>= 1)
                mx = fmaxf(mx, __shfl_xor_sync(0xffffffffu, mx, off));
            float mn = fmaxf(mrun[i], mx);
            float f  = __expf(mrun[i] - mn);
            float p0 = __expf(sv.x - mn);
            float p1 = __expf(sv.y - mn);
            float ps = p0 + p1;
#pragma unroll
            for (int off = 16; off > 0; off >>= 1)
                ps += __shfl_xor_sync(0xffffffffu, ps, off);
            lrun[i] = lrun[i] * f + ps;
            mrun[i] = mn;
            if (u < NU)
                *(float2*)(out_s + ((size_t)(b * NU + u)) * LK + kg0 + 2 * tx) = sv;
            *(float2*)&SP[u * 68 + 2 * tx] = make_float2(p0, p1);
            if (tx == 0) fS[u] = f;
        }
        __syncthreads();

        // ---- PV phase: O += P @ V via 3xtf32. warp ty owns O cols 8*ty..+7
#pragma unroll
        for (int mt = 0; mt < 3; ++mt) {
            float f0 = fS[mt * 16 + gid];
            float f1 = fS[mt * 16 + gid + 8];
            oc[mt][0] *= f0; oc[mt][1] *= f0;
            oc[mt][2] *= f1; oc[mt][3] *= f1;
        }
#pragma unroll
        for (int ks = 0; ks < 8; ++ks) {
            float v0 = Vs[(ks * 8 + tig) * 72 + 8 * ty + gid];
            float v1 = Vs[(ks * 8 + tig + 4) * 72 + 8 * ty + gid];
            uint32_t vb0, vl0, vb1, vl1;
            tf32split(v0, vb0, vl0);
            tf32split(v1, vb1, vl1);
#pragma unroll
            for (int mt = 0; mt < 3; ++mt) {
                int ra = (mt * 16 + gid) * 68 + ks * 8 + tig;
                int rb = (mt * 16 + gid + 8) * 68 + ks * 8 + tig;
                float p0 = SP[ra], p1 = SP[rb], p2 = SP[ra + 4], p3 = SP[rb + 4];
                uint32_t pb[4], pl[4];
                tf32split(p0, pb[0], pl[0]);
                tf32split(p1, pb[1], pl[1]);
                tf32split(p2, pb[2], pl[2]);
                tf32split(p3, pb[3], pl[3]);
                mma_tf32(oc[mt], pb, vb0, vb1);
                mma_tf32(oc[mt], pb, vl0, vl1);
                mma_tf32(oc[mt], pl, vb0, vb1);
            }
        }
    }

    // ---- write partials
    if (tx == 0) {
#pragma unroll
        for (int i = 0; i < 6; ++i) {
            int u = 6 * ty + i;
            g_pm[(b * NCHUNK + chunk) * NUP + u] = mrun[i];
            g_pl[(b * NCHUNK + chunk) * NUP + u] = lrun[i];
        }
    }
#pragma unroll
    for (int mt = 0; mt < 3; ++mt) {
        int r0 = mt * 16 + gid;
        *(float2*)&g_pacc[((size_t)(b * NCHUNK + chunk) * NUP + r0) * DH + 8 * ty + 2 * tig] =
            make_float2(oc[mt][0], oc[mt][1]);
        *(float2*)&g_pacc[((size_t)(b * NCHUNK + chunk) * NUP + r0 + 8) * DH + 8 * ty + 2 * tig] =
            make_float2(oc[mt][2], oc[mt][3]);
    }
}

// ---------------- kernel 8: combine split-softmax partials ----------------
__global__ void k_combine(float* __restrict__ out_o) {
    int u = blockIdx.x;
    int b = blockIdx.y;
    int d = threadIdx.x;
    float gm = -INFINITY;
    for (int c = 0; c < NCHUNK; ++c)
        gm = fmaxf(gm, g_pm[(b * NCHUNK + c) * NUP + u]);
    float L = 0.f, a = 0.f;
    for (int c = 0; c < NCHUNK; ++c) {
        float w = __expf(g_pm[(b * NCHUNK + c) * NUP + u] - gm);
        L += g_pl[(b * NCHUNK + c) * NUP + u] * w;
        a += g_pacc[((size_t)(b * NCHUNK + c) * NUP + u) * DH + d] * w;
    }
    out_o[(b * NU + u) * DH + d] = a / L;
}

// ---------------- launch ----------------
extern "C" void kernel_launch(void* const* d_in, const int* in_sizes, int n_in,
                              void* d_out, int out_size) {
    const float* q  = (const float*)d_in[0];
    const float* K  = (const float*)d_in[1];
    const float* V  = (const float*)d_in[2];
    const int* idx  = (const int*)d_in[3];
    float* out_o = (float*)d_out;                  // attn_output [8,45,64]
    float* out_s = out_o + NB * NU * DH;           // attn_scores [8,45,32768]

    (void)in_sizes; (void)n_in; (void)out_size;

    const int smem_attn  = (48 * 68 * 2 + 64 * 68 + 64 * 72 + 48 * 68 + 48) * 4; // 75200
    const int smem_exact = (250 * 68 + 128 * 68) * 4;                             // 102816
    cudaFuncSetAttribute(k_attn,    cudaFuncAttributeMaxDynamicSharedMemorySize, smem_attn);
    cudaFuncSetAttribute(k_M_exact, cudaFuncAttributeMaxDynamicSharedMemorySize, smem_exact);

    k_dedup<<<1, 1024>>>(idx);
    k_gather<<<(NB * LKS * 8 + 255) / 256, 256>>>(K);
    k_ksum1<<<dim3(8, NB), 256>>>(K, idx);
    k_ksum2<<<NB, 64>>>();
    k_M_mma<<<dim3(LQ / 64, NB), 256>>>(q);
    k_thresh<<<NB, 512>>>();
    k_M_exact<<<dim3(NSPLIT, NB), 256, smem_exact>>>(q, K);
    k_select<<<NB, 256>>>(q);
    k_attn<<<dim3(NCHUNK, NB), 256, smem_attn>>>(q, K, V, out_s);
    k_combine<<<dim3(NU, NB), 64>>>(out_o);
}

// round 8
// speedup vs baseline: 3.5482x; 1.0595x over previous
#include <cuda_runtime.h>
#include <cuda_bf16.h>
#include <math.h>
#include <stdint.h>

#define NB 8
#define LQ 4096
#define LK 32768
#define DH 64
#define LKS 8000
#define NU 45
#define NUP 48
#define NCHUNK 64
#define CK 512
#define KT 64
#define CANDMAX 1024
#define NSPLIT 32
#define MARGIN 1.0f

// ---------------- device scratch ----------------
__device__ __nv_bfloat16 g_KsampH[NB * LKS * DH];
__device__ int   g_uniq[LKS];
__device__ int   g_ucount;
__device__ int   g_upad;
__device__ float g_KsumP[NB * 8 * DH];
__device__ float g_Ksum[NB * DH];
__device__ float g_M[NB * LQ];
__device__ int   g_top[NB * NUP];
__device__ int   g_cand[NB * CANDMAX];
__device__ float g_candP[NB * CANDMAX * NSPLIT];
__device__ int   g_ccount[NB];
__device__ float g_pm[NB * NCHUNK * NUP];
__device__ float g_pl[NB * NCHUNK * NUP];
__device__ float g_pacc[NB * NCHUNK * NUP * DH];

// ---------------- helpers ----------------
__device__ __forceinline__ void mma_bf16(float c[4], const uint32_t a[4],
                                         uint32_t b0, uint32_t b1) {
    asm volatile(
        "mma.sync.aligned.m16n8k16.row.col.f32.bf16.bf16.f32 "
        "{%0,%1,%2,%3}, {%4,%5,%6,%7}, {%8,%9}, {%0,%1,%2,%3};"
        : "+f"(c[0]), "+f"(c[1]), "+f"(c[2]), "+f"(c[3])
        : "r"(a[0]), "r"(a[1]), "r"(a[2]), "r"(a[3]), "r"(b0), "r"(b1));
}
__device__ __forceinline__ uint32_t packbf(float x, float y) {
    __nv_bfloat162 h = __floats2bfloat162_rn(x, y);
    return *(uint32_t*)&h;
}
// split pair (x,y) into bf16 hi/lo packed u32s
__device__ __forceinline__ void bfsplit2(float x, float y, uint32_t& h, uint32_t& l) {
    __nv_bfloat16 hx = __float2bfloat16_rn(x), hy = __float2bfloat16_rn(y);
    float rx = x - __bfloat162float(hx);
    float ry = y - __bfloat162float(hy);
    __nv_bfloat16 lx = __float2bfloat16_rn(rx), ly = __float2bfloat16_rn(ry);
    h = ((uint32_t)(*(uint16_t*)&hy) << 16) | (uint32_t)(*(uint16_t*)&hx);
    l = ((uint32_t)(*(uint16_t*)&ly) << 16) | (uint32_t)(*(uint16_t*)&lx);
}
__device__ __forceinline__ void cp16(uint32_t dst, const void* src) {
    asm volatile("cp.async.ca.shared.global [%0], [%1], 16;\n" :: "r"(dst), "l"(src));
}
__device__ __forceinline__ void ldsm_x4(uint32_t r[4], uint32_t addr) {
    asm volatile("ldmatrix.sync.aligned.m8n8.x4.shared.b16 {%0,%1,%2,%3}, [%4];"
                 : "=r"(r[0]), "=r"(r[1]), "=r"(r[2]), "=r"(r[3]) : "r"(addr));
}

// ---------------- kernel 0: dedupe sampled indices ----------------
__global__ void k_dedup(const int* __restrict__ idx) {
    __shared__ unsigned bm[250];
    __shared__ int wo[251];
    int tid = threadIdx.x;
    for (int i = tid; i < 250; i += 1024) bm[i] = 0u;
    __syncthreads();
    for (int i = tid; i < LKS; i += 1024) {
        int v = idx[i];
        atomicOr(&bm[v >> 5], 1u << (v & 31));
    }
    __syncthreads();
    if (tid == 0) {
        int acc = 0;
        for (int w = 0; w < 250; ++w) { wo[w] = acc; acc += __popc(bm[w]); }
        wo[250] = acc;
        g_ucount = acc;
        g_upad = (acc + 63) & ~63;
    }
    __syncthreads();
    for (int w = tid; w < 250; w += 1024) {
        unsigned m = bm[w];
        int o = wo[w];
        while (m) {
            int b = __ffs(m) - 1;
            g_uniq[o++] = w * 32 + b;
            m &= m - 1;
        }
    }
    __syncthreads();
    if (tid < 64) {
        int uc = wo[250];
        int up = (uc + 63) & ~63;
        if (uc + tid < up) g_uniq[uc + tid] = g_uniq[0];
    }
}

// ---------------- kernel 1: gather unique K rows -> bf16 ----------------
__global__ void k_gather(const float* __restrict__ K) {
    int t = blockIdx.x * blockDim.x + threadIdx.x;
    int chunk = t & 7;
    int rest = t >> 3;
    int j = rest % LKS;
    int b = rest / LKS;
    if (b >= NB) return;
    if (j >= g_upad) return;
    int src = g_uniq[j];
    const float4* p = (const float4*)(K + ((size_t)b * LK + src) * DH + chunk * 8);
    float4 v0 = p[0], v1 = p[1];
    uint4 w = make_uint4(packbf(v0.x, v0.y), packbf(v0.z, v0.w),
                         packbf(v1.x, v1.y), packbf(v1.z, v1.w));
    *(uint4*)(g_KsampH + ((size_t)(b * LKS) + j) * DH + chunk * 8) = w;
}

// ---------------- kernel 2a/2b: Ksum, two-stage ----------------
__global__ void k_ksum1(const float* __restrict__ K, const int* __restrict__ idx) {
    int b = blockIdx.y;
    int sp = blockIdx.x;
    int d = threadIdx.x & 63;
    int g = threadIdx.x >> 6;
    float s = 0.f;
    for (int u = sp * 1000 + g; u < (sp + 1) * 1000; u += 4)
        s += K[((size_t)b * LK + idx[u]) * DH + d];
    __shared__ float red[4][64];
    red[g][d] = s;
    __syncthreads();
    if (g == 0)
        g_KsumP[(b * 8 + sp) * DH + d] = red[0][d] + red[1][d] + red[2][d] + red[3][d];
}
__global__ void k_ksum2() {
    int b = blockIdx.x;
    int d = threadIdx.x;
    float s = 0.f;
#pragma unroll
    for (int sp = 0; sp < 8; ++sp) s += g_KsumP[(b * 8 + sp) * DH + d];
    g_Ksum[b * DH + d] = s;
}

// ---------------- kernel 3: approx M via bf16 mma + ldmatrix ---------------
__global__ __launch_bounds__(256) void k_M_mma(const float* __restrict__ q) {
    __shared__ __nv_bfloat16 Bs[2][64 * 72];
    __shared__ float rowmaxS[4][64];
    __shared__ float ksumS[64];

    const int tid  = threadIdx.x;
    const int wid  = tid >> 5;
    const int lane = tid & 31;
    const int gid  = lane >> 2;
    const int tig  = lane & 3;
    const int b    = blockIdx.y;
    const int m0   = blockIdx.x * 64;
    const int mwarp = (wid & 1) * 32;
    const int nquad = wid >> 1;

    if (tid < 64) ksumS[tid] = g_Ksum[b * DH + tid];

    uint32_t a[2][4][4];
#pragma unroll
    for (int mb = 0; mb < 2; ++mb) {
        int r0 = m0 + mwarp + mb * 16 + gid;
        int r1 = r0 + 8;
        const float* q0 = q + ((size_t)(b * LQ) + r0) * DH;
        const float* q1 = q + ((size_t)(b * LQ) + r1) * DH;
#pragma unroll
        for (int kk = 0; kk < 4; ++kk) {
            int c = kk * 16 + 2 * tig;
            float2 x0 = *(const float2*)(q0 + c);
            float2 x1 = *(const float2*)(q1 + c);
            float2 x2 = *(const float2*)(q0 + c + 8);
            float2 x3 = *(const float2*)(q1 + c + 8);
            a[mb][kk][0] = packbf(x0.x, x0.y);
            a[mb][kk][1] = packbf(x1.x, x1.y);
            a[mb][kk][2] = packbf(x2.x, x2.y);
            a[mb][kk][3] = packbf(x3.x, x3.y);
        }
    }

    const int niter = g_upad >> 6;
    const int prow = tid >> 2, pseg = tid & 3;
    uint32_t sBase = (uint32_t)__cvta_generic_to_shared(&Bs[0][0]);

    {
        const __nv_bfloat16* src = g_KsampH + ((size_t)(b * LKS) + prow) * DH + pseg * 16;
        uint32_t dst = sBase + prow * 144 + pseg * 32;
        cp16(dst, src);
        cp16(dst + 16, src + 8);
    }
    asm volatile("cp.async.commit_group;\n");

    float rmax[2][2];
    rmax[0][0] = rmax[0][1] = rmax[1][0] = rmax[1][1] = -INFINITY;

    for (int t = 0; t < niter; ++t) {
        asm volatile("cp.async.wait_group 0;\n");
        __syncthreads();
        if (t + 1 < niter) {
            const __nv_bfloat16* src =
                g_KsampH + ((size_t)(b * LKS) + (t + 1) * 64 + prow) * DH + pseg * 16;
            uint32_t dst = sBase + ((t + 1) & 1) * 9216 + prow * 144 + pseg * 32;
            cp16(dst, src);
            cp16(dst + 16, src + 8);
        }
        asm volatile("cp.async.commit_group;\n");

        uint32_t bufBase = sBase + (t & 1) * 9216;
#pragma unroll
        for (int nc = 0; nc < 2; ++nc) {
            int nb = nquad * 16 + nc * 8;
            int row = nb + (lane & 7);
            uint32_t addr0 = bufBase + (uint32_t)(row * 144 + (lane >> 3) * 16);
            uint32_t bk[4], bk2[4];
            ldsm_x4(bk,  addr0);
            ldsm_x4(bk2, addr0 + 64);
            float acc0[4] = {0.f, 0.f, 0.f, 0.f};
            float acc1[4] = {0.f, 0.f, 0.f, 0.f};
            mma_bf16(acc0, a[0][0], bk[0],  bk[1]);
            mma_bf16(acc1, a[1][0], bk[0],  bk[1]);
            mma_bf16(acc0, a[0][1], bk[2],  bk[3]);
            mma_bf16(acc1, a[1][1], bk[2],  bk[3]);
            mma_bf16(acc0, a[0][2], bk2[0], bk2[1]);
            mma_bf16(acc1, a[1][2], bk2[0], bk2[1]);
            mma_bf16(acc0, a[0][3], bk2[2], bk2[3]);
            mma_bf16(acc1, a[1][3], bk2[2], bk2[3]);
            rmax[0][0] = fmaxf(rmax[0][0], fmaxf(acc0[0], acc0[1]));
            rmax[0][1] = fmaxf(rmax[0][1], fmaxf(acc0[2], acc0[3]));
            rmax[1][0] = fmaxf(rmax[1][0], fmaxf(acc1[0], acc1[1]));
            rmax[1][1] = fmaxf(rmax[1][1], fmaxf(acc1[2], acc1[3]));
        }
    }

#pragma unroll
    for (int mb = 0; mb < 2; ++mb)
#pragma unroll
        for (int h = 0; h < 2; ++h) {
            rmax[mb][h] = fmaxf(rmax[mb][h], __shfl_xor_sync(0xffffffffu, rmax[mb][h], 1));
            rmax[mb][h] = fmaxf(rmax[mb][h], __shfl_xor_sync(0xffffffffu, rmax[mb][h], 2));
        }
    if (tig == 0) {
        rowmaxS[nquad][mwarp + gid]      = rmax[0][0];
        rowmaxS[nquad][mwarp + gid + 8]  = rmax[0][1];
        rowmaxS[nquad][mwarp + 16 + gid] = rmax[1][0];
        rowmaxS[nquad][mwarp + 24 + gid] = rmax[1][1];
    }
    __syncthreads();

    if (tid < 64) {
        int m = m0 + tid;
        float mx = fmaxf(fmaxf(rowmaxS[0][tid], rowmaxS[1][tid]),
                         fmaxf(rowmaxS[2][tid], rowmaxS[3][tid]));
        const float* qp = q + ((size_t)(b * LQ) + m) * DH;
        float d0 = 0.f, d1 = 0.f, d2 = 0.f, d3 = 0.f;
#pragma unroll
        for (int d = 0; d < 64; d += 4) {
            d0 += qp[d]     * ksumS[d];
            d1 += qp[d + 1] * ksumS[d + 1];
            d2 += qp[d + 2] * ksumS[d + 2];
            d3 += qp[d + 3] * ksumS[d + 3];
        }
        g_M[b * LQ + m] = mx - ((d0 + d1) + (d2 + d3)) * (1.0f / (float)LKS);
    }
}

// ---------------- kernel 4: histogram threshold + candidate collect --------
__global__ __launch_bounds__(512) void k_thresh() {
    const int b = blockIdx.x;
    const int tid = threadIdx.x;
    __shared__ float sv[LQ];
    __shared__ int hist[512];
    __shared__ float wmn[16], wmx[16];
    __shared__ float s_mn, s_range, s_thresh;
    __shared__ int s_cnt;

    float mn = INFINITY, mx = -INFINITY;
    for (int j = tid; j < LQ; j += 512) {
        float v = g_M[b * LQ + j];
        sv[j] = v;
        mn = fminf(mn, v);
        mx = fmaxf(mx, v);
    }
#pragma unroll
    for (int off = 16; off > 0; off >>= 1) {
        mn = fminf(mn, __shfl_xor_sync(0xffffffffu, mn, off));
        mx = fmaxf(mx, __shfl_xor_sync(0xffffffffu, mx, off));
    }
    if ((tid & 31) == 0) { wmn[tid >> 5] = mn; wmx[tid >> 5] = mx; }
    if (tid < 512) hist[tid] = 0;
    if (tid == 0) s_cnt = 0;
    __syncthreads();
    if (tid == 0) {
        float a = INFINITY, z = -INFINITY;
        for (int g = 0; g < 16; ++g) { a = fminf(a, wmn[g]); z = fmaxf(z, wmx[g]); }
        s_mn = a;
        s_range = z - a + 1e-6f;
    }
    __syncthreads();
    const float scale = 511.0f / s_range;
    for (int j = tid; j < LQ; j += 512) {
        int bin = (int)((sv[j] - s_mn) * scale);
        bin = max(0, min(511, bin));
        atomicAdd(&hist[bin], 1);
    }
    __syncthreads();
    if (tid == 0) {
        int cum = 0, bsel = 511;
        for (int i = 0; i < 512; ++i) {
            cum += hist[i];
            if (cum >= NU) { bsel = i; break; }
        }
        s_thresh = s_mn + (float)(bsel + 1) * (s_range / 511.0f) + MARGIN;
    }
    __syncthreads();
    const float th = s_thresh;
    for (int j = tid; j < LQ; j += 512) {
        if (sv[j] <= th) {
            int p = atomicAdd(&s_cnt, 1);
            if (p < CANDMAX) g_cand[b * CANDMAX + p] = j;
        }
    }
    __syncthreads();
    if (tid == 0) g_ccount[b] = min(s_cnt, CANDMAX);
}

// ---------------- kernel 5: exact fp32 max (split-K over unique keys) ------
__global__ __launch_bounds__(256) void k_M_exact(const float* __restrict__ q,
                                                 const float* __restrict__ K) {
    extern __shared__ float sh[];
    float* Kc = sh;
    float* Qc = sh + 250 * 68;

    const int b = blockIdx.y;
    const int sp = blockIdx.x;
    const int tid = threadIdx.x;
    const int wid = tid >> 5;
    const int lane = tid & 31;

    const int uc = g_ucount;
    const int j0 = (sp * uc) / NSPLIT;
    const int j1 = ((sp + 1) * uc) / NSPLIT;
    const int nr = j1 - j0;

    for (int i = tid; i < nr * 16; i += 256) {
        int r = i >> 4, d4 = i & 15;
        int src = g_uniq[j0 + r];
        *(float4*)&Kc[r * 68 + 4 * d4] =
            *(const float4*)(K + ((size_t)b * LK + src) * DH + 4 * d4);
    }
    const int cnt = g_ccount[b];

    for (int cg = 0; cg < cnt; cg += 128) {
        int ncg = min(128, cnt - cg);
        __syncthreads();
        for (int i = tid; i < ncg * 16; i += 256) {
            int c = i >> 4, d4 = i & 15;
            int qi = g_cand[b * CANDMAX + cg + c];
            *(float4*)&Qc[c * 68 + 4 * d4] =
                *(const float4*)(q + ((size_t)(b * LQ) + qi) * DH + 4 * d4);
        }
        __syncthreads();
        for (int c = wid; c < ncg; c += 8) {
            const float* qr = &Qc[c * 68];
            float mx = -INFINITY;
            for (int r = lane; r < nr; r += 32) {
                const float* kr = &Kc[r * 68];
                float a0 = 0.f, a1 = 0.f, a2 = 0.f, a3 = 0.f;
#pragma unroll
                for (int d4 = 0; d4 < 16; ++d4) {
                    float4 kv = *(const float4*)&kr[4 * d4];
                    float4 qv = *(const float4*)&qr[4 * d4];
                    a0 += qv.x * kv.x;
                    a1 += qv.y * kv.y;
                    a2 += qv.z * kv.z;
                    a3 += qv.w * kv.w;
                }
                mx = fmaxf(mx, (a0 + a1) + (a2 + a3));
            }
#pragma unroll
            for (int off = 16; off > 0; off >>= 1)
                mx = fmaxf(mx, __shfl_xor_sync(0xffffffffu, mx, off));
            if (lane == 0)
                g_candP[((size_t)(b * CANDMAX) + cg + c) * NSPLIT + sp] = mx;
        }
    }
}

// ---------------- kernel 6: finalize exact M + top-45 selection ------------
__global__ __launch_bounds__(256) void k_select(const float* __restrict__ q) {
    const int b = blockIdx.x;
    const int tid = threadIdx.x;
    __shared__ float cv[CANDMAX];
    __shared__ int   ci[CANDMAX];
    const int cnt = g_ccount[b];

    for (int c = tid; c < CANDMAX; c += 256) {
        if (c < cnt) {
            float mx = -INFINITY;
#pragma unroll
            for (int s = 0; s < NSPLIT; ++s)
                mx = fmaxf(mx, g_candP[((size_t)(b * CANDMAX) + c) * NSPLIT + s]);
            int qi = g_cand[b * CANDMAX + c];
            const float* qp = q + ((size_t)(b * LQ) + qi) * DH;
            float dot = 0.f;
            for (int d = 0; d < 64; ++d) dot += qp[d] * g_Ksum[b * DH + d];
            cv[c] = mx - dot * (1.0f / (float)LKS);
            ci[c] = qi;
        } else {
            cv[c] = INFINITY;
            ci[c] = 1 << 30;
        }
    }
    __syncthreads();

    if (tid < 32) {
        for (int it = 0; it < NU; ++it) {
            float best = INFINITY; int bidx = 1 << 30; int bslot = 0;
            for (int j = tid; j < CANDMAX; j += 32) {
                float v = cv[j]; int qi2 = ci[j];
                if (v < best || (v == best && qi2 < bidx)) { best = v; bidx = qi2; bslot = j; }
            }
#pragma unroll
            for (int off = 16; off > 0; off >>= 1) {
                float v2 = __shfl_xor_sync(0xffffffffu, best, off);
                int   i2 = __shfl_xor_sync(0xffffffffu, bidx, off);
                int   s2 = __shfl_xor_sync(0xffffffffu, bslot, off);
                if (v2 < best || (v2 == best && i2 < bidx)) { best = v2; bidx = i2; bslot = s2; }
            }
            if (tid == 0) { g_top[b * NUP + it] = bidx; cv[bslot] = INFINITY; }
            __syncwarp();
        }
        if (tid < NUP - NU) g_top[b * NUP + NU + tid] = 0;
    }
}

// ---------------- kernel 7: bf16x2-Karatsuba mma attention ----------
// smem bf16: Qh/Ql[48*72] Kh/Kl[64*72] Vth/Vtl[64*72]  union{SP f32[48*68] | Ph/Pl[48*72]}  fS[48]
__global__ __launch_bounds__(256, 3) void k_attn(const float* __restrict__ q,
                                                 const float* __restrict__ K,
                                                 const float* __restrict__ V,
                                                 float* __restrict__ out_s) {
    extern __shared__ char smc[];
    __nv_bfloat16* Qh  = (__nv_bfloat16*)smc;            // 48*72
    __nv_bfloat16* Ql  = Qh + 48 * 72;
    __nv_bfloat16* Kh  = Ql + 48 * 72;                   // 64*72
    __nv_bfloat16* Kl  = Kh + 64 * 72;
    __nv_bfloat16* Vth = Kl + 64 * 72;                   // 64*72 rows=d
    __nv_bfloat16* Vtl = Vth + 64 * 72;
    char* Ub = (char*)(Vtl + 64 * 72);                   // union, 13824 B
    float* SP = (float*)Ub;                              // [48][68] f32
    __nv_bfloat16* Ph = (__nv_bfloat16*)Ub;              // [48][72]
    __nv_bfloat16* Pl = Ph + 48 * 72;
    float* fS = (float*)(Ub + 13824);                    // [48]

    const uint32_t sQh = (uint32_t)__cvta_generic_to_shared(Qh);
    const uint32_t sQl = (uint32_t)__cvta_generic_to_shared(Ql);
    const uint32_t sKh = (uint32_t)__cvta_generic_to_shared(Kh);
    const uint32_t sKl = (uint32_t)__cvta_generic_to_shared(Kl);
    const uint32_t sVh = (uint32_t)__cvta_generic_to_shared(Vth);
    const uint32_t sVl = (uint32_t)__cvta_generic_to_shared(Vtl);
    const uint32_t sPh = (uint32_t)__cvta_generic_to_shared(Ph);
    const uint32_t sPl = (uint32_t)__cvta_generic_to_shared(Pl);

    const int tid = threadIdx.x;
    const int ty = tid >> 5;          // warp 0..7
    const int tx = tid & 31;
    const int gid = tx >> 2;
    const int tig = tx & 3;
    const int b = blockIdx.y;
    const int chunk = blockIdx.x;
    const int kchunk0 = chunk * CK;

    // ---- load 48 selected q rows, split bf16 hi/lo
#pragma unroll
    for (int i = 0; i < 3; ++i) {
        int fidx = tid + 256 * i;        // 0..767
        int u    = fidx >> 4;
        int d4   = fidx & 15;
        float4 v = make_float4(0.f, 0.f, 0.f, 0.f);
        if (u < NU) {
            int qi = g_top[b * NUP + u];
            v = *(const float4*)(q + ((size_t)(b * LQ + qi)) * DH + 4 * d4);
        }
        uint32_t h0, l0, h1, l1;
        bfsplit2(v.x, v.y, h0, l0);
        bfsplit2(v.z, v.w, h1, l1);
        *(uint32_t*)(Qh + u * 72 + 4 * d4)     = h0;
        *(uint32_t*)(Qh + u * 72 + 4 * d4 + 2) = h1;
        *(uint32_t*)(Ql + u * 72 + 4 * d4)     = l0;
        *(uint32_t*)(Ql + u * 72 + 4 * d4 + 2) = l1;
    }

    float mrun[6], lrun[6];
#pragma unroll
    for (int i = 0; i < 6; ++i) { mrun[i] = -INFINITY; lrun[i] = 0.f; }
    float oc[3][4];
#pragma unroll
    for (int mt = 0; mt < 3; ++mt)
#pragma unroll
        for (int i = 0; i < 4; ++i) oc[mt][i] = 0.f;

    for (int kt = 0; kt < CK / KT; ++kt) {
        const int kg0 = kchunk0 + kt * KT;
        __syncthreads();
        // ---- load K tile (rows=key) and V tile transposed (rows=d), split hi/lo
#pragma unroll
        for (int i = 0; i < 4; ++i) {
            int fidx = tid + 256 * i;     // 0..1023
            int k    = fidx >> 4;
            int d4   = fidx & 15;
            float4 kv = *(const float4*)(K + ((size_t)(b * LK + kg0 + k)) * DH + 4 * d4);
            uint32_t h0, l0, h1, l1;
            bfsplit2(kv.x, kv.y, h0, l0);
            bfsplit2(kv.z, kv.w, h1, l1);
            *(uint32_t*)(Kh + k * 72 + 4 * d4)     = h0;
            *(uint32_t*)(Kh + k * 72 + 4 * d4 + 2) = h1;
            *(uint32_t*)(Kl + k * 72 + 4 * d4)     = l0;
            *(uint32_t*)(Kl + k * 72 + 4 * d4 + 2) = l1;
            float4 vv = *(const float4*)(V + ((size_t)(b * LK + kg0 + k)) * DH + 4 * d4);
#pragma unroll
            for (int j = 0; j < 4; ++j) {
                float x = (j == 0) ? vv.x : (j == 1) ? vv.y : (j == 2) ? vv.z : vv.w;
                __nv_bfloat16 hx = __float2bfloat16_rn(x);
                __nv_bfloat16 lx = __float2bfloat16_rn(x - __bfloat162float(hx));
                Vth[(4 * d4 + j) * 72 + k] = hx;
                Vtl[(4 * d4 + j) * 72 + k] = lx;
            }
        }
        __syncthreads();

        // ---- S = Q K^T (3-mma Karatsuba). warp ty owns keys 8ty..8ty+7
        {
            uint32_t bh[8], bl[8];
            uint32_t kaddr = sKh + (uint32_t)((8 * ty + (tx & 7)) * 144 + (tx >> 3) * 16);
            ldsm_x4(bh,     kaddr);
            ldsm_x4(bh + 4, kaddr + 64);
            kaddr = sKl + (uint32_t)((8 * ty + (tx & 7)) * 144 + (tx >> 3) * 16);
            ldsm_x4(bl,     kaddr);
            ldsm_x4(bl + 4, kaddr + 64);

#pragma unroll
            for (int mt = 0; mt < 3; ++mt) {
                float accS[4] = {0.f, 0.f, 0.f, 0.f};
                uint32_t arow = (uint32_t)((mt * 16 + (tx & 15)) * 144 + (tx >> 4) * 16);
#pragma unroll
                for (int ks = 0; ks < 4; ++ks) {
                    uint32_t ah[4], al[4];
                    ldsm_x4(ah, sQh + arow + ks * 32);
                    ldsm_x4(al, sQl + arow + ks * 32);
                    mma_bf16(accS, ah, bh[2 * ks], bh[2 * ks + 1]);
                    mma_bf16(accS, ah, bl[2 * ks], bl[2 * ks + 1]);
                    mma_bf16(accS, al, bh[2 * ks], bh[2 * ks + 1]);
                }
                int r0 = mt * 16 + gid;
                *(float2*)&SP[r0 * 68 + 8 * ty + 2 * tig] =
                    make_float2(accS[0] * 0.125f, accS[1] * 0.125f);
                *(float2*)&SP[(r0 + 8) * 68 + 8 * ty + 2 * tig] =
                    make_float2(accS[2] * 0.125f, accS[3] * 0.125f);
            }
        }
        __syncthreads();

        // ---- phase A: warp-private online softmax over rows 6ty..6ty+5
        float pr[6][2], fnew[6];
#pragma unroll
        for (int i = 0; i < 6; ++i) {
            int u = 6 * ty + i;
            float2 sv = *(const float2*)&SP[u * 68 + 2 * tx];
            float mx = fmaxf(sv.x, sv.y);
#pragma unroll
            for (int off = 16; off > 0; off >>= 1)
                mx = fmaxf(mx, __shfl_xor_sync(0xffffffffu, mx, off));
            float mn = fmaxf(mrun[i], mx);
            float f  = __expf(mrun[i] - mn);
            float p0 = __expf(sv.x - mn);
            float p1 = __expf(sv.y - mn);
            float ps = p0 + p1;
#pragma unroll
            for (int off = 16; off > 0; off >>= 1)
                ps += __shfl_xor_sync(0xffffffffu, ps, off);
            lrun[i] = lrun[i] * f + ps;
            mrun[i] = mn;
            fnew[i] = f;
            pr[i][0] = p0; pr[i][1] = p1;
            if (u < NU)
                *(float2*)(out_s + ((size_t)(b * NU + u)) * LK + kg0 + 2 * tx) = sv;
        }
        __syncthreads();

        // ---- phase B: write split P + rescale factors
#pragma unroll
        for (int i = 0; i < 6; ++i) {
            int u = 6 * ty + i;
            uint32_t h, l;
            bfsplit2(pr[i][0], pr[i][1], h, l);
            *(uint32_t*)(Ph + u * 72 + 2 * tx) = h;
            *(uint32_t*)(Pl + u * 72 + 2 * tx) = l;
            if (tx == 0) fS[u] = fnew[i];
        }
        __syncthreads();

        // ---- phase C: O += P V (3-mma Karatsuba). warp ty owns d-cols 8ty..+7
        {
            uint32_t bh[8], bl[8];
            uint32_t vaddr = sVh + (uint32_t)((8 * ty + (tx & 7)) * 144 + (tx >> 3) * 16);
            ldsm_x4(bh,     vaddr);
            ldsm_x4(bh + 4, vaddr + 64);
            vaddr = sVl + (uint32_t)((8 * ty + (tx & 7)) * 144 + (tx >> 3) * 16);
            ldsm_x4(bl,     vaddr);
            ldsm_x4(bl + 4, vaddr + 64);

#pragma unroll
            for (int mt = 0; mt < 3; ++mt) {
                float f0 = fS[mt * 16 + gid];
                float f1 = fS[mt * 16 + gid + 8];
                oc[mt][0] *= f0; oc[mt][1] *= f0;
                oc[mt][2] *= f1; oc[mt][3] *= f1;
                uint32_t arow = (uint32_t)((mt * 16 + (tx & 15)) * 144 + (tx >> 4) * 16);
#pragma unroll
                for (int ks = 0; ks < 4; ++ks) {
                    uint32_t ph[4], pl2[4];
                    ldsm_x4(ph,  sPh + arow + ks * 32);
                    ldsm_x4(pl2, sPl + arow + ks * 32);
                    mma_bf16(oc[mt], ph,  bh[2 * ks], bh[2 * ks + 1]);
                    mma_bf16(oc[mt], ph,  bl[2 * ks], bl[2 * ks + 1]);
                    mma_bf16(oc[mt], pl2, bh[2 * ks], bh[2 * ks + 1]);
                }
            }
        }
    }

    // ---- write partials
    if (tx == 0) {
#pragma unroll
        for (int i = 0; i < 6; ++i) {
            int u = 6 * ty + i;
            g_pm[(b * NCHUNK + chunk) * NUP + u] = mrun[i];
            g_pl[(b * NCHUNK + chunk) * NUP + u] = lrun[i];
        }
    }
#pragma unroll
    for (int mt = 0; mt < 3; ++mt) {
        int r0 = mt * 16 + gid;
        *(float2*)&g_pacc[((size_t)(b * NCHUNK + chunk) * NUP + r0) * DH + 8 * ty + 2 * tig] =
            make_float2(oc[mt][0], oc[mt][1]);
        *(float2*)&g_pacc[((size_t)(b * NCHUNK + chunk) * NUP + r0 + 8) * DH + 8 * ty + 2 * tig] =
            make_float2(oc[mt][2], oc[mt][3]);
    }
}

// ---------------- kernel 8: combine split-softmax partials ----------------
__global__ void k_combine(float* __restrict__ out_o) {
    int u = blockIdx.x;
    int b = blockIdx.y;
    int d = threadIdx.x;
    float gm = -INFINITY;
    for (int c = 0; c < NCHUNK; ++c)
        gm = fmaxf(gm, g_pm[(b * NCHUNK + c) * NUP + u]);
    float L = 0.f, a = 0.f;
    for (int c = 0; c < NCHUNK; ++c) {
        float w = __expf(g_pm[(b * NCHUNK + c) * NUP + u] - gm);
        L += g_pl[(b * NCHUNK + c) * NUP + u] * w;
        a += g_pacc[((size_t)(b * NCHUNK + c) * NUP + u) * DH + d] * w;
    }
    out_o[(b * NU + u) * DH + d] = a / L;
}

// ---------------- launch ----------------
extern "C" void kernel_launch(void* const* d_in, const int* in_sizes, int n_in,
                              void* d_out, int out_size) {
    const float* q  = (const float*)d_in[0];
    const float* K  = (const float*)d_in[1];
    const float* V  = (const float*)d_in[2];
    const int* idx  = (const int*)d_in[3];
    float* out_o = (float*)d_out;                  // attn_output [8,45,64]
    float* out_s = out_o + NB * NU * DH;           // attn_scores [8,45,32768]

    (void)in_sizes; (void)n_in; (void)out_size;

    const int smem_attn  = 48 * 72 * 2 * 2 + 64 * 72 * 2 * 2 * 2 + 13824 + 192;  // 64704
    const int smem_exact = (250 * 68 + 128 * 68) * 4;                            // 102816
    cudaFuncSetAttribute(k_attn,    cudaFuncAttributeMaxDynamicSharedMemorySize, smem_attn);
    cudaFuncSetAttribute(k_M_exact, cudaFuncAttributeMaxDynamicSharedMemorySize, smem_exact);

    k_dedup<<<1, 1024>>>(idx);
    k_gather<<<(NB * LKS * 8 + 255) / 256, 256>>>(K);
    k_ksum1<<<dim3(8, NB), 256>>>(K, idx);
    k_ksum2<<<NB, 64>>>();
    k_M_mma<<<dim3(LQ / 64, NB), 256>>>(q);
    k_thresh<<<NB, 512>>>();
    k_M_exact<<<dim3(NSPLIT, NB), 256, smem_exact>>>(q, K);
    k_select<<<NB, 256>>>(q);
    k_attn<<<dim3(NCHUNK, NB), 256, smem_attn>>>(q, K, V, out_s);
    k_combine<<<dim3(NU, NB), 64>>>(out_o);
}

// round 11
// speedup vs baseline: 3.8226x; 1.0773x over previous
#include <cuda_runtime.h>
#include <cuda_bf16.h>
#include <math.h>
#include <stdint.h>

#define NB 8
#define LQ 4096
#define LK 32768
#define DH 64
#define LKS 8000
#define NU 45
#define NUP 48
#define NCHUNK 64
#define CK 512
#define KT 64
#define CANDMAX 1024
#define NSPLIT 32
#define MARGIN 1.0f

// ---------------- device scratch ----------------
__device__ __nv_bfloat16 g_KsampH[NB * LKS * DH];
__device__ int   g_uniq[LKS];
__device__ int   g_ucount;
__device__ int   g_upad;
__device__ float g_KsumP[NB * 8 * DH];
__device__ float g_M[NB * LQ];
__device__ int   g_top[NB * NUP];
__device__ int   g_cand[NB * CANDMAX];
__device__ float g_candP[NB * CANDMAX * NSPLIT];
__device__ int   g_ccount[NB];
__device__ float g_pm[NB * NCHUNK * NUP];
__device__ float g_pl[NB * NCHUNK * NUP];
__device__ float g_pacc[NB * NCHUNK * NUP * DH];

// ---------------- helpers ----------------
__device__ __forceinline__ void mma_bf16(float c[4], const uint32_t a[4],
                                         uint32_t b0, uint32_t b1) {
    asm volatile(
        "mma.sync.aligned.m16n8k16.row.col.f32.bf16.bf16.f32 "
        "{%0,%1,%2,%3}, {%4,%5,%6,%7}, {%8,%9}, {%0,%1,%2,%3};"
        : "+f"(c[0]), "+f"(c[1]), "+f"(c[2]), "+f"(c[3])
        : "r"(a[0]), "r"(a[1]), "r"(a[2]), "r"(a[3]), "r"(b0), "r"(b1));
}
__device__ __forceinline__ uint32_t packbf(float x, float y) {
    __nv_bfloat162 h = __floats2bfloat162_rn(x, y);
    return *(uint32_t*)&h;
}
__device__ __forceinline__ void bfsplit2(float x, float y, uint32_t& h, uint32_t& l) {
    __nv_bfloat16 hx = __float2bfloat16_rn(x), hy = __float2bfloat16_rn(y);
    float rx = x - __bfloat162float(hx);
    float ry = y - __bfloat162float(hy);
    __nv_bfloat16 lx = __float2bfloat16_rn(rx), ly = __float2bfloat16_rn(ry);
    h = ((uint32_t)(*(uint16_t*)&hy) << 16) | (uint32_t)(*(uint16_t*)&hx);
    l = ((uint32_t)(*(uint16_t*)&ly) << 16) | (uint32_t)(*(uint16_t*)&lx);
}
__device__ __forceinline__ void cp16(uint32_t dst, const void* src) {
    asm volatile("cp.async.ca.shared.global [%0], [%1], 16;\n" :: "r"(dst), "l"(src));
}
__device__ __forceinline__ void ldsm_x4(uint32_t r[4], uint32_t addr) {
    asm volatile("ldmatrix.sync.aligned.m8n8.x4.shared.b16 {%0,%1,%2,%3}, [%4];"
                 : "=r"(r[0]), "=r"(r[1]), "=r"(r[2]), "=r"(r[3]) : "r"(addr));
}
__device__ __forceinline__ void ldsm_x4_t(uint32_t r[4], uint32_t addr) {
    asm volatile("ldmatrix.sync.aligned.m8n8.x4.trans.shared.b16 {%0,%1,%2,%3}, [%4];"
                 : "=r"(r[0]), "=r"(r[1]), "=r"(r[2]), "=r"(r[3]) : "r"(addr));
}

// ---------------- kernel 0: dedupe sampled indices ----------------
__global__ void k_dedup(const int* __restrict__ idx) {
    __shared__ unsigned bm[250];
    __shared__ int wo[251];
    int tid = threadIdx.x;
    for (int i = tid; i < 250; i += 1024) bm[i] = 0u;
    __syncthreads();
    for (int i = tid; i < LKS; i += 1024) {
        int v = idx[i];
        atomicOr(&bm[v >> 5], 1u << (v & 31));
    }
    __syncthreads();
    if (tid == 0) {
        int acc = 0;
        for (int w = 0; w < 250; ++w) { wo[w] = acc; acc += __popc(bm[w]); }
        wo[250] = acc;
        g_ucount = acc;
        g_upad = (acc + 63) & ~63;
    }
    __syncthreads();
    for (int w = tid; w < 250; w += 1024) {
        unsigned m = bm[w];
        int o = wo[w];
        while (m) {
            int b = __ffs(m) - 1;
            g_uniq[o++] = w * 32 + b;
            m &= m - 1;
        }
    }
    __syncthreads();
    if (tid < 64) {
        int uc = wo[250];
        int up = (uc + 63) & ~63;
        if (uc + tid < up) g_uniq[uc + tid] = g_uniq[0];
    }
}

// ---------------- kernel 1: gather unique K rows -> bf16 ----------------
__global__ void k_gather(const float* __restrict__ K) {
    int t = blockIdx.x * blockDim.x + threadIdx.x;
    int chunk = t & 7;
    int rest = t >> 3;
    int j = rest % LKS;
    int b = rest / LKS;
    if (b >= NB) return;
    if (j >= g_upad) return;
    int src = g_uniq[j];
    const float4* p = (const float4*)(K + ((size_t)b * LK + src) * DH + chunk * 8);
    float4 v0 = p[0], v1 = p[1];
    uint4 w = make_uint4(packbf(v0.x, v0.y), packbf(v0.z, v0.w),
                         packbf(v1.x, v1.y), packbf(v1.z, v1.w));
    *(uint4*)(g_KsampH + ((size_t)(b * LKS) + j) * DH + chunk * 8) = w;
}

// ---------------- kernel 2: Ksum partials over full multiset ----------------
__global__ void k_ksum1(const float* __restrict__ K, const int* __restrict__ idx) {
    int b = blockIdx.y;
    int sp = blockIdx.x;
    int d = threadIdx.x & 63;
    int g = threadIdx.x >> 6;
    float s = 0.f;
    for (int u = sp * 1000 + g; u < (sp + 1) * 1000; u += 4)
        s += K[((size_t)b * LK + idx[u]) * DH + d];
    __shared__ float red[4][64];
    red[g][d] = s;
    __syncthreads();
    if (g == 0)
        g_KsumP[(b * 8 + sp) * DH + d] = red[0][d] + red[1][d] + red[2][d] + red[3][d];
}

// ---------------- kernel 3: approx M via bf16 mma + ldmatrix ---------------
__global__ __launch_bounds__(256) void k_M_mma(const float* __restrict__ q) {
    __shared__ __nv_bfloat16 Bs[2][64 * 72];
    __shared__ float rowmaxS[4][64];
    __shared__ float ksumS[64];

    const int tid  = threadIdx.x;
    const int wid  = tid >> 5;
    const int lane = tid & 31;
    const int gid  = lane >> 2;
    const int tig  = lane & 3;
    const int b    = blockIdx.y;
    const int m0   = blockIdx.x * 64;
    const int mwarp = (wid & 1) * 32;
    const int nquad = wid >> 1;

    if (tid < 64) {
        float s = 0.f;
#pragma unroll
        for (int sp = 0; sp < 8; ++sp) s += g_KsumP[(b * 8 + sp) * DH + tid];
        ksumS[tid] = s;
    }

    uint32_t a[2][4][4];
#pragma unroll
    for (int mb = 0; mb < 2; ++mb) {
        int r0 = m0 + mwarp + mb * 16 + gid;
        int r1 = r0 + 8;
        const float* q0 = q + ((size_t)(b * LQ) + r0) * DH;
        const float* q1 = q + ((size_t)(b * LQ) + r1) * DH;
#pragma unroll
        for (int kk = 0; kk < 4; ++kk) {
            int c = kk * 16 + 2 * tig;
            float2 x0 = *(const float2*)(q0 + c);
            float2 x1 = *(const float2*)(q1 + c);
            float2 x2 = *(const float2*)(q0 + c + 8);
            float2 x3 = *(const float2*)(q1 + c + 8);
            a[mb][kk][0] = packbf(x0.x, x0.y);
            a[mb][kk][1] = packbf(x1.x, x1.y);
            a[mb][kk][2] = packbf(x2.x, x2.y);
            a[mb][kk][3] = packbf(x3.x, x3.y);
        }
    }

    const int niter = g_upad >> 6;
    const int prow = tid >> 2, pseg = tid & 3;
    uint32_t sBase = (uint32_t)__cvta_generic_to_shared(&Bs[0][0]);

    {
        const __nv_bfloat16* src = g_KsampH + ((size_t)(b * LKS) + prow) * DH + pseg * 16;
        uint32_t dst = sBase + prow * 144 + pseg * 32;
        cp16(dst, src);
        cp16(dst + 16, src + 8);
    }
    asm volatile("cp.async.commit_group;\n");

    float rmax[2][2];
    rmax[0][0] = rmax[0][1] = rmax[1][0] = rmax[1][1] = -INFINITY;

    for (int t = 0; t < niter; ++t) {
        asm volatile("cp.async.wait_group 0;\n");
        __syncthreads();
        if (t + 1 < niter) {
            const __nv_bfloat16* src =
                g_KsampH + ((size_t)(b * LKS) + (t + 1) * 64 + prow) * DH + pseg * 16;
            uint32_t dst = sBase + ((t + 1) & 1) * 9216 + prow * 144 + pseg * 32;
            cp16(dst, src);
            cp16(dst + 16, src + 8);
        }
        asm volatile("cp.async.commit_group;\n");

        uint32_t bufBase = sBase + (t & 1) * 9216;
#pragma unroll
        for (int nc = 0; nc < 2; ++nc) {
            int nb = nquad * 16 + nc * 8;
            int row = nb + (lane & 7);
            uint32_t addr0 = bufBase + (uint32_t)(row * 144 + (lane >> 3) * 16);
            uint32_t bk[4], bk2[4];
            ldsm_x4(bk,  addr0);
            ldsm_x4(bk2, addr0 + 64);
            float acc0[4] = {0.f, 0.f, 0.f, 0.f};
            float acc1[4] = {0.f, 0.f, 0.f, 0.f};
            mma_bf16(acc0, a[0][0], bk[0],  bk[1]);
            mma_bf16(acc1, a[1][0], bk[0],  bk[1]);
            mma_bf16(acc0, a[0][1], bk[2],  bk[3]);
            mma_bf16(acc1, a[1][1], bk[2],  bk[3]);
            mma_bf16(acc0, a[0][2], bk2[0], bk2[1]);
            mma_bf16(acc1, a[1][2], bk2[0], bk2[1]);
            mma_bf16(acc0, a[0][3], bk2[2], bk2[3]);
            mma_bf16(acc1, a[1][3], bk2[2], bk2[3]);
            rmax[0][0] = fmaxf(rmax[0][0], fmaxf(acc0[0], acc0[1]));
            rmax[0][1] = fmaxf(rmax[0][1], fmaxf(acc0[2], acc0[3]));
            rmax[1][0] = fmaxf(rmax[1][0], fmaxf(acc1[0], acc1[1]));
            rmax[1][1] = fmaxf(rmax[1][1], fmaxf(acc1[2], acc1[3]));
        }
    }

#pragma unroll
    for (int mb = 0; mb < 2; ++mb)
#pragma unroll
        for (int h = 0; h < 2; ++h) {
            rmax[mb][h] = fmaxf(rmax[mb][h], __shfl_xor_sync(0xffffffffu, rmax[mb][h], 1));
            rmax[mb][h] = fmaxf(rmax[mb][h], __shfl_xor_sync(0xffffffffu, rmax[mb][h], 2));
        }
    if (tig == 0) {
        rowmaxS[nquad][mwarp + gid]      = rmax[0][0];
        rowmaxS[nquad][mwarp + gid + 8]  = rmax[0][1];
        rowmaxS[nquad][mwarp + 16 + gid] = rmax[1][0];
        rowmaxS[nquad][mwarp + 24 + gid] = rmax[1][1];
    }
    __syncthreads();

    if (tid < 64) {
        int m = m0 + tid;
        float mx = fmaxf(fmaxf(rowmaxS[0][tid], rowmaxS[1][tid]),
                         fmaxf(rowmaxS[2][tid], rowmaxS[3][tid]));
        const float* qp = q + ((size_t)(b * LQ) + m) * DH;
        float d0 = 0.f, d1 = 0.f, d2 = 0.f, d3 = 0.f;
#pragma unroll
        for (int d = 0; d < 64; d += 4) {
            d0 += qp[d]     * ksumS[d];
            d1 += qp[d + 1] * ksumS[d + 1];
            d2 += qp[d + 2] * ksumS[d + 2];
            d3 += qp[d + 3] * ksumS[d + 3];
        }
        g_M[b * LQ + m] = mx - ((d0 + d1) + (d2 + d3)) * (1.0f / (float)LKS);
    }
}

// ---------------- kernel 4: histogram threshold + candidate collect --------
__global__ __launch_bounds__(512) void k_thresh() {
    const int b = blockIdx.x;
    const int tid = threadIdx.x;
    __shared__ float sv[LQ];
    __shared__ int hist[512];
    __shared__ float wmn[16], wmx[16];
    __shared__ float s_mn, s_range, s_thresh;
    __shared__ int s_cnt;

    float mn = INFINITY, mx = -INFINITY;
    for (int j = tid; j < LQ; j += 512) {
        float v = g_M[b * LQ + j];
        sv[j] = v;
        mn = fminf(mn, v);
        mx = fmaxf(mx, v);
    }
#pragma unroll
    for (int off = 16; off > 0; off >>= 1) {
        mn = fminf(mn, __shfl_xor_sync(0xffffffffu, mn, off));
        mx = fmaxf(mx, __shfl_xor_sync(0xffffffffu, mx, off));
    }
    if ((tid & 31) == 0) { wmn[tid >> 5] = mn; wmx[tid >> 5] = mx; }
    if (tid < 512) hist[tid] = 0;
    if (tid == 0) s_cnt = 0;
    __syncthreads();
    if (tid == 0) {
        float a = INFINITY, z = -INFINITY;
        for (int g = 0; g < 16; ++g) { a = fminf(a, wmn[g]); z = fmaxf(z, wmx[g]); }
        s_mn = a;
        s_range = z - a + 1e-6f;
    }
    __syncthreads();
    const float scale = 511.0f / s_range;
    for (int j = tid; j < LQ; j += 512) {
        int bin = (int)((sv[j] - s_mn) * scale);
        bin = max(0, min(511, bin));
        atomicAdd(&hist[bin], 1);
    }
    __syncthreads();
    if (tid == 0) {
        int cum = 0, bsel = 511;
        for (int i = 0; i < 512; ++i) {
            cum += hist[i];
            if (cum >= NU) { bsel = i; break; }
        }
        s_thresh = s_mn + (float)(bsel + 1) * (s_range / 511.0f) + MARGIN;
    }
    __syncthreads();
    const float th = s_thresh;
    for (int j = tid; j < LQ; j += 512) {
        if (sv[j] <= th) {
            int p = atomicAdd(&s_cnt, 1);
            if (p < CANDMAX) g_cand[b * CANDMAX + p] = j;
        }
    }
    __syncthreads();
    if (tid == 0) g_ccount[b] = min(s_cnt, CANDMAX);
}

// ---------------- kernel 5: exact fp32 max (split-K over unique keys) ------
__global__ __launch_bounds__(256) void k_M_exact(const float* __restrict__ q,
                                                 const float* __restrict__ K) {
    extern __shared__ float sh[];
    float* Kc = sh;
    float* Qc = sh + 250 * 68;

    const int b = blockIdx.y;
    const int sp = blockIdx.x;
    const int tid = threadIdx.x;
    const int wid = tid >> 5;
    const int lane = tid & 31;

    const int uc = g_ucount;
    const int j0 = (sp * uc) / NSPLIT;
    const int j1 = ((sp + 1) * uc) / NSPLIT;
    const int nr = j1 - j0;

    for (int i = tid; i < nr * 16; i += 256) {
        int r = i >> 4, d4 = i & 15;
        int src = g_uniq[j0 + r];
        *(float4*)&Kc[r * 68 + 4 * d4] =
            *(const float4*)(K + ((size_t)b * LK + src) * DH + 4 * d4);
    }
    const int cnt = g_ccount[b];

    for (int cg = 0; cg < cnt; cg += 128) {
        int ncg = min(128, cnt - cg);
        __syncthreads();
        for (int i = tid; i < ncg * 16; i += 256) {
            int c = i >> 4, d4 = i & 15;
            int qi = g_cand[b * CANDMAX + cg + c];
            *(float4*)&Qc[c * 68 + 4 * d4] =
                *(const float4*)(q + ((size_t)(b * LQ) + qi) * DH + 4 * d4);
        }
        __syncthreads();
        for (int c = wid; c < ncg; c += 8) {
            const float* qr = &Qc[c * 68];
            float mx = -INFINITY;
            for (int r = lane; r < nr; r += 32) {
                const float* kr = &Kc[r * 68];
                float a0 = 0.f, a1 = 0.f, a2 = 0.f, a3 = 0.f;
#pragma unroll
                for (int d4 = 0; d4 < 16; ++d4) {
                    float4 kv = *(const float4*)&kr[4 * d4];
                    float4 qv = *(const float4*)&qr[4 * d4];
                    a0 += qv.x * kv.x;
                    a1 += qv.y * kv.y;
                    a2 += qv.z * kv.z;
                    a3 += qv.w * kv.w;
                }
                mx = fmaxf(mx, (a0 + a1) + (a2 + a3));
            }
#pragma unroll
            for (int off = 16; off > 0; off >>= 1)
                mx = fmaxf(mx, __shfl_xor_sync(0xffffffffu, mx, off));
            if (lane == 0)
                g_candP[((size_t)(b * CANDMAX) + cg + c) * NSPLIT + sp] = mx;
        }
    }
}

// ---------------- kernel 6: finalize exact M + top-45 selection ------------
__global__ __launch_bounds__(256) void k_select(const float* __restrict__ q) {
    const int b = blockIdx.x;
    const int tid = threadIdx.x;
    __shared__ float cv[CANDMAX];
    __shared__ int   ci[CANDMAX];
    __shared__ float ksumS[64];
    const int cnt = g_ccount[b];

    if (tid < 64) {
        float s = 0.f;
#pragma unroll
        for (int sp = 0; sp < 8; ++sp) s += g_KsumP[(b * 8 + sp) * DH + tid];
        ksumS[tid] = s;
    }
    __syncthreads();

    for (int c = tid; c < CANDMAX; c += 256) {
        if (c < cnt) {
            float mx = -INFINITY;
#pragma unroll
            for (int s = 0; s < NSPLIT; ++s)
                mx = fmaxf(mx, g_candP[((size_t)(b * CANDMAX) + c) * NSPLIT + s]);
            int qi = g_cand[b * CANDMAX + c];
            const float* qp = q + ((size_t)(b * LQ) + qi) * DH;
            float dot = 0.f;
            for (int d = 0; d < 64; ++d) dot += qp[d] * ksumS[d];
            cv[c] = mx - dot * (1.0f / (float)LKS);
            ci[c] = qi;
        } else {
            cv[c] = INFINITY;
            ci[c] = 1 << 30;
        }
    }
    __syncthreads();

    if (tid < 32) {
        for (int it = 0; it < NU; ++it) {
            float best = INFINITY; int bidx = 1 << 30; int bslot = 0;
            for (int j = tid; j < CANDMAX; j += 32) {
                float v = cv[j]; int qi2 = ci[j];
                if (v < best || (v == best && qi2 < bidx)) { best = v; bidx = qi2; bslot = j; }
            }
#pragma unroll
            for (int off = 16; off > 0; off >>= 1) {
                float v2 = __shfl_xor_sync(0xffffffffu, best, off);
                int   i2 = __shfl_xor_sync(0xffffffffu, bidx, off);
                int   s2 = __shfl_xor_sync(0xffffffffu, bslot, off);
                if (v2 < best || (v2 == best && i2 < bidx)) { best = v2; bidx = i2; bslot = s2; }
            }
            if (tid == 0) { g_top[b * NUP + it] = bidx; cv[bslot] = INFINITY; }
            __syncwarp();
        }
        if (tid < NUP - NU) g_top[b * NUP + NU + tid] = 0;
    }
}

// ---------------- kernel 7: bf16x2-Karatsuba mma attention ----------
// smem bf16: Qh/Ql[48*72] Kh/Kl[64*72] Vh/Vl[64*72]  union{SP f32[48*68] | Ph/Pl[48*72]}  fS[48]
__global__ __launch_bounds__(256, 3) void k_attn(const float* __restrict__ q,
                                                 const float* __restrict__ K,
                                                 const float* __restrict__ V,
                                                 float* __restrict__ out_s) {
    extern __shared__ char smc[];
    __nv_bfloat16* Qh = (__nv_bfloat16*)smc;            // 48*72
    __nv_bfloat16* Ql = Qh + 48 * 72;
    __nv_bfloat16* Kh = Ql + 48 * 72;                   // 64*72
    __nv_bfloat16* Kl = Kh + 64 * 72;
    __nv_bfloat16* Vh = Kl + 64 * 72;                   // 64*72 rows=key
    __nv_bfloat16* Vl = Vh + 64 * 72;
    char* Ub = (char*)(Vl + 64 * 72);                   // union, 13824 B
    float* SP = (float*)Ub;                             // [48][68] f32
    __nv_bfloat16* Ph = (__nv_bfloat16*)Ub;             // [48][72]
    __nv_bfloat16* Pl = Ph + 48 * 72;
    float* fS = (float*)(Ub + 13824);                   // [48]

    const uint32_t sQh = (uint32_t)__cvta_generic_to_shared(Qh);
    const uint32_t sQl = (uint32_t)__cvta_generic_to_shared(Ql);
    const uint32_t sKh = (uint32_t)__cvta_generic_to_shared(Kh);
    const uint32_t sKl = (uint32_t)__cvta_generic_to_shared(Kl);
    const uint32_t sVh = (uint32_t)__cvta_generic_to_shared(Vh);
    const uint32_t sVl = (uint32_t)__cvta_generic_to_shared(Vl);
    const uint32_t sPh = (uint32_t)__cvta_generic_to_shared(Ph);
    const uint32_t sPl = (uint32_t)__cvta_generic_to_shared(Pl);

    const int tid = threadIdx.x;
    const int ty = tid >> 5;          // warp 0..7
    const int tx = tid & 31;
    const int gid = tx >> 2;
    const int tig = tx & 3;
    const int b = blockIdx.y;
    const int chunk = blockIdx.x;
    const int kchunk0 = chunk * CK;

    // ---- load 48 selected q rows, split bf16 hi/lo
#pragma unroll
    for (int i = 0; i < 3; ++i) {
        int fidx = tid + 256 * i;        // 0..767
        int u    = fidx >> 4;
        int d4   = fidx & 15;
        float4 v = make_float4(0.f, 0.f, 0.f, 0.f);
        if (u < NU) {
            int qi = g_top[b * NUP + u];
            v = *(const float4*)(q + ((size_t)(b * LQ + qi)) * DH + 4 * d4);
        }
        uint32_t h0, l0, h1, l1;
        bfsplit2(v.x, v.y, h0, l0);
        bfsplit2(v.z, v.w, h1, l1);
        *(uint32_t*)(Qh + u * 72 + 4 * d4)     = h0;
        *(uint32_t*)(Qh + u * 72 + 4 * d4 + 2) = h1;
        *(uint32_t*)(Ql + u * 72 + 4 * d4)     = l0;
        *(uint32_t*)(Ql + u * 72 + 4 * d4 + 2) = l1;
    }

    float mrun[6], lrun[6];
#pragma unroll
    for (int i = 0; i < 6; ++i) { mrun[i] = -INFINITY; lrun[i] = 0.f; }
    float oc[3][4];
#pragma unroll
    for (int mt = 0; mt < 3; ++mt)
#pragma unroll
        for (int i = 0; i < 4; ++i) oc[mt][i] = 0.f;

    for (int kt = 0; kt < CK / KT; ++kt) {
        const int kg0 = kchunk0 + kt * KT;
        __syncthreads();
        // ---- load K and V tiles (both rows=key), split hi/lo, vectorized
#pragma unroll
        for (int i = 0; i < 4; ++i) {
            int fidx = tid + 256 * i;     // 0..1023
            int k    = fidx >> 4;
            int d4   = fidx & 15;
            float4 kv = *(const float4*)(K + ((size_t)(b * LK + kg0 + k)) * DH + 4 * d4);
            uint32_t h0, l0, h1, l1;
            bfsplit2(kv.x, kv.y, h0, l0);
            bfsplit2(kv.z, kv.w, h1, l1);
            *(uint32_t*)(Kh + k * 72 + 4 * d4)     = h0;
            *(uint32_t*)(Kh + k * 72 + 4 * d4 + 2) = h1;
            *(uint32_t*)(Kl + k * 72 + 4 * d4)     = l0;
            *(uint32_t*)(Kl + k * 72 + 4 * d4 + 2) = l1;
            float4 vv = *(const float4*)(V + ((size_t)(b * LK + kg0 + k)) * DH + 4 * d4);
            bfsplit2(vv.x, vv.y, h0, l0);
            bfsplit2(vv.z, vv.w, h1, l1);
            *(uint32_t*)(Vh + k * 72 + 4 * d4)     = h0;
            *(uint32_t*)(Vh + k * 72 + 4 * d4 + 2) = h1;
            *(uint32_t*)(Vl + k * 72 + 4 * d4)     = l0;
            *(uint32_t*)(Vl + k * 72 + 4 * d4 + 2) = l1;
        }
        __syncthreads();

        // ---- S = Q K^T (3-mma Karatsuba). warp ty owns keys 8ty..8ty+7
        {
            uint32_t bh[8], bl[8];
            uint32_t kaddr = sKh + (uint32_t)((8 * ty + (tx & 7)) * 144 + (tx >> 3) * 16);
            ldsm_x4(bh,     kaddr);
            ldsm_x4(bh + 4, kaddr + 64);
            kaddr = sKl + (uint32_t)((8 * ty + (tx & 7)) * 144 + (tx >> 3) * 16);
            ldsm_x4(bl,     kaddr);
            ldsm_x4(bl + 4, kaddr + 64);

#pragma unroll
            for (int mt = 0; mt < 3; ++mt) {
                float accS[4] = {0.f, 0.f, 0.f, 0.f};
                uint32_t arow = (uint32_t)((mt * 16 + (tx & 15)) * 144 + (tx >> 4) * 16);
#pragma unroll
                for (int ks = 0; ks < 4; ++ks) {
                    uint32_t ah[4], al[4];
                    ldsm_x4(ah, sQh + arow + ks * 32);
                    ldsm_x4(al, sQl + arow + ks * 32);
                    mma_bf16(accS, ah, bh[2 * ks], bh[2 * ks + 1]);
                    mma_bf16(accS, ah, bl[2 * ks], bl[2 * ks + 1]);
                    mma_bf16(accS, al, bh[2 * ks], bh[2 * ks + 1]);
                }
                int r0 = mt * 16 + gid;
                *(float2*)&SP[r0 * 68 + 8 * ty + 2 * tig] =
                    make_float2(accS[0] * 0.125f, accS[1] * 0.125f);
                *(float2*)&SP[(r0 + 8) * 68 + 8 * ty + 2 * tig] =
                    make_float2(accS[2] * 0.125f, accS[3] * 0.125f);
            }
        }
        __syncthreads();

        // ---- phase A: warp-private online softmax over rows 6ty..6ty+5
        float pr[6][2], fnew[6];
#pragma unroll
        for (int i = 0; i < 6; ++i) {
            int u = 6 * ty + i;
            float2 sv = *(const float2*)&SP[u * 68 + 2 * tx];
            float mx = fmaxf(sv.x, sv.y);
#pragma unroll
            for (int off = 16; off > 0; off >>= 1)
                mx = fmaxf(mx, __shfl_xor_sync(0xffffffffu, mx, off));
            float mn = fmaxf(mrun[i], mx);
            float f  = __expf(mrun[i] - mn);
            float p0 = __expf(sv.x - mn);
            float p1 = __expf(sv.y - mn);
            float ps = p0 + p1;
#pragma unroll
            for (int off = 16; off > 0; off >>= 1)
                ps += __shfl_xor_sync(0xffffffffu, ps, off);
            lrun[i] = lrun[i] * f + ps;
            mrun[i] = mn;
            fnew[i] = f;
            pr[i][0] = p0; pr[i][1] = p1;
            if (u < NU)
                *(float2*)(out_s + ((size_t)(b * NU + u)) * LK + kg0 + 2 * tx) = sv;
        }
        __syncthreads();

        // ---- phase B: write split P + rescale factors
#pragma unroll
        for (int i = 0; i < 6; ++i) {
            int u = 6 * ty + i;
            uint32_t h, l;
            bfsplit2(pr[i][0], pr[i][1], h, l);
            *(uint32_t*)(Ph + u * 72 + 2 * tx) = h;
            *(uint32_t*)(Pl + u * 72 + 2 * tx) = l;
            if (tx == 0) fS[u] = fnew[i];
        }
        __syncthreads();

        // ---- phase C: O += P V (3-mma Karatsuba). B-frags via ldmatrix.trans
        {
            uint32_t bh[8], bl[8];
            uint32_t vaddr = sVh + (uint32_t)(tx * 144 + 16 * ty);
            ldsm_x4_t(bh,     vaddr);
            ldsm_x4_t(bh + 4, vaddr + 32 * 144);
            vaddr = sVl + (uint32_t)(tx * 144 + 16 * ty);
            ldsm_x4_t(bl,     vaddr);
            ldsm_x4_t(bl + 4, vaddr + 32 * 144);

#pragma unroll
            for (int mt = 0; mt < 3; ++mt) {
                float f0 = fS[mt * 16 + gid];
                float f1 = fS[mt * 16 + gid + 8];
                oc[mt][0] *= f0; oc[mt][1] *= f0;
                oc[mt][2] *= f1; oc[mt][3] *= f1;
                uint32_t arow = (uint32_t)((mt * 16 + (tx & 15)) * 144 + (tx >> 4) * 16);
#pragma unroll
                for (int ks = 0; ks < 4; ++ks) {
                    uint32_t ph[4], pl2[4];
                    ldsm_x4(ph,  sPh + arow + ks * 32);
                    ldsm_x4(pl2, sPl + arow + ks * 32);
                    mma_bf16(oc[mt], ph,  bh[2 * ks], bh[2 * ks + 1]);
                    mma_bf16(oc[mt], ph,  bl[2 * ks], bl[2 * ks + 1]);
                    mma_bf16(oc[mt], pl2, bh[2 * ks], bh[2 * ks + 1]);
                }
            }
        }
    }

    // ---- write partials
    if (tx == 0) {
#pragma unroll
        for (int i = 0; i < 6; ++i) {
            int u = 6 * ty + i;
            g_pm[(b * NCHUNK + chunk) * NUP + u] = mrun[i];
            g_pl[(b * NCHUNK + chunk) * NUP + u] = lrun[i];
        }
    }
#pragma unroll
    for (int mt = 0; mt < 3; ++mt) {
        int r0 = mt * 16 + gid;
        *(float2*)&g_pacc[((size_t)(b * NCHUNK + chunk) * NUP + r0) * DH + 8 * ty + 2 * tig] =
            make_float2(oc[mt][0], oc[mt][1]);
        *(float2*)&g_pacc[((size_t)(b * NCHUNK + chunk) * NUP + r0 + 8) * DH + 8 * ty + 2 * tig] =
            make_float2(oc[mt][2], oc[mt][3]);
    }
}

// ---------------- kernel 8: combine split-softmax partials ----------------
__global__ void k_combine(float* __restrict__ out_o) {
    int u = blockIdx.x;
    int b = blockIdx.y;
    int d = threadIdx.x;
    float gm = -INFINITY;
    for (int c = 0; c < NCHUNK; ++c)
        gm = fmaxf(gm, g_pm[(b * NCHUNK + c) * NUP + u]);
    float L = 0.f, a = 0.f;
    for (int c = 0; c < NCHUNK; ++c) {
        float w = __expf(g_pm[(b * NCHUNK + c) * NUP + u] - gm);
        L += g_pl[(b * NCHUNK + c) * NUP + u] * w;
        a += g_pacc[((size_t)(b * NCHUNK + c) * NUP + u) * DH + d] * w;
    }
    out_o[(b * NU + u) * DH + d] = a / L;
}

// ---------------- launch ----------------
extern "C" void kernel_launch(void* const* d_in, const int* in_sizes, int n_in,
                              void* d_out, int out_size) {
    const float* q  = (const float*)d_in[0];
    const float* K  = (const float*)d_in[1];
    const float* V  = (const float*)d_in[2];
    const int* idx  = (const int*)d_in[3];
    float* out_o = (float*)d_out;                  // attn_output [8,45,64]
    float* out_s = out_o + NB * NU * DH;           // attn_scores [8,45,32768]

    (void)in_sizes; (void)n_in; (void)out_size;

    const int smem_attn  = 48 * 72 * 2 * 2 + 64 * 72 * 2 * 2 * 2 + 13824 + 192;  // 64704
    const int smem_exact = (250 * 68 + 128 * 68) * 4;                            // 102816
    cudaFuncSetAttribute(k_attn,    cudaFuncAttributeMaxDynamicSharedMemorySize, smem_attn);
    cudaFuncSetAttribute(k_M_exact, cudaFuncAttributeMaxDynamicSharedMemorySize, smem_exact);

    k_dedup<<<1, 1024>>>(idx);
    k_gather<<<(NB * LKS * 8 + 255) / 256, 256>>>(K);
    k_ksum1<<<dim3(8, NB), 256>>>(K, idx);
    k_M_mma<<<dim3(LQ / 64, NB), 256>>>(q);
    k_thresh<<<NB, 512>>>();
    k_M_exact<<<dim3(NSPLIT, NB), 256, smem_exact>>>(q, K);
    k_select<<<NB, 256>>>(q);
    k_attn<<<dim3(NCHUNK, NB), 256, smem_attn>>>(q, K, V, out_s);
    k_combine<<<dim3(NU, NB), 64>>>(out_o);
}

// round 12
// speedup vs baseline: 3.9579x; 1.0354x over previous
#include <cuda_runtime.h>
#include <cuda_bf16.h>
#include <math.h>
#include <stdint.h>

#define NB 8
#define LQ 4096
#define LK 32768
#define DH 64
#define LKS 8000
#define NU 45
#define NUP 48
#define NCHUNK 64
#define CK 512
#define KT 64
#define CANDMAX 1024
#define NSPLIT 32
#define MARGIN 1.0f

// ---------------- device scratch ----------------
__device__ __nv_bfloat16 g_KsampH[NB * LKS * DH];
__device__ int   g_uniq[LKS];
__device__ int   g_ucount;
__device__ int   g_upad;
__device__ float g_KsumP[NB * 8 * DH];
__device__ float g_M[NB * LQ];
__device__ int   g_top[NB * NUP];
__device__ int   g_cand[NB * CANDMAX];
__device__ float g_candP[NB * CANDMAX * NSPLIT];
__device__ int   g_ccount[NB];
__device__ float g_pm[NB * NCHUNK * NUP];
__device__ float g_pl[NB * NCHUNK * NUP];
__device__ float g_pacc[NB * NCHUNK * NUP * DH];

// ---------------- helpers ----------------
__device__ __forceinline__ void mma_bf16(float c[4], const uint32_t a[4],
                                         uint32_t b0, uint32_t b1) {
    asm volatile(
        "mma.sync.aligned.m16n8k16.row.col.f32.bf16.bf16.f32 "
        "{%0,%1,%2,%3}, {%4,%5,%6,%7}, {%8,%9}, {%0,%1,%2,%3};"
        : "+f"(c[0]), "+f"(c[1]), "+f"(c[2]), "+f"(c[3])
        : "r"(a[0]), "r"(a[1]), "r"(a[2]), "r"(a[3]), "r"(b0), "r"(b1));
}
__device__ __forceinline__ uint32_t packbf(float x, float y) {
    __nv_bfloat162 h = __floats2bfloat162_rn(x, y);
    return *(uint32_t*)&h;
}
__device__ __forceinline__ void bfsplit2(float x, float y, uint32_t& h, uint32_t& l) {
    __nv_bfloat16 hx = __float2bfloat16_rn(x), hy = __float2bfloat16_rn(y);
    float rx = x - __bfloat162float(hx);
    float ry = y - __bfloat162float(hy);
    __nv_bfloat16 lx = __float2bfloat16_rn(rx), ly = __float2bfloat16_rn(ry);
    h = ((uint32_t)(*(uint16_t*)&hy) << 16) | (uint32_t)(*(uint16_t*)&hx);
    l = ((uint32_t)(*(uint16_t*)&ly) << 16) | (uint32_t)(*(uint16_t*)&lx);
}
__device__ __forceinline__ void cp16(uint32_t dst, const void* src) {
    asm volatile("cp.async.ca.shared.global [%0], [%1], 16;\n" :: "r"(dst), "l"(src));
}
__device__ __forceinline__ void ldsm_x4(uint32_t r[4], uint32_t addr) {
    asm volatile("ldmatrix.sync.aligned.m8n8.x4.shared.b16 {%0,%1,%2,%3}, [%4];"
                 : "=r"(r[0]), "=r"(r[1]), "=r"(r[2]), "=r"(r[3]) : "r"(addr));
}
__device__ __forceinline__ void ldsm_x4_t(uint32_t r[4], uint32_t addr) {
    asm volatile("ldmatrix.sync.aligned.m8n8.x4.trans.shared.b16 {%0,%1,%2,%3}, [%4];"
                 : "=r"(r[0]), "=r"(r[1]), "=r"(r[2]), "=r"(r[3]) : "r"(addr));
}

// ---------------- kernel 0: dedupe sampled indices ----------------
__global__ void k_dedup(const int* __restrict__ idx) {
    __shared__ unsigned bm[250];
    __shared__ int wo[251];
    int tid = threadIdx.x;
    for (int i = tid; i < 250; i += 1024) bm[i] = 0u;
    __syncthreads();
    for (int i = tid; i < LKS; i += 1024) {
        int v = idx[i];
        atomicOr(&bm[v >> 5], 1u << (v & 31));
    }
    __syncthreads();
    if (tid == 0) {
        int acc = 0;
        for (int w = 0; w < 250; ++w) { wo[w] = acc; acc += __popc(bm[w]); }
        wo[250] = acc;
        g_ucount = acc;
        g_upad = (acc + 63) & ~63;
    }
    __syncthreads();
    for (int w = tid; w < 250; w += 1024) {
        unsigned m = bm[w];
        int o = wo[w];
        while (m) {
            int b = __ffs(m) - 1;
            g_uniq[o++] = w * 32 + b;
            m &= m - 1;
        }
    }
    __syncthreads();
    if (tid < 64) {
        int uc = wo[250];
        int up = (uc + 63) & ~63;
        if (uc + tid < up) g_uniq[uc + tid] = g_uniq[0];
    }
}

// ---------------- kernel 1: gather unique K rows -> bf16 ----------------
__global__ void k_gather(const float* __restrict__ K) {
    int t = blockIdx.x * blockDim.x + threadIdx.x;
    int chunk = t & 7;
    int rest = t >> 3;
    int j = rest % LKS;
    int b = rest / LKS;
    if (b >= NB) return;
    if (j >= g_upad) return;
    int src = g_uniq[j];
    const float4* p = (const float4*)(K + ((size_t)b * LK + src) * DH + chunk * 8);
    float4 v0 = p[0], v1 = p[1];
    uint4 w = make_uint4(packbf(v0.x, v0.y), packbf(v0.z, v0.w),
                         packbf(v1.x, v1.y), packbf(v1.z, v1.w));
    *(uint4*)(g_KsampH + ((size_t)(b * LKS) + j) * DH + chunk * 8) = w;
}

// ---------------- kernel 2: Ksum partials over full multiset ----------------
__global__ void k_ksum1(const float* __restrict__ K, const int* __restrict__ idx) {
    int b = blockIdx.y;
    int sp = blockIdx.x;
    int d = threadIdx.x & 63;
    int g = threadIdx.x >> 6;
    float s = 0.f;
    for (int u = sp * 1000 + g; u < (sp + 1) * 1000; u += 4)
        s += K[((size_t)b * LK + idx[u]) * DH + d];
    __shared__ float red[4][64];
    red[g][d] = s;
    __syncthreads();
    if (g == 0)
        g_KsumP[(b * 8 + sp) * DH + d] = red[0][d] + red[1][d] + red[2][d] + red[3][d];
}

// ---------------- kernel 3: approx M via bf16 mma, m128 x n64 tiles --------
// 8 warps: mhalf = wid&1 (m64 each), nquad = wid>>1 (n16 each).
// Warp = m64 x n16: each ldsm_x4-pair feeds 16 mma (ratio 1:8 vs 1:4 before).
__global__ __launch_bounds__(256, 2) void k_M_mma(const float* __restrict__ q) {
    __shared__ __nv_bfloat16 Bs[2][64 * 72];
    __shared__ float rowmaxS[4][128];
    __shared__ float ksumS[64];

    const int tid  = threadIdx.x;
    const int wid  = tid >> 5;
    const int lane = tid & 31;
    const int gid  = lane >> 2;
    const int tig  = lane & 3;
    const int b    = blockIdx.y;
    const int m0   = blockIdx.x * 128;
    const int mhalf = (wid & 1) * 64;
    const int nquad = wid >> 1;           // 0..3 -> keys [16*nquad, +16)

    if (tid < 64) {
        float s = 0.f;
#pragma unroll
        for (int sp = 0; sp < 8; ++sp) s += g_KsumP[(b * 8 + sp) * DH + tid];
        ksumS[tid] = s;
    }

    // A fragments for 4 m-blocks (persist whole kernel)
    uint32_t a[4][4][4];
#pragma unroll
    for (int mb = 0; mb < 4; ++mb) {
        int r0 = m0 + mhalf + mb * 16 + gid;
        int r1 = r0 + 8;
        const float* q0 = q + ((size_t)(b * LQ) + r0) * DH;
        const float* q1 = q + ((size_t)(b * LQ) + r1) * DH;
#pragma unroll
        for (int kk = 0; kk < 4; ++kk) {
            int c = kk * 16 + 2 * tig;
            float2 x0 = *(const float2*)(q0 + c);
            float2 x1 = *(const float2*)(q1 + c);
            float2 x2 = *(const float2*)(q0 + c + 8);
            float2 x3 = *(const float2*)(q1 + c + 8);
            a[mb][kk][0] = packbf(x0.x, x0.y);
            a[mb][kk][1] = packbf(x1.x, x1.y);
            a[mb][kk][2] = packbf(x2.x, x2.y);
            a[mb][kk][3] = packbf(x3.x, x3.y);
        }
    }

    const int niter = g_upad >> 6;
    const int prow = tid >> 2, pseg = tid & 3;
    uint32_t sBase = (uint32_t)__cvta_generic_to_shared(&Bs[0][0]);

    {   // prologue: tile 0
        const __nv_bfloat16* src = g_KsampH + ((size_t)(b * LKS) + prow) * DH + pseg * 16;
        uint32_t dst = sBase + prow * 144 + pseg * 32;
        cp16(dst, src);
        cp16(dst + 16, src + 8);
    }
    asm volatile("cp.async.commit_group;\n");

    float rmax[4][2];
#pragma unroll
    for (int mb = 0; mb < 4; ++mb) { rmax[mb][0] = -INFINITY; rmax[mb][1] = -INFINITY; }

    for (int t = 0; t < niter; ++t) {
        asm volatile("cp.async.wait_group 0;\n");
        __syncthreads();
        if (t + 1 < niter) {
            const __nv_bfloat16* src =
                g_KsampH + ((size_t)(b * LKS) + (t + 1) * 64 + prow) * DH + pseg * 16;
            uint32_t dst = sBase + ((t + 1) & 1) * 9216 + prow * 144 + pseg * 32;
            cp16(dst, src);
            cp16(dst + 16, src + 8);
        }
        asm volatile("cp.async.commit_group;\n");

        uint32_t bufBase = sBase + (t & 1) * 9216;
#pragma unroll
        for (int nc = 0; nc < 2; ++nc) {
            int row = nquad * 16 + nc * 8 + (lane & 7);
            uint32_t addr0 = bufBase + (uint32_t)(row * 144 + (lane >> 3) * 16);
            uint32_t bk[4], bk2[4];
            ldsm_x4(bk,  addr0);          // k 0..31
            ldsm_x4(bk2, addr0 + 64);     // k 32..63
#pragma unroll
            for (int mb = 0; mb < 4; ++mb) {
                float acc[4] = {0.f, 0.f, 0.f, 0.f};
                mma_bf16(acc, a[mb][0], bk[0],  bk[1]);
                mma_bf16(acc, a[mb][1], bk[2],  bk[3]);
                mma_bf16(acc, a[mb][2], bk2[0], bk2[1]);
                mma_bf16(acc, a[mb][3], bk2[2], bk2[3]);
                rmax[mb][0] = fmaxf(rmax[mb][0], fmaxf(acc[0], acc[1]));
                rmax[mb][1] = fmaxf(rmax[mb][1], fmaxf(acc[2], acc[3]));
            }
        }
    }

#pragma unroll
    for (int mb = 0; mb < 4; ++mb)
#pragma unroll
        for (int h = 0; h < 2; ++h) {
            rmax[mb][h] = fmaxf(rmax[mb][h], __shfl_xor_sync(0xffffffffu, rmax[mb][h], 1));
            rmax[mb][h] = fmaxf(rmax[mb][h], __shfl_xor_sync(0xffffffffu, rmax[mb][h], 2));
        }
    if (tig == 0) {
#pragma unroll
        for (int mb = 0; mb < 4; ++mb) {
            rowmaxS[nquad][mhalf + mb * 16 + gid]     = rmax[mb][0];
            rowmaxS[nquad][mhalf + mb * 16 + gid + 8] = rmax[mb][1];
        }
    }
    __syncthreads();

    if (tid < 128) {
        int m = m0 + tid;
        float mx = fmaxf(fmaxf(rowmaxS[0][tid], rowmaxS[1][tid]),
                         fmaxf(rowmaxS[2][tid], rowmaxS[3][tid]));
        const float* qp = q + ((size_t)(b * LQ) + m) * DH;
        float d0 = 0.f, d1 = 0.f, d2 = 0.f, d3 = 0.f;
#pragma unroll
        for (int d = 0; d < 64; d += 4) {
            d0 += qp[d]     * ksumS[d];
            d1 += qp[d + 1] * ksumS[d + 1];
            d2 += qp[d + 2] * ksumS[d + 2];
            d3 += qp[d + 3] * ksumS[d + 3];
        }
        g_M[b * LQ + m] = mx - ((d0 + d1) + (d2 + d3)) * (1.0f / (float)LKS);
    }
}

// ---------------- kernel 4: histogram threshold + candidate collect --------
__global__ __launch_bounds__(512) void k_thresh() {
    const int b = blockIdx.x;
    const int tid = threadIdx.x;
    __shared__ float sv[LQ];
    __shared__ int hist[512];
    __shared__ float wmn[16], wmx[16];
    __shared__ float s_mn, s_range, s_thresh;
    __shared__ int s_cnt;

    float mn = INFINITY, mx = -INFINITY;
    for (int j = tid; j < LQ; j += 512) {
        float v = g_M[b * LQ + j];
        sv[j] = v;
        mn = fminf(mn, v);
        mx = fmaxf(mx, v);
    }
#pragma unroll
    for (int off = 16; off > 0; off >>= 1) {
        mn = fminf(mn, __shfl_xor_sync(0xffffffffu, mn, off));
        mx = fmaxf(mx, __shfl_xor_sync(0xffffffffu, mx, off));
    }
    if ((tid & 31) == 0) { wmn[tid >> 5] = mn; wmx[tid >> 5] = mx; }
    if (tid < 512) hist[tid] = 0;
    if (tid == 0) s_cnt = 0;
    __syncthreads();
    if (tid == 0) {
        float a = INFINITY, z = -INFINITY;
        for (int g = 0; g < 16; ++g) { a = fminf(a, wmn[g]); z = fmaxf(z, wmx[g]); }
        s_mn = a;
        s_range = z - a + 1e-6f;
    }
    __syncthreads();
    const float scale = 511.0f / s_range;
    for (int j = tid; j < LQ; j += 512) {
        int bin = (int)((sv[j] - s_mn) * scale);
        bin = max(0, min(511, bin));
        atomicAdd(&hist[bin], 1);
    }
    __syncthreads();
    if (tid == 0) {
        int cum = 0, bsel = 511;
        for (int i = 0; i < 512; ++i) {
            cum += hist[i];
            if (cum >= NU) { bsel = i; break; }
        }
        s_thresh = s_mn + (float)(bsel + 1) * (s_range / 511.0f) + MARGIN;
    }
    __syncthreads();
    const float th = s_thresh;
    for (int j = tid; j < LQ; j += 512) {
        if (sv[j] <= th) {
            int p = atomicAdd(&s_cnt, 1);
            if (p < CANDMAX) g_cand[b * CANDMAX + p] = j;
        }
    }
    __syncthreads();
    if (tid == 0) g_ccount[b] = min(s_cnt, CANDMAX);
}

// ---------------- kernel 5: exact fp32 max (split-K over unique keys) ------
__global__ __launch_bounds__(256) void k_M_exact(const float* __restrict__ q,
                                                 const float* __restrict__ K) {
    extern __shared__ float sh[];
    float* Kc = sh;
    float* Qc = sh + 250 * 68;

    const int b = blockIdx.y;
    const int sp = blockIdx.x;
    const int tid = threadIdx.x;
    const int wid = tid >> 5;
    const int lane = tid & 31;

    const int uc = g_ucount;
    const int j0 = (sp * uc) / NSPLIT;
    const int j1 = ((sp + 1) * uc) / NSPLIT;
    const int nr = j1 - j0;

    for (int i = tid; i < nr * 16; i += 256) {
        int r = i >> 4, d4 = i & 15;
        int src = g_uniq[j0 + r];
        *(float4*)&Kc[r * 68 + 4 * d4] =
            *(const float4*)(K + ((size_t)b * LK + src) * DH + 4 * d4);
    }
    const int cnt = g_ccount[b];

    for (int cg = 0; cg < cnt; cg += 128) {
        int ncg = min(128, cnt - cg);
        __syncthreads();
        for (int i = tid; i < ncg * 16; i += 256) {
            int c = i >> 4, d4 = i & 15;
            int qi = g_cand[b * CANDMAX + cg + c];
            *(float4*)&Qc[c * 68 + 4 * d4] =
                *(const float4*)(q + ((size_t)(b * LQ) + qi) * DH + 4 * d4);
        }
        __syncthreads();
        for (int c = wid; c < ncg; c += 8) {
            const float* qr = &Qc[c * 68];
            float mx = -INFINITY;
            for (int r = lane; r < nr; r += 32) {
                const float* kr = &Kc[r * 68];
                float a0 = 0.f, a1 = 0.f, a2 = 0.f, a3 = 0.f;
#pragma unroll
                for (int d4 = 0; d4 < 16; ++d4) {
                    float4 kv = *(const float4*)&kr[4 * d4];
                    float4 qv = *(const float4*)&qr[4 * d4];
                    a0 += qv.x * kv.x;
                    a1 += qv.y * kv.y;
                    a2 += qv.z * kv.z;
                    a3 += qv.w * kv.w;
                }
                mx = fmaxf(mx, (a0 + a1) + (a2 + a3));
            }
#pragma unroll
            for (int off = 16; off > 0; off >>= 1)
                mx = fmaxf(mx, __shfl_xor_sync(0xffffffffu, mx, off));
            if (lane == 0)
                g_candP[((size_t)(b * CANDMAX) + cg + c) * NSPLIT + sp] = mx;
        }
    }
}

// ---------------- kernel 6: finalize exact M + top-45 selection ------------
__global__ __launch_bounds__(256) void k_select(const float* __restrict__ q) {
    const int b = blockIdx.x;
    const int tid = threadIdx.x;
    __shared__ float cv[CANDMAX];
    __shared__ int   ci[CANDMAX];
    __shared__ float ksumS[64];
    const int cnt = g_ccount[b];

    if (tid < 64) {
        float s = 0.f;
#pragma unroll
        for (int sp = 0; sp < 8; ++sp) s += g_KsumP[(b * 8 + sp) * DH + tid];
        ksumS[tid] = s;
    }
    __syncthreads();

    for (int c = tid; c < CANDMAX; c += 256) {
        if (c < cnt) {
            float mx = -INFINITY;
#pragma unroll
            for (int s = 0; s < NSPLIT; ++s)
                mx = fmaxf(mx, g_candP[((size_t)(b * CANDMAX) + c) * NSPLIT + s]);
            int qi = g_cand[b * CANDMAX + c];
            const float* qp = q + ((size_t)(b * LQ) + qi) * DH;
            float dot = 0.f;
            for (int d = 0; d < 64; ++d) dot += qp[d] * ksumS[d];
            cv[c] = mx - dot * (1.0f / (float)LKS);
            ci[c] = qi;
        } else {
            cv[c] = INFINITY;
            ci[c] = 1 << 30;
        }
    }
    __syncthreads();

    if (tid < 32) {
        for (int it = 0; it < NU; ++it) {
            float best = INFINITY; int bidx = 1 << 30; int bslot = 0;
            for (int j = tid; j < CANDMAX; j += 32) {
                float v = cv[j]; int qi2 = ci[j];
                if (v < best || (v == best && qi2 < bidx)) { best = v; bidx = qi2; bslot = j; }
            }
#pragma unroll
            for (int off = 16; off > 0; off >>= 1) {
                float v2 = __shfl_xor_sync(0xffffffffu, best, off);
                int   i2 = __shfl_xor_sync(0xffffffffu, bidx, off);
                int   s2 = __shfl_xor_sync(0xffffffffu, bslot, off);
                if (v2 < best || (v2 == best && i2 < bidx)) { best = v2; bidx = i2; bslot = s2; }
            }
            if (tid == 0) { g_top[b * NUP + it] = bidx; cv[bslot] = INFINITY; }
            __syncwarp();
        }
        if (tid < NUP - NU) g_top[b * NUP + NU + tid] = 0;
    }
}

// ---------------- kernel 7: bf16x2-Karatsuba mma attention ----------
__global__ __launch_bounds__(256, 3) void k_attn(const float* __restrict__ q,
                                                 const float* __restrict__ K,
                                                 const float* __restrict__ V,
                                                 float* __restrict__ out_s) {
    extern __shared__ char smc[];
    __nv_bfloat16* Qh = (__nv_bfloat16*)smc;            // 48*72
    __nv_bfloat16* Ql = Qh + 48 * 72;
    __nv_bfloat16* Kh = Ql + 48 * 72;                   // 64*72
    __nv_bfloat16* Kl = Kh + 64 * 72;
    __nv_bfloat16* Vh = Kl + 64 * 72;                   // 64*72 rows=key
    __nv_bfloat16* Vl = Vh + 64 * 72;
    char* Ub = (char*)(Vl + 64 * 72);                   // union, 13824 B
    float* SP = (float*)Ub;                             // [48][68] f32
    __nv_bfloat16* Ph = (__nv_bfloat16*)Ub;             // [48][72]
    __nv_bfloat16* Pl = Ph + 48 * 72;
    float* fS = (float*)(Ub + 13824);                   // [48]

    const uint32_t sQh = (uint32_t)__cvta_generic_to_shared(Qh);
    const uint32_t sQl = (uint32_t)__cvta_generic_to_shared(Ql);
    const uint32_t sKh = (uint32_t)__cvta_generic_to_shared(Kh);
    const uint32_t sKl = (uint32_t)__cvta_generic_to_shared(Kl);
    const uint32_t sVh = (uint32_t)__cvta_generic_to_shared(Vh);
    const uint32_t sVl = (uint32_t)__cvta_generic_to_shared(Vl);
    const uint32_t sPh = (uint32_t)__cvta_generic_to_shared(Ph);
    const uint32_t sPl = (uint32_t)__cvta_generic_to_shared(Pl);

    const int tid = threadIdx.x;
    const int ty = tid >> 5;
    const int tx = tid & 31;
    const int gid = tx >> 2;
    const int tig = tx & 3;
    const int b = blockIdx.y;
    const int chunk = blockIdx.x;
    const int kchunk0 = chunk * CK;

#pragma unroll
    for (int i = 0; i < 3; ++i) {
        int fidx = tid + 256 * i;
        int u    = fidx >> 4;
        int d4   = fidx & 15;
        float4 v = make_float4(0.f, 0.f, 0.f, 0.f);
        if (u < NU) {
            int qi = g_top[b * NUP + u];
            v = *(const float4*)(q + ((size_t)(b * LQ + qi)) * DH + 4 * d4);
        }
        uint32_t h0, l0, h1, l1;
        bfsplit2(v.x, v.y, h0, l0);
        bfsplit2(v.z, v.w, h1, l1);
        *(uint32_t*)(Qh + u * 72 + 4 * d4)     = h0;
        *(uint32_t*)(Qh + u * 72 + 4 * d4 + 2) = h1;
        *(uint32_t*)(Ql + u * 72 + 4 * d4)     = l0;
        *(uint32_t*)(Ql + u * 72 + 4 * d4 + 2) = l1;
    }

    float mrun[6], lrun[6];
#pragma unroll
    for (int i = 0; i < 6; ++i) { mrun[i] = -INFINITY; lrun[i] = 0.f; }
    float oc[3][4];
#pragma unroll
    for (int mt = 0; mt < 3; ++mt)
#pragma unroll
        for (int i = 0; i < 4; ++i) oc[mt][i] = 0.f;

    for (int kt = 0; kt < CK / KT; ++kt) {
        const int kg0 = kchunk0 + kt * KT;
        __syncthreads();
#pragma unroll
        for (int i = 0; i < 4; ++i) {
            int fidx = tid + 256 * i;
            int k    = fidx >> 4;
            int d4   = fidx & 15;
            float4 kv = *(const float4*)(K + ((size_t)(b * LK + kg0 + k)) * DH + 4 * d4);
            uint32_t h0, l0, h1, l1;
            bfsplit2(kv.x, kv.y, h0, l0);
            bfsplit2(kv.z, kv.w, h1, l1);
            *(uint32_t*)(Kh + k * 72 + 4 * d4)     = h0;
            *(uint32_t*)(Kh + k * 72 + 4 * d4 + 2) = h1;
            *(uint32_t*)(Kl + k * 72 + 4 * d4)     = l0;
            *(uint32_t*)(Kl + k * 72 + 4 * d4 + 2) = l1;
            float4 vv = *(const float4*)(V + ((size_t)(b * LK + kg0 + k)) * DH + 4 * d4);
            bfsplit2(vv.x, vv.y, h0, l0);
            bfsplit2(vv.z, vv.w, h1, l1);
            *(uint32_t*)(Vh + k * 72 + 4 * d4)     = h0;
            *(uint32_t*)(Vh + k * 72 + 4 * d4 + 2) = h1;
            *(uint32_t*)(Vl + k * 72 + 4 * d4)     = l0;
            *(uint32_t*)(Vl + k * 72 + 4 * d4 + 2) = l1;
        }
        __syncthreads();

        {
            uint32_t bh[8], bl[8];
            uint32_t kaddr = sKh + (uint32_t)((8 * ty + (tx & 7)) * 144 + (tx >> 3) * 16);
            ldsm_x4(bh,     kaddr);
            ldsm_x4(bh + 4, kaddr + 64);
            kaddr = sKl + (uint32_t)((8 * ty + (tx & 7)) * 144 + (tx >> 3) * 16);
            ldsm_x4(bl,     kaddr);
            ldsm_x4(bl + 4, kaddr + 64);

#pragma unroll
            for (int mt = 0; mt < 3; ++mt) {
                float accS[4] = {0.f, 0.f, 0.f, 0.f};
                uint32_t arow = (uint32_t)((mt * 16 + (tx & 15)) * 144 + (tx >> 4) * 16);
#pragma unroll
                for (int ks = 0; ks < 4; ++ks) {
                    uint32_t ah[4], al[4];
                    ldsm_x4(ah, sQh + arow + ks * 32);
                    ldsm_x4(al, sQl + arow + ks * 32);
                    mma_bf16(accS, ah, bh[2 * ks], bh[2 * ks + 1]);
                    mma_bf16(accS, ah, bl[2 * ks], bl[2 * ks + 1]);
                    mma_bf16(accS, al, bh[2 * ks], bh[2 * ks + 1]);
                }
                int r0 = mt * 16 + gid;
                *(float2*)&SP[r0 * 68 + 8 * ty + 2 * tig] =
                    make_float2(accS[0] * 0.125f, accS[1] * 0.125f);
                *(float2*)&SP[(r0 + 8) * 68 + 8 * ty + 2 * tig] =
                    make_float2(accS[2] * 0.125f, accS[3] * 0.125f);
            }
        }
        __syncthreads();

        float pr[6][2], fnew[6];
#pragma unroll
        for (int i = 0; i < 6; ++i) {
            int u = 6 * ty + i;
            float2 sv = *(const float2*)&SP[u * 68 + 2 * tx];
            float mx = fmaxf(sv.x, sv.y);
#pragma unroll
            for (int off = 16; off > 0; off >>= 1)
                mx = fmaxf(mx, __shfl_xor_sync(0xffffffffu, mx, off));
            float mn = fmaxf(mrun[i], mx);
            float f  = __expf(mrun[i] - mn);
            float p0 = __expf(sv.x - mn);
            float p1 = __expf(sv.y - mn);
            float ps = p0 + p1;
#pragma unroll
            for (int off = 16; off > 0; off >>= 1)
                ps += __shfl_xor_sync(0xffffffffu, ps, off);
            lrun[i] = lrun[i] * f + ps;
            mrun[i] = mn;
            fnew[i] = f;
            pr[i][0] = p0; pr[i][1] = p1;
            if (u < NU)
                *(float2*)(out_s + ((size_t)(b * NU + u)) * LK + kg0 + 2 * tx) = sv;
        }
        __syncthreads();

#pragma unroll
        for (int i = 0; i < 6; ++i) {
            int u = 6 * ty + i;
            uint32_t h, l;
            bfsplit2(pr[i][0], pr[i][1], h, l);
            *(uint32_t*)(Ph + u * 72 + 2 * tx) = h;
            *(uint32_t*)(Pl + u * 72 + 2 * tx) = l;
            if (tx == 0) fS[u] = fnew[i];
        }
        __syncthreads();

        {
            uint32_t bh[8], bl[8];
            uint32_t vaddr = sVh + (uint32_t)(tx * 144 + 16 * ty);
            ldsm_x4_t(bh,     vaddr);
            ldsm_x4_t(bh + 4, vaddr + 32 * 144);
            vaddr = sVl + (uint32_t)(tx * 144 + 16 * ty);
            ldsm_x4_t(bl,     vaddr);
            ldsm_x4_t(bl + 4, vaddr + 32 * 144);

#pragma unroll
            for (int mt = 0; mt < 3; ++mt) {
                float f0 = fS[mt * 16 + gid];
                float f1 = fS[mt * 16 + gid + 8];
                oc[mt][0] *= f0; oc[mt][1] *= f0;
                oc[mt][2] *= f1; oc[mt][3] *= f1;
                uint32_t arow = (uint32_t)((mt * 16 + (tx & 15)) * 144 + (tx >> 4) * 16);
#pragma unroll
                for (int ks = 0; ks < 4; ++ks) {
                    uint32_t ph[4], pl2[4];
                    ldsm_x4(ph,  sPh + arow + ks * 32);
                    ldsm_x4(pl2, sPl + arow + ks * 32);
                    mma_bf16(oc[mt], ph,  bh[2 * ks], bh[2 * ks + 1]);
                    mma_bf16(oc[mt], ph,  bl[2 * ks], bl[2 * ks + 1]);
                    mma_bf16(oc[mt], pl2, bh[2 * ks], bh[2 * ks + 1]);
                }
            }
        }
    }

    if (tx == 0) {
#pragma unroll
        for (int i = 0; i < 6; ++i) {
            int u = 6 * ty + i;
            g_pm[(b * NCHUNK + chunk) * NUP + u] = mrun[i];
            g_pl[(b * NCHUNK + chunk) * NUP + u] = lrun[i];
        }
    }
#pragma unroll
    for (int mt = 0; mt < 3; ++mt) {
        int r0 = mt * 16 + gid;
        *(float2*)&g_pacc[((size_t)(b * NCHUNK + chunk) * NUP + r0) * DH + 8 * ty + 2 * tig] =
            make_float2(oc[mt][0], oc[mt][1]);
        *(float2*)&g_pacc[((size_t)(b * NCHUNK + chunk) * NUP + r0 + 8) * DH + 8 * ty + 2 * tig] =
            make_float2(oc[mt][2], oc[mt][3]);
    }
}

// ---------------- kernel 8: combine split-softmax partials ----------------
__global__ void k_combine(float* __restrict__ out_o) {
    int u = blockIdx.x;
    int b = blockIdx.y;
    int d = threadIdx.x;
    float gm = -INFINITY;
    for (int c = 0; c < NCHUNK; ++c)
        gm = fmaxf(gm, g_pm[(b * NCHUNK + c) * NUP + u]);
    float L = 0.f, a = 0.f;
    for (int c = 0; c < NCHUNK; ++c) {
        float w = __expf(g_pm[(b * NCHUNK + c) * NUP + u] - gm);
        L += g_pl[(b * NCHUNK + c) * NUP + u] * w;
        a += g_pacc[((size_t)(b * NCHUNK + c) * NUP + u) * DH + d] * w;
    }
    out_o[(b * NU + u) * DH + d] = a / L;
}

// ---------------- launch ----------------
extern "C" void kernel_launch(void* const* d_in, const int* in_sizes, int n_in,
                              void* d_out, int out_size) {
    const float* q  = (const float*)d_in[0];
    const float* K  = (const float*)d_in[1];
    const float* V  = (const float*)d_in[2];
    const int* idx  = (const int*)d_in[3];
    float* out_o = (float*)d_out;                  // attn_output [8,45,64]
    float* out_s = out_o + NB * NU * DH;           // attn_scores [8,45,32768]

    (void)in_sizes; (void)n_in; (void)out_size;

    const int smem_attn  = 48 * 72 * 2 * 2 + 64 * 72 * 2 * 2 * 2 + 13824 + 192;  // 64704
    const int smem_exact = (250 * 68 + 128 * 68) * 4;                            // 102816
    cudaFuncSetAttribute(k_attn,    cudaFuncAttributeMaxDynamicSharedMemorySize, smem_attn);
    cudaFuncSetAttribute(k_M_exact, cudaFuncAttributeMaxDynamicSharedMemorySize, smem_exact);

    k_dedup<<<1, 1024>>>(idx);
    k_gather<<<(NB * LKS * 8 + 255) / 256, 256>>>(K);
    k_ksum1<<<dim3(8, NB), 256>>>(K, idx);
    k_M_mma<<<dim3(LQ / 128, NB), 256>>>(q);
    k_thresh<<<NB, 512>>>();
    k_M_exact<<<dim3(NSPLIT, NB), 256, smem_exact>>>(q, K);
    k_select<<<NB, 256>>>(q);
    k_attn<<<dim3(NCHUNK, NB), 256, smem_attn>>>(q, K, V, out_s);
    k_combine<<<dim3(NU, NB), 64>>>(out_o);
}

// round 13
// speedup vs baseline: 4.4582x; 1.1264x over previous
#include <cuda_runtime.h>
#include <cuda_bf16.h>
#include <math.h>
#include <stdint.h>

#define NB 8
#define LQ 4096
#define LK 32768
#define DH 64
#define LKS 8000
#define UPM 8064            // upper bound for 128-padded unique count
#define GPB 252             // gather blocks per batch = UPM/32
#define NU 45
#define NUP 48
#define NCHUNK 54
#define KT 64
#define NTILES 512          // LK / KT
#define CANDMAX 1024
#define NSPLIT 32
#define MARGIN 1.0f

// ---------------- device scratch ----------------
__device__ __nv_bfloat16 g_KsampH[NB * UPM * DH];
__device__ int   g_uniq[UPM];
__device__ float g_ucnt[UPM];
__device__ int   g_ucount;
__device__ int   g_upad;
__device__ float g_Kpart[NB * GPB * DH];
__device__ float g_Ksum[NB * DH];
__device__ float g_M[NB * LQ];
__device__ int   g_top[NB * NUP];
__device__ int   g_cand[NB * CANDMAX];
__device__ float g_candP[NB * CANDMAX * NSPLIT];
__device__ int   g_ccount[NB];
__device__ float g_pm[NB * NCHUNK * NUP];
__device__ float g_pl[NB * NCHUNK * NUP];
__device__ float g_pacc[NB * NCHUNK * NUP * DH];

// ---------------- helpers ----------------
__device__ __forceinline__ void mma_bf16(float c[4], const uint32_t a[4],
                                         uint32_t b0, uint32_t b1) {
    asm volatile(
        "mma.sync.aligned.m16n8k16.row.col.f32.bf16.bf16.f32 "
        "{%0,%1,%2,%3}, {%4,%5,%6,%7}, {%8,%9}, {%0,%1,%2,%3};"
        : "+f"(c[0]), "+f"(c[1]), "+f"(c[2]), "+f"(c[3])
        : "r"(a[0]), "r"(a[1]), "r"(a[2]), "r"(a[3]), "r"(b0), "r"(b1));
}
__device__ __forceinline__ uint32_t packbf(float x, float y) {
    __nv_bfloat162 h = __floats2bfloat162_rn(x, y);
    return *(uint32_t*)&h;
}
__device__ __forceinline__ void bfsplit2(float x, float y, uint32_t& h, uint32_t& l) {
    __nv_bfloat16 hx = __float2bfloat16_rn(x), hy = __float2bfloat16_rn(y);
    float rx = x - __bfloat162float(hx);
    float ry = y - __bfloat162float(hy);
    __nv_bfloat16 lx = __float2bfloat16_rn(rx), ly = __float2bfloat16_rn(ry);
    h = ((uint32_t)(*(uint16_t*)&hy) << 16) | (uint32_t)(*(uint16_t*)&hx);
    l = ((uint32_t)(*(uint16_t*)&ly) << 16) | (uint32_t)(*(uint16_t*)&lx);
}
__device__ __forceinline__ void cp16(uint32_t dst, const void* src) {
    asm volatile("cp.async.ca.shared.global [%0], [%1], 16;\n" :: "r"(dst), "l"(src));
}
__device__ __forceinline__ void ldsm_x4(uint32_t r[4], uint32_t addr) {
    asm volatile("ldmatrix.sync.aligned.m8n8.x4.shared.b16 {%0,%1,%2,%3}, [%4];"
                 : "=r"(r[0]), "=r"(r[1]), "=r"(r[2]), "=r"(r[3]) : "r"(addr));
}
__device__ __forceinline__ void ldsm_x4_t(uint32_t r[4], uint32_t addr) {
    asm volatile("ldmatrix.sync.aligned.m8n8.x4.trans.shared.b16 {%0,%1,%2,%3}, [%4];"
                 : "=r"(r[0]), "=r"(r[1]), "=r"(r[2]), "=r"(r[3]) : "r"(addr));
}

// ---------------- kernel 0: dedupe sampled indices + counts ----------------
__global__ void k_dedup(const int* __restrict__ idx) {
    __shared__ unsigned bm[250];
    __shared__ int wo[251];
    __shared__ int hist[LKS];
    int tid = threadIdx.x;
    for (int i = tid; i < 250; i += 1024) bm[i] = 0u;
    for (int i = tid; i < LKS; i += 1024) hist[i] = 0;
    __syncthreads();
    for (int i = tid; i < LKS; i += 1024) {
        int v = idx[i];
        atomicOr(&bm[v >> 5], 1u << (v & 31));
        atomicAdd(&hist[v], 1);
    }
    __syncthreads();
    if (tid == 0) {
        int acc = 0;
        for (int w = 0; w < 250; ++w) { wo[w] = acc; acc += __popc(bm[w]); }
        wo[250] = acc;
        g_ucount = acc;
        g_upad = (acc + 127) & ~127;
    }
    __syncthreads();
    for (int w = tid; w < 250; w += 1024) {
        unsigned m = bm[w];
        int o = wo[w];
        while (m) {
            int bbit = __ffs(m) - 1;
            int v = w * 32 + bbit;
            g_uniq[o] = v;
            g_ucnt[o] = (float)hist[v];
            ++o;
            m &= m - 1;
        }
    }
    __syncthreads();
    if (tid < 128) {
        int uc = wo[250];
        int up = (uc + 127) & ~127;
        if (uc + tid < up) {
            g_uniq[uc + tid] = g_uniq[0];
            g_ucnt[uc + tid] = 0.f;
        }
    }
}

// ---------------- kernel 1: gather unique K rows -> bf16 + weighted partial ksum
// grid = NB*UPM*8/256 = 2016 blocks; block covers 32 rows of one batch
__global__ __launch_bounds__(256) void k_gather(const float* __restrict__ K) {
    __shared__ float red[32][65];
    const int tid = threadIdx.x;
    const int t = blockIdx.x * 256 + tid;
    const int chunk = t & 7;              // 8 dims each
    const int rest = t >> 3;
    const int j = rest % UPM;
    const int b = rest / UPM;
    const int r = tid >> 3;               // row within block
    const int upad = g_upad;
    const int uc = g_ucount;

    float v[8];
#pragma unroll
    for (int d = 0; d < 8; ++d) v[d] = 0.f;
    float w = 0.f;

    if (j < upad) {
        int src = g_uniq[j];
        const float4* p = (const float4*)(K + ((size_t)b * LK + src) * DH + chunk * 8);
        float4 v0 = p[0], v1 = p[1];
        v[0] = v0.x; v[1] = v0.y; v[2] = v0.z; v[3] = v0.w;
        v[4] = v1.x; v[5] = v1.y; v[6] = v1.z; v[7] = v1.w;
        uint4 wq = make_uint4(packbf(v0.x, v0.y), packbf(v0.z, v0.w),
                              packbf(v1.x, v1.y), packbf(v1.z, v1.w));
        *(uint4*)(g_KsampH + ((size_t)(b * UPM) + j) * DH + chunk * 8) = wq;
        if (j < uc) w = g_ucnt[j];
    }
#pragma unroll
    for (int d = 0; d < 8; ++d) red[r][chunk * 8 + d] = w * v[d];
    __syncthreads();
    if (tid < 64) {
        float s = 0.f;
#pragma unroll 8
        for (int rr = 0; rr < 32; ++rr) s += red[rr][tid];
        g_Kpart[((size_t)b * GPB + (blockIdx.x % GPB)) * DH + tid] = s;
    }
}

// ---------------- kernel 2: reduce ksum partials ----------------
__global__ void k_ksum2() {
    int b = blockIdx.x;
    int d = threadIdx.x;
    float s = 0.f;
    for (int i = 0; i < GPB; ++i) s += g_Kpart[((size_t)b * GPB + i) * DH + d];
    g_Ksum[b * DH + d] = s;
}

// ---------------- kernel 3: approx M via bf16 mma, m128 x KT2=128 tiles ----
__global__ __launch_bounds__(256, 2) void k_M_mma(const float* __restrict__ q) {
    __shared__ __nv_bfloat16 Bs[2][128 * 72];
    __shared__ float rowmaxS[4][128];
    __shared__ float ksumS[64];

    const int tid  = threadIdx.x;
    const int wid  = tid >> 5;
    const int lane = tid & 31;
    const int gid  = lane >> 2;
    const int tig  = lane & 3;
    const int b    = blockIdx.y;
    const int m0   = blockIdx.x * 128;
    const int mhalf = (wid & 1) * 64;
    const int nquad = wid >> 1;           // 0..3 -> keys [32*nquad, +32)

    if (tid < 64) ksumS[tid] = g_Ksum[b * DH + tid];

    // A fragments for 4 m-blocks (persist whole kernel)
    uint32_t a[4][4][4];
#pragma unroll
    for (int mb = 0; mb < 4; ++mb) {
        int r0 = m0 + mhalf + mb * 16 + gid;
        int r1 = r0 + 8;
        const float* q0 = q + ((size_t)(b * LQ) + r0) * DH;
        const float* q1 = q + ((size_t)(b * LQ) + r1) * DH;
#pragma unroll
        for (int kk = 0; kk < 4; ++kk) {
            int c = kk * 16 + 2 * tig;
            float2 x0 = *(const float2*)(q0 + c);
            float2 x1 = *(const float2*)(q1 + c);
            float2 x2 = *(const float2*)(q0 + c + 8);
            float2 x3 = *(const float2*)(q1 + c + 8);
            a[mb][kk][0] = packbf(x0.x, x0.y);
            a[mb][kk][1] = packbf(x1.x, x1.y);
            a[mb][kk][2] = packbf(x2.x, x2.y);
            a[mb][kk][3] = packbf(x3.x, x3.y);
        }
    }

    const int niter = g_upad >> 7;        // tiles of 128 keys
    uint32_t sBase = (uint32_t)__cvta_generic_to_shared(&Bs[0][0]);

    {   // prologue: tile 0 (1024 cp16 = 16 KB)
#pragma unroll
        for (int it2 = 0; it2 < 2; ++it2) {
            int unit = tid + 256 * it2;
            int row = unit >> 2, seg = unit & 3;
            const __nv_bfloat16* src = g_KsampH + ((size_t)(b * UPM) + row) * DH + seg * 16;
            uint32_t dst = sBase + row * 144 + seg * 32;
            cp16(dst, src);
            cp16(dst + 16, src + 8);
        }
    }
    asm volatile("cp.async.commit_group;\n");

    float rmax[4][2];
#pragma unroll
    for (int mb = 0; mb < 4; ++mb) { rmax[mb][0] = -INFINITY; rmax[mb][1] = -INFINITY; }

    for (int t = 0; t < niter; ++t) {
        asm volatile("cp.async.wait_group 0;\n");
        __syncthreads();
        if (t + 1 < niter) {
#pragma unroll
            for (int it2 = 0; it2 < 2; ++it2) {
                int unit = tid + 256 * it2;
                int row = unit >> 2, seg = unit & 3;
                const __nv_bfloat16* src =
                    g_KsampH + ((size_t)(b * UPM) + (t + 1) * 128 + row) * DH + seg * 16;
                uint32_t dst = sBase + ((t + 1) & 1) * 18432 + row * 144 + seg * 32;
                cp16(dst, src);
                cp16(dst + 16, src + 8);
            }
        }
        asm volatile("cp.async.commit_group;\n");

        uint32_t bufBase = sBase + (t & 1) * 18432;
#pragma unroll
        for (int nc = 0; nc < 4; ++nc) {
            int row = nquad * 32 + nc * 8 + (lane & 7);
            uint32_t addr0 = bufBase + (uint32_t)(row * 144 + (lane >> 3) * 16);
            uint32_t bk[4], bk2[4];
            ldsm_x4(bk,  addr0);          // k 0..31
            ldsm_x4(bk2, addr0 + 64);     // k 32..63
#pragma unroll
            for (int mb = 0; mb < 4; ++mb) {
                float acc[4] = {0.f, 0.f, 0.f, 0.f};
                mma_bf16(acc, a[mb][0], bk[0],  bk[1]);
                mma_bf16(acc, a[mb][1], bk[2],  bk[3]);
                mma_bf16(acc, a[mb][2], bk2[0], bk2[1]);
                mma_bf16(acc, a[mb][3], bk2[2], bk2[3]);
                rmax[mb][0] = fmaxf(rmax[mb][0], fmaxf(acc[0], acc[1]));
                rmax[mb][1] = fmaxf(rmax[mb][1], fmaxf(acc[2], acc[3]));
            }
        }
    }

#pragma unroll
    for (int mb = 0; mb < 4; ++mb)
#pragma unroll
        for (int h = 0; h < 2; ++h) {
            rmax[mb][h] = fmaxf(rmax[mb][h], __shfl_xor_sync(0xffffffffu, rmax[mb][h], 1));
            rmax[mb][h] = fmaxf(rmax[mb][h], __shfl_xor_sync(0xffffffffu, rmax[mb][h], 2));
        }
    if (tig == 0) {
#pragma unroll
        for (int mb = 0; mb < 4; ++mb) {
            rowmaxS[nquad][mhalf + mb * 16 + gid]     = rmax[mb][0];
            rowmaxS[nquad][mhalf + mb * 16 + gid + 8] = rmax[mb][1];
        }
    }
    __syncthreads();

    if (tid < 128) {
        int m = m0 + tid;
        float mx = fmaxf(fmaxf(rowmaxS[0][tid], rowmaxS[1][tid]),
                         fmaxf(rowmaxS[2][tid], rowmaxS[3][tid]));
        const float* qp = q + ((size_t)(b * LQ) + m) * DH;
        float d0 = 0.f, d1 = 0.f, d2 = 0.f, d3 = 0.f;
#pragma unroll
        for (int d = 0; d < 64; d += 4) {
            d0 += qp[d]     * ksumS[d];
            d1 += qp[d + 1] * ksumS[d + 1];
            d2 += qp[d + 2] * ksumS[d + 2];
            d3 += qp[d + 3] * ksumS[d + 3];
        }
        g_M[b * LQ + m] = mx - ((d0 + d1) + (d2 + d3)) * (1.0f / (float)LKS);
    }
}

// ---------------- kernel 4: histogram threshold + candidate collect --------
__global__ __launch_bounds__(512) void k_thresh() {
    const int b = blockIdx.x;
    const int tid = threadIdx.x;
    __shared__ float sv[LQ];
    __shared__ int hist[512];
    __shared__ float wmn[16], wmx[16];
    __shared__ float s_mn, s_range, s_thresh;
    __shared__ int s_cnt;

    float mn = INFINITY, mx = -INFINITY;
    for (int j = tid; j < LQ; j += 512) {
        float v = g_M[b * LQ + j];
        sv[j] = v;
        mn = fminf(mn, v);
        mx = fmaxf(mx, v);
    }
#pragma unroll
    for (int off = 16; off > 0; off >>= 1) {
        mn = fminf(mn, __shfl_xor_sync(0xffffffffu, mn, off));
        mx = fmaxf(mx, __shfl_xor_sync(0xffffffffu, mx, off));
    }
    if ((tid & 31) == 0) { wmn[tid >> 5] = mn; wmx[tid >> 5] = mx; }
    if (tid < 512) hist[tid] = 0;
    if (tid == 0) s_cnt = 0;
    __syncthreads();
    if (tid == 0) {
        float a = INFINITY, z = -INFINITY;
        for (int g = 0; g < 16; ++g) { a = fminf(a, wmn[g]); z = fmaxf(z, wmx[g]); }
        s_mn = a;
        s_range = z - a + 1e-6f;
    }
    __syncthreads();
    const float scale = 511.0f / s_range;
    for (int j = tid; j < LQ; j += 512) {
        int bin = (int)((sv[j] - s_mn) * scale);
        bin = max(0, min(511, bin));
        atomicAdd(&hist[bin], 1);
    }
    __syncthreads();
    if (tid == 0) {
        int cum = 0, bsel = 511;
        for (int i = 0; i < 512; ++i) {
            cum += hist[i];
            if (cum >= NU) { bsel = i; break; }
        }
        s_thresh = s_mn + (float)(bsel + 1) * (s_range / 511.0f) + MARGIN;
    }
    __syncthreads();
    const float th = s_thresh;
    for (int j = tid; j < LQ; j += 512) {
        if (sv[j] <= th) {
            int p = atomicAdd(&s_cnt, 1);
            if (p < CANDMAX) g_cand[b * CANDMAX + p] = j;
        }
    }
    __syncthreads();
    if (tid == 0) g_ccount[b] = min(s_cnt, CANDMAX);
}

// ---------------- kernel 5: exact fp32 max (split-K over unique keys) ------
__global__ __launch_bounds__(256) void k_M_exact(const float* __restrict__ q,
                                                 const float* __restrict__ K) {
    extern __shared__ float sh[];
    float* Kc = sh;
    float* Qc = sh + 253 * 68;

    const int b = blockIdx.y;
    const int sp = blockIdx.x;
    const int tid = threadIdx.x;
    const int wid = tid >> 5;
    const int lane = tid & 31;

    const int uc = g_ucount;
    const int j0 = (sp * uc) / NSPLIT;
    const int j1 = ((sp + 1) * uc) / NSPLIT;
    const int nr = j1 - j0;

    for (int i = tid; i < nr * 16; i += 256) {
        int r = i >> 4, d4 = i & 15;
        int src = g_uniq[j0 + r];
        *(float4*)&Kc[r * 68 + 4 * d4] =
            *(const float4*)(K + ((size_t)b * LK + src) * DH + 4 * d4);
    }
    const int cnt = g_ccount[b];

    for (int cg = 0; cg < cnt; cg += 128) {
        int ncg = min(128, cnt - cg);
        __syncthreads();
        for (int i = tid; i < ncg * 16; i += 256) {
            int c = i >> 4, d4 = i & 15;
            int qi = g_cand[b * CANDMAX + cg + c];
            *(float4*)&Qc[c * 68 + 4 * d4] =
                *(const float4*)(q + ((size_t)(b * LQ) + qi) * DH + 4 * d4);
        }
        __syncthreads();
        for (int c = wid; c < ncg; c += 8) {
            const float* qr = &Qc[c * 68];
            float mx = -INFINITY;
            for (int r = lane; r < nr; r += 32) {
                const float* kr = &Kc[r * 68];
                float a0 = 0.f, a1 = 0.f, a2 = 0.f, a3 = 0.f;
#pragma unroll
                for (int d4 = 0; d4 < 16; ++d4) {
                    float4 kv = *(const float4*)&kr[4 * d4];
                    float4 qv = *(const float4*)&qr[4 * d4];
                    a0 += qv.x * kv.x;
                    a1 += qv.y * kv.y;
                    a2 += qv.z * kv.z;
                    a3 += qv.w * kv.w;
                }
                mx = fmaxf(mx, (a0 + a1) + (a2 + a3));
            }
#pragma unroll
            for (int off = 16; off > 0; off >>= 1)
                mx = fmaxf(mx, __shfl_xor_sync(0xffffffffu, mx, off));
            if (lane == 0)
                g_candP[((size_t)(b * CANDMAX) + cg + c) * NSPLIT + sp] = mx;
        }
    }
}

// ---------------- kernel 6: finalize exact M + top-45 selection ------------
__global__ __launch_bounds__(256) void k_select(const float* __restrict__ q) {
    const int b = blockIdx.x;
    const int tid = threadIdx.x;
    __shared__ float cv[CANDMAX];
    __shared__ int   ci[CANDMAX];
    __shared__ float ksumS[64];
    const int cnt = g_ccount[b];

    if (tid < 64) ksumS[tid] = g_Ksum[b * DH + tid];
    __syncthreads();

    for (int c = tid; c < CANDMAX; c += 256) {
        if (c < cnt) {
            float mx = -INFINITY;
#pragma unroll
            for (int s = 0; s < NSPLIT; ++s)
                mx = fmaxf(mx, g_candP[((size_t)(b * CANDMAX) + c) * NSPLIT + s]);
            int qi = g_cand[b * CANDMAX + c];
            const float* qp = q + ((size_t)(b * LQ) + qi) * DH;
            float dot = 0.f;
            for (int d = 0; d < 64; ++d) dot += qp[d] * ksumS[d];
            cv[c] = mx - dot * (1.0f / (float)LKS);
            ci[c] = qi;
        } else {
            cv[c] = INFINITY;
            ci[c] = 1 << 30;
        }
    }
    __syncthreads();

    if (tid < 32) {
        for (int it = 0; it < NU; ++it) {
            float best = INFINITY; int bidx = 1 << 30; int bslot = 0;
            for (int j = tid; j < CANDMAX; j += 32) {
                float v = cv[j]; int qi2 = ci[j];
                if (v < best || (v == best && qi2 < bidx)) { best = v; bidx = qi2; bslot = j; }
            }
#pragma unroll
            for (int off = 16; off > 0; off >>= 1) {
                float v2 = __shfl_xor_sync(0xffffffffu, best, off);
                int   i2 = __shfl_xor_sync(0xffffffffu, bidx, off);
                int   s2 = __shfl_xor_sync(0xffffffffu, bslot, off);
                if (v2 < best || (v2 == best && i2 < bidx)) { best = v2; bidx = i2; bslot = s2; }
            }
            if (tid == 0) { g_top[b * NUP + it] = bidx; cv[bslot] = INFINITY; }
            __syncwarp();
        }
        if (tid < NUP - NU) g_top[b * NUP + NU + tid] = 0;
    }
}

// ---------------- kernel 7: bf16x2-Karatsuba mma attention (single wave) ---
__global__ __launch_bounds__(256, 3) void k_attn(const float* __restrict__ q,
                                                 const float* __restrict__ K,
                                                 const float* __restrict__ V,
                                                 float* __restrict__ out_s) {
    extern __shared__ char smc[];
    __nv_bfloat16* Qh = (__nv_bfloat16*)smc;            // 48*72
    __nv_bfloat16* Ql = Qh + 48 * 72;
    __nv_bfloat16* Kh = Ql + 48 * 72;                   // 64*72
    __nv_bfloat16* Kl = Kh + 64 * 72;
    __nv_bfloat16* Vh = Kl + 64 * 72;                   // 64*72 rows=key
    __nv_bfloat16* Vl = Vh + 64 * 72;
    char* Ub = (char*)(Vl + 64 * 72);                   // union, 13824 B
    float* SP = (float*)Ub;                             // [48][68] f32
    __nv_bfloat16* Ph = (__nv_bfloat16*)Ub;             // [48][72]
    __nv_bfloat16* Pl = Ph + 48 * 72;
    float* fS = (float*)(Ub + 13824);                   // [48]

    const uint32_t sQh = (uint32_t)__cvta_generic_to_shared(Qh);
    const uint32_t sQl = (uint32_t)__cvta_generic_to_shared(Ql);
    const uint32_t sKh = (uint32_t)__cvta_generic_to_shared(Kh);
    const uint32_t sKl = (uint32_t)__cvta_generic_to_shared(Kl);
    const uint32_t sVh = (uint32_t)__cvta_generic_to_shared(Vh);
    const uint32_t sVl = (uint32_t)__cvta_generic_to_shared(Vl);
    const uint32_t sPh = (uint32_t)__cvta_generic_to_shared(Ph);
    const uint32_t sPl = (uint32_t)__cvta_generic_to_shared(Pl);

    const int tid = threadIdx.x;
    const int ty = tid >> 5;
    const int tx = tid & 31;
    const int gid = tx >> 2;
    const int tig = tx & 3;
    const int b = blockIdx.y;
    const int chunk = blockIdx.x;
    const int t0 = (chunk * NTILES) / NCHUNK;
    const int t1 = ((chunk + 1) * NTILES) / NCHUNK;

#pragma unroll
    for (int i = 0; i < 3; ++i) {
        int fidx = tid + 256 * i;
        int u    = fidx >> 4;
        int d4   = fidx & 15;
        float4 v = make_float4(0.f, 0.f, 0.f, 0.f);
        if (u < NU) {
            int qi = g_top[b * NUP + u];
            v = *(const float4*)(q + ((size_t)(b * LQ + qi)) * DH + 4 * d4);
        }
        uint32_t h0, l0, h1, l1;
        bfsplit2(v.x, v.y, h0, l0);
        bfsplit2(v.z, v.w, h1, l1);
        *(uint32_t*)(Qh + u * 72 + 4 * d4)     = h0;
        *(uint32_t*)(Qh + u * 72 + 4 * d4 + 2) = h1;
        *(uint32_t*)(Ql + u * 72 + 4 * d4)     = l0;
        *(uint32_t*)(Ql + u * 72 + 4 * d4 + 2) = l1;
    }

    float mrun[6], lrun[6];
#pragma unroll
    for (int i = 0; i < 6; ++i) { mrun[i] = -INFINITY; lrun[i] = 0.f; }
    float oc[3][4];
#pragma unroll
    for (int mt = 0; mt < 3; ++mt)
#pragma unroll
        for (int i = 0; i < 4; ++i) oc[mt][i] = 0.f;

    for (int kt = t0; kt < t1; ++kt) {
        const int kg0 = kt * KT;
        __syncthreads();
#pragma unroll
        for (int i = 0; i < 4; ++i) {
            int fidx = tid + 256 * i;
            int k    = fidx >> 4;
            int d4   = fidx & 15;
            float4 kv = *(const float4*)(K + ((size_t)(b * LK + kg0 + k)) * DH + 4 * d4);
            uint32_t h0, l0, h1, l1;
            bfsplit2(kv.x, kv.y, h0, l0);
            bfsplit2(kv.z, kv.w, h1, l1);
            *(uint32_t*)(Kh + k * 72 + 4 * d4)     = h0;
            *(uint32_t*)(Kh + k * 72 + 4 * d4 + 2) = h1;
            *(uint32_t*)(Kl + k * 72 + 4 * d4)     = l0;
            *(uint32_t*)(Kl + k * 72 + 4 * d4 + 2) = l1;
            float4 vv = *(const float4*)(V + ((size_t)(b * LK + kg0 + k)) * DH + 4 * d4);
            bfsplit2(vv.x, vv.y, h0, l0);
            bfsplit2(vv.z, vv.w, h1, l1);
            *(uint32_t*)(Vh + k * 72 + 4 * d4)     = h0;
            *(uint32_t*)(Vh + k * 72 + 4 * d4 + 2) = h1;
            *(uint32_t*)(Vl + k * 72 + 4 * d4)     = l0;
            *(uint32_t*)(Vl + k * 72 + 4 * d4 + 2) = l1;
        }
        __syncthreads();

        {
            uint32_t bh[8], bl[8];
            uint32_t kaddr = sKh + (uint32_t)((8 * ty + (tx & 7)) * 144 + (tx >> 3) * 16);
            ldsm_x4(bh,     kaddr);
            ldsm_x4(bh + 4, kaddr + 64);
            kaddr = sKl + (uint32_t)((8 * ty + (tx & 7)) * 144 + (tx >> 3) * 16);
            ldsm_x4(bl,     kaddr);
            ldsm_x4(bl + 4, kaddr + 64);

#pragma unroll
            for (int mt = 0; mt < 3; ++mt) {
                float accS[4] = {0.f, 0.f, 0.f, 0.f};
                uint32_t arow = (uint32_t)((mt * 16 + (tx & 15)) * 144 + (tx >> 4) * 16);
#pragma unroll
                for (int ks = 0; ks < 4; ++ks) {
                    uint32_t ah[4], al[4];
                    ldsm_x4(ah, sQh + arow + ks * 32);
                    ldsm_x4(al, sQl + arow + ks * 32);
                    mma_bf16(accS, ah, bh[2 * ks], bh[2 * ks + 1]);
                    mma_bf16(accS, ah, bl[2 * ks], bl[2 * ks + 1]);
                    mma_bf16(accS, al, bh[2 * ks], bh[2 * ks + 1]);
                }
                int r0 = mt * 16 + gid;
                *(float2*)&SP[r0 * 68 + 8 * ty + 2 * tig] =
                    make_float2(accS[0] * 0.125f, accS[1] * 0.125f);
                *(float2*)&SP[(r0 + 8) * 68 + 8 * ty + 2 * tig] =
                    make_float2(accS[2] * 0.125f, accS[3] * 0.125f);
            }
        }
        __syncthreads();

        float pr[6][2], fnew[6];
#pragma unroll
        for (int i = 0; i < 6; ++i) {
            int u = 6 * ty + i;
            float2 sv = *(const float2*)&SP[u * 68 + 2 * tx];
            float mx = fmaxf(sv.x, sv.y);
#pragma unroll
            for (int off = 16; off > 0; off >>= 1)
                mx = fmaxf(mx, __shfl_xor_sync(0xffffffffu, mx, off));
            float mn = fmaxf(mrun[i], mx);
            float f  = __expf(mrun[i] - mn);
            float p0 = __expf(sv.x - mn);
            float p1 = __expf(sv.y - mn);
            float ps = p0 + p1;
#pragma unroll
            for (int off = 16; off > 0; off >>= 1)
                ps += __shfl_xor_sync(0xffffffffu, ps, off);
            lrun[i] = lrun[i] * f + ps;
            mrun[i] = mn;
            fnew[i] = f;
            pr[i][0] = p0; pr[i][1] = p1;
            if (u < NU)
                *(float2*)(out_s + ((size_t)(b * NU + u)) * LK + kg0 + 2 * tx) = sv;
        }
        __syncthreads();

#pragma unroll
        for (int i = 0; i < 6; ++i) {
            int u = 6 * ty + i;
            uint32_t h, l;
            bfsplit2(pr[i][0], pr[i][1], h, l);
            *(uint32_t*)(Ph + u * 72 + 2 * tx) = h;
            *(uint32_t*)(Pl + u * 72 + 2 * tx) = l;
            if (tx == 0) fS[u] = fnew[i];
        }
        __syncthreads();

        {
            uint32_t bh[8], bl[8];
            uint32_t vaddr = sVh + (uint32_t)(tx * 144 + 16 * ty);
            ldsm_x4_t(bh,     vaddr);
            ldsm_x4_t(bh + 4, vaddr + 32 * 144);
            vaddr = sVl + (uint32_t)(tx * 144 + 16 * ty);
            ldsm_x4_t(bl,     vaddr);
            ldsm_x4_t(bl + 4, vaddr + 32 * 144);

#pragma unroll
            for (int mt = 0; mt < 3; ++mt) {
                float f0 = fS[mt * 16 + gid];
                float f1 = fS[mt * 16 + gid + 8];
                oc[mt][0] *= f0; oc[mt][1] *= f0;
                oc[mt][2] *= f1; oc[mt][3] *= f1;
                uint32_t arow = (uint32_t)((mt * 16 + (tx & 15)) * 144 + (tx >> 4) * 16);
#pragma unroll
                for (int ks = 0; ks < 4; ++ks) {
                    uint32_t ph[4], pl2[4];
                    ldsm_x4(ph,  sPh + arow + ks * 32);
                    ldsm_x4(pl2, sPl + arow + ks * 32);
                    mma_bf16(oc[mt], ph,  bh[2 * ks], bh[2 * ks + 1]);
                    mma_bf16(oc[mt], ph,  bl[2 * ks], bl[2 * ks + 1]);
                    mma_bf16(oc[mt], pl2, bh[2 * ks], bh[2 * ks + 1]);
                }
            }
        }
    }

    if (tx == 0) {
#pragma unroll
        for (int i = 0; i < 6; ++i) {
            int u = 6 * ty + i;
            g_pm[(b * NCHUNK + chunk) * NUP + u] = mrun[i];
            g_pl[(b * NCHUNK + chunk) * NUP + u] = lrun[i];
        }
    }
#pragma unroll
    for (int mt = 0; mt < 3; ++mt) {
        int r0 = mt * 16 + gid;
        *(float2*)&g_pacc[((size_t)(b * NCHUNK + chunk) * NUP + r0) * DH + 8 * ty + 2 * tig] =
            make_float2(oc[mt][0], oc[mt][1]);
        *(float2*)&g_pacc[((size_t)(b * NCHUNK + chunk) * NUP + r0 + 8) * DH + 8 * ty + 2 * tig] =
            make_float2(oc[mt][2], oc[mt][3]);
    }
}

// ---------------- kernel 8: combine split-softmax partials ----------------
__global__ void k_combine(float* __restrict__ out_o) {
    int u = blockIdx.x;
    int b = blockIdx.y;
    int d = threadIdx.x;
    float gm = -INFINITY;
    for (int c = 0; c < NCHUNK; ++c)
        gm = fmaxf(gm, g_pm[(b * NCHUNK + c) * NUP + u]);
    float L = 0.f, a = 0.f;
    for (int c = 0; c < NCHUNK; ++c) {
        float w = __expf(g_pm[(b * NCHUNK + c) * NUP + u] - gm);
        L += g_pl[(b * NCHUNK + c) * NUP + u] * w;
        a += g_pacc[((size_t)(b * NCHUNK + c) * NUP + u) * DH + d] * w;
    }
    out_o[(b * NU + u) * DH + d] = a / L;
}

// ---------------- launch ----------------
extern "C" void kernel_launch(void* const* d_in, const int* in_sizes, int n_in,
                              void* d_out, int out_size) {
    const float* q  = (const float*)d_in[0];
    const float* K  = (const float*)d_in[1];
    const float* V  = (const float*)d_in[2];
    const int* idx  = (const int*)d_in[3];
    float* out_o = (float*)d_out;                  // attn_output [8,45,64]
    float* out_s = out_o + NB * NU * DH;           // attn_scores [8,45,32768]

    (void)in_sizes; (void)n_in; (void)out_size;

    const int smem_attn  = 48 * 72 * 2 * 2 + 64 * 72 * 2 * 2 * 2 + 13824 + 192;  // 64704
    const int smem_exact = (253 * 68 + 128 * 68) * 4;                            // 103632
    cudaFuncSetAttribute(k_attn,    cudaFuncAttributeMaxDynamicSharedMemorySize, smem_attn);
    cudaFuncSetAttribute(k_M_exact, cudaFuncAttributeMaxDynamicSharedMemorySize, smem_exact);

    k_dedup<<<1, 1024>>>(idx);
    k_gather<<<NB * GPB, 256>>>(K);
    k_ksum2<<<NB, 64>>>();
    k_M_mma<<<dim3(LQ / 128, NB), 256>>>(q);
    k_thresh<<<NB, 512>>>();
    k_M_exact<<<dim3(NSPLIT, NB), 256, smem_exact>>>(q, K);
    k_select<<<NB, 256>>>(q);
    k_attn<<<dim3(NCHUNK, NB), 256, smem_attn>>>(q, K, V, out_s);
    k_combine<<<dim3(NU, NB), 64>>>(out_o);
}

// round 14
// speedup vs baseline: 4.4986x; 1.0091x over previous
#include <cuda_runtime.h>
#include <cuda_bf16.h>
#include <math.h>
#include <stdint.h>

#define NB 8
#define LQ 4096
#define LK 32768
#define DH 64
#define LKS 8000
#define UPM 8064            // upper bound for 128-padded unique count
#define GPB 252             // gather blocks per batch = UPM/32
#define NU 45
#define NUP 48
#define NCHUNK 54
#define KT 64
#define NTILES 512          // LK / KT
#define CANDMAX 1024
#define NSPLIT 32
#define KROWS 176           // smem K rows per chunk in k_M_exact
#define MARGIN 1.0f

// ---------------- device scratch ----------------
__device__ __nv_bfloat16 g_KsampH[NB * UPM * DH];
__device__ int   g_uniq[UPM];
__device__ float g_ucnt[UPM];
__device__ int   g_ucount;
__device__ int   g_upad;
__device__ float g_Kpart[NB * GPB * DH];
__device__ float g_Ksum[NB * DH];
__device__ float g_M[NB * LQ];
__device__ int   g_top[NB * NUP];
__device__ int   g_cand[NB * CANDMAX];
__device__ float g_candP[NB * CANDMAX * NSPLIT];
__device__ int   g_ccount[NB];
__device__ float g_pm[NB * NCHUNK * NUP];
__device__ float g_pl[NB * NCHUNK * NUP];
__device__ float g_pacc[NB * NCHUNK * NUP * DH];

// ---------------- helpers ----------------
__device__ __forceinline__ void mma_bf16(float c[4], const uint32_t a[4],
                                         uint32_t b0, uint32_t b1) {
    asm volatile(
        "mma.sync.aligned.m16n8k16.row.col.f32.bf16.bf16.f32 "
        "{%0,%1,%2,%3}, {%4,%5,%6,%7}, {%8,%9}, {%0,%1,%2,%3};"
        : "+f"(c[0]), "+f"(c[1]), "+f"(c[2]), "+f"(c[3])
        : "r"(a[0]), "r"(a[1]), "r"(a[2]), "r"(a[3]), "r"(b0), "r"(b1));
}
__device__ __forceinline__ uint32_t packbf(float x, float y) {
    __nv_bfloat162 h = __floats2bfloat162_rn(x, y);
    return *(uint32_t*)&h;
}
// fast split: 2 packed cvts + bit-unpack hi + 2 subs (identical rounding to scalar path)
__device__ __forceinline__ void bfsplit2(float x, float y, uint32_t& h, uint32_t& l) {
    uint32_t hh;
    asm("cvt.rn.bf16x2.f32 %0, %1, %2;" : "=r"(hh) : "f"(y), "f"(x));
    float hx = __uint_as_float(hh << 16);
    float hy = __uint_as_float(hh & 0xffff0000u);
    float rx = x - hx;
    float ry = y - hy;
    asm("cvt.rn.bf16x2.f32 %0, %1, %2;" : "=r"(l) : "f"(ry), "f"(rx));
    h = hh;
}
__device__ __forceinline__ void cp16(uint32_t dst, const void* src) {
    asm volatile("cp.async.ca.shared.global [%0], [%1], 16;\n" :: "r"(dst), "l"(src));
}
__device__ __forceinline__ void ldsm_x4(uint32_t r[4], uint32_t addr) {
    asm volatile("ldmatrix.sync.aligned.m8n8.x4.shared.b16 {%0,%1,%2,%3}, [%4];"
                 : "=r"(r[0]), "=r"(r[1]), "=r"(r[2]), "=r"(r[3]) : "r"(addr));
}
__device__ __forceinline__ void ldsm_x4_t(uint32_t r[4], uint32_t addr) {
    asm volatile("ldmatrix.sync.aligned.m8n8.x4.trans.shared.b16 {%0,%1,%2,%3}, [%4];"
                 : "=r"(r[0]), "=r"(r[1]), "=r"(r[2]), "=r"(r[3]) : "r"(addr));
}

// ---------------- kernel 0: dedupe sampled indices + counts ----------------
__global__ void k_dedup(const int* __restrict__ idx) {
    __shared__ unsigned bm[250];
    __shared__ int wo[251];
    __shared__ int hist[LKS];
    int tid = threadIdx.x;
    for (int i = tid; i < 250; i += 1024) bm[i] = 0u;
    for (int i = tid; i < LKS; i += 1024) hist[i] = 0;
    __syncthreads();
    for (int i = tid; i < LKS; i += 1024) {
        int v = idx[i];
        atomicOr(&bm[v >> 5], 1u << (v & 31));
        atomicAdd(&hist[v], 1);
    }
    __syncthreads();
    if (tid == 0) {
        int acc = 0;
        for (int w = 0; w < 250; ++w) { wo[w] = acc; acc += __popc(bm[w]); }
        wo[250] = acc;
        g_ucount = acc;
        g_upad = (acc + 127) & ~127;
    }
    __syncthreads();
    for (int w = tid; w < 250; w += 1024) {
        unsigned m = bm[w];
        int o = wo[w];
        while (m) {
            int bbit = __ffs(m) - 1;
            int v = w * 32 + bbit;
            g_uniq[o] = v;
            g_ucnt[o] = (float)hist[v];
            ++o;
            m &= m - 1;
        }
    }
    __syncthreads();
    if (tid < 128) {
        int uc = wo[250];
        int up = (uc + 127) & ~127;
        if (uc + tid < up) {
            g_uniq[uc + tid] = g_uniq[0];
            g_ucnt[uc + tid] = 0.f;
        }
    }
}

// ---------------- kernel 1: gather unique K rows -> bf16 + weighted partial ksum
__global__ __launch_bounds__(256) void k_gather(const float* __restrict__ K) {
    __shared__ float red[32][65];
    const int tid = threadIdx.x;
    const int t = blockIdx.x * 256 + tid;
    const int chunk = t & 7;
    const int rest = t >> 3;
    const int j = rest % UPM;
    const int b = rest / UPM;
    const int r = tid >> 3;
    const int upad = g_upad;
    const int uc = g_ucount;

    float v[8];
#pragma unroll
    for (int d = 0; d < 8; ++d) v[d] = 0.f;
    float w = 0.f;

    if (j < upad) {
        int src = g_uniq[j];
        const float4* p = (const float4*)(K + ((size_t)b * LK + src) * DH + chunk * 8);
        float4 v0 = p[0], v1 = p[1];
        v[0] = v0.x; v[1] = v0.y; v[2] = v0.z; v[3] = v0.w;
        v[4] = v1.x; v[5] = v1.y; v[6] = v1.z; v[7] = v1.w;
        uint4 wq = make_uint4(packbf(v0.x, v0.y), packbf(v0.z, v0.w),
                              packbf(v1.x, v1.y), packbf(v1.z, v1.w));
        *(uint4*)(g_KsampH + ((size_t)(b * UPM) + j) * DH + chunk * 8) = wq;
        if (j < uc) w = g_ucnt[j];
    }
#pragma unroll
    for (int d = 0; d < 8; ++d) red[r][chunk * 8 + d] = w * v[d];
    __syncthreads();
    if (tid < 64) {
        float s = 0.f;
#pragma unroll 8
        for (int rr = 0; rr < 32; ++rr) s += red[rr][tid];
        g_Kpart[((size_t)b * GPB + (blockIdx.x % GPB)) * DH + tid] = s;
    }
}

// ---------------- kernel 2: reduce ksum partials ----------------
__global__ void k_ksum2() {
    int b = blockIdx.x;
    int d = threadIdx.x;
    float s = 0.f;
    for (int i = 0; i < GPB; ++i) s += g_Kpart[((size_t)b * GPB + i) * DH + d];
    g_Ksum[b * DH + d] = s;
}

// ---------------- kernel 3: approx M via bf16 mma, m128 x KT2=128 tiles ----
__global__ __launch_bounds__(256, 2) void k_M_mma(const float* __restrict__ q) {
    __shared__ __nv_bfloat16 Bs[2][128 * 72];
    __shared__ float rowmaxS[4][128];
    __shared__ float ksumS[64];

    const int tid  = threadIdx.x;
    const int wid  = tid >> 5;
    const int lane = tid & 31;
    const int gid  = lane >> 2;
    const int tig  = lane & 3;
    const int b    = blockIdx.y;
    const int m0   = blockIdx.x * 128;
    const int mhalf = (wid & 1) * 64;
    const int nquad = wid >> 1;

    if (tid < 64) ksumS[tid] = g_Ksum[b * DH + tid];

    uint32_t a[4][4][4];
#pragma unroll
    for (int mb = 0; mb < 4; ++mb) {
        int r0 = m0 + mhalf + mb * 16 + gid;
        int r1 = r0 + 8;
        const float* q0 = q + ((size_t)(b * LQ) + r0) * DH;
        const float* q1 = q + ((size_t)(b * LQ) + r1) * DH;
#pragma unroll
        for (int kk = 0; kk < 4; ++kk) {
            int c = kk * 16 + 2 * tig;
            float2 x0 = *(const float2*)(q0 + c);
            float2 x1 = *(const float2*)(q1 + c);
            float2 x2 = *(const float2*)(q0 + c + 8);
            float2 x3 = *(const float2*)(q1 + c + 8);
            a[mb][kk][0] = packbf(x0.x, x0.y);
            a[mb][kk][1] = packbf(x1.x, x1.y);
            a[mb][kk][2] = packbf(x2.x, x2.y);
            a[mb][kk][3] = packbf(x3.x, x3.y);
        }
    }

    const int niter = g_upad >> 7;
    uint32_t sBase = (uint32_t)__cvta_generic_to_shared(&Bs[0][0]);

    // per-warp ldsm row offsets, hoisted
    uint32_t rowoff[4];
#pragma unroll
    for (int nc = 0; nc < 4; ++nc) {
        int row = nquad * 32 + nc * 8 + (lane & 7);
        rowoff[nc] = (uint32_t)(row * 144 + (lane >> 3) * 16);
    }

    {   // prologue: tile 0
#pragma unroll
        for (int it2 = 0; it2 < 2; ++it2) {
            int unit = tid + 256 * it2;
            int row = unit >> 2, seg = unit & 3;
            const __nv_bfloat16* src = g_KsampH + ((size_t)(b * UPM) + row) * DH + seg * 16;
            uint32_t dst = sBase + row * 144 + seg * 32;
            cp16(dst, src);
            cp16(dst + 16, src + 8);
        }
    }
    asm volatile("cp.async.commit_group;\n");

    float rmax[4][2];
#pragma unroll
    for (int mb = 0; mb < 4; ++mb) { rmax[mb][0] = -INFINITY; rmax[mb][1] = -INFINITY; }

    for (int t = 0; t < niter; ++t) {
        asm volatile("cp.async.wait_group 0;\n");
        __syncthreads();
        if (t + 1 < niter) {
#pragma unroll
            for (int it2 = 0; it2 < 2; ++it2) {
                int unit = tid + 256 * it2;
                int row = unit >> 2, seg = unit & 3;
                const __nv_bfloat16* src =
                    g_KsampH + ((size_t)(b * UPM) + (t + 1) * 128 + row) * DH + seg * 16;
                uint32_t dst = sBase + ((t + 1) & 1) * 18432 + row * 144 + seg * 32;
                cp16(dst, src);
                cp16(dst + 16, src + 8);
            }
        }
        asm volatile("cp.async.commit_group;\n");

        uint32_t bufBase = sBase + (t & 1) * 18432;
#pragma unroll
        for (int nc = 0; nc < 4; ++nc) {
            uint32_t addr0 = bufBase + rowoff[nc];
            uint32_t bk[4], bk2[4];
            ldsm_x4(bk,  addr0);
            ldsm_x4(bk2, addr0 + 64);
#pragma unroll
            for (int mb = 0; mb < 4; ++mb) {
                float acc[4] = {0.f, 0.f, 0.f, 0.f};
                mma_bf16(acc, a[mb][0], bk[0],  bk[1]);
                mma_bf16(acc, a[mb][1], bk[2],  bk[3]);
                mma_bf16(acc, a[mb][2], bk2[0], bk2[1]);
                mma_bf16(acc, a[mb][3], bk2[2], bk2[3]);
                rmax[mb][0] = fmaxf(rmax[mb][0], fmaxf(acc[0], acc[1]));
                rmax[mb][1] = fmaxf(rmax[mb][1], fmaxf(acc[2], acc[3]));
            }
        }
    }

#pragma unroll
    for (int mb = 0; mb < 4; ++mb)
#pragma unroll
        for (int h = 0; h < 2; ++h) {
            rmax[mb][h] = fmaxf(rmax[mb][h], __shfl_xor_sync(0xffffffffu, rmax[mb][h], 1));
            rmax[mb][h] = fmaxf(rmax[mb][h], __shfl_xor_sync(0xffffffffu, rmax[mb][h], 2));
        }
    if (tig == 0) {
#pragma unroll
        for (int mb = 0; mb < 4; ++mb) {
            rowmaxS[nquad][mhalf + mb * 16 + gid]     = rmax[mb][0];
            rowmaxS[nquad][mhalf + mb * 16 + gid + 8] = rmax[mb][1];
        }
    }
    __syncthreads();

    if (tid < 128) {
        int m = m0 + tid;
        float mx = fmaxf(fmaxf(rowmaxS[0][tid], rowmaxS[1][tid]),
                         fmaxf(rowmaxS[2][tid], rowmaxS[3][tid]));
        const float* qp = q + ((size_t)(b * LQ) + m) * DH;
        float d0 = 0.f, d1 = 0.f, d2 = 0.f, d3 = 0.f;
#pragma unroll
        for (int d = 0; d < 64; d += 4) {
            d0 += qp[d]     * ksumS[d];
            d1 += qp[d + 1] * ksumS[d + 1];
            d2 += qp[d + 2] * ksumS[d + 2];
            d3 += qp[d + 3] * ksumS[d + 3];
        }
        g_M[b * LQ + m] = mx - ((d0 + d1) + (d2 + d3)) * (1.0f / (float)LKS);
    }
}

// ---------------- kernel 4: histogram threshold + candidate collect --------
__global__ __launch_bounds__(512) void k_thresh() {
    const int b = blockIdx.x;
    const int tid = threadIdx.x;
    __shared__ float sv[LQ];
    __shared__ int hist[512];
    __shared__ float wmn[16], wmx[16];
    __shared__ float s_mn, s_range, s_thresh;
    __shared__ int s_cnt;

    float mn = INFINITY, mx = -INFINITY;
    for (int j = tid; j < LQ; j += 512) {
        float v = g_M[b * LQ + j];
        sv[j] = v;
        mn = fminf(mn, v);
        mx = fmaxf(mx, v);
    }
#pragma unroll
    for (int off = 16; off > 0; off >>= 1) {
        mn = fminf(mn, __shfl_xor_sync(0xffffffffu, mn, off));
        mx = fmaxf(mx, __shfl_xor_sync(0xffffffffu, mx, off));
    }
    if ((tid & 31) == 0) { wmn[tid >> 5] = mn; wmx[tid >> 5] = mx; }
    if (tid < 512) hist[tid] = 0;
    if (tid == 0) s_cnt = 0;
    __syncthreads();
    if (tid == 0) {
        float a = INFINITY, z = -INFINITY;
        for (int g = 0; g < 16; ++g) { a = fminf(a, wmn[g]); z = fmaxf(z, wmx[g]); }
        s_mn = a;
        s_range = z - a + 1e-6f;
    }
    __syncthreads();
    const float scale = 511.0f / s_range;
    for (int j = tid; j < LQ; j += 512) {
        int bin = (int)((sv[j] - s_mn) * scale);
        bin = max(0, min(511, bin));
        atomicAdd(&hist[bin], 1);
    }
    __syncthreads();
    if (tid == 0) {
        int cum = 0, bsel = 511;
        for (int i = 0; i < 512; ++i) {
            cum += hist[i];
            if (cum >= NU) { bsel = i; break; }
        }
        s_thresh = s_mn + (float)(bsel + 1) * (s_range / 511.0f) + MARGIN;
    }
    __syncthreads();
    const float th = s_thresh;
    for (int j = tid; j < LQ; j += 512) {
        if (sv[j] <= th) {
            int p = atomicAdd(&s_cnt, 1);
            if (p < CANDMAX) g_cand[b * CANDMAX + p] = j;
        }
    }
    __syncthreads();
    if (tid == 0) g_ccount[b] = min(s_cnt, CANDMAX);
}

// ---------------- kernel 5: exact fp32 max (split-K over unique keys) ------
// smem sized for KROWS=176 key rows -> 82.7 KB -> 2 blocks/SM
__global__ __launch_bounds__(256) void k_M_exact(const float* __restrict__ q,
                                                 const float* __restrict__ K) {
    extern __shared__ float sh[];
    float* Kc = sh;                       // [KROWS][68]
    float* Qc = sh + KROWS * 68;          // [128][68]

    const int b = blockIdx.y;
    const int sp = blockIdx.x;
    const int tid = threadIdx.x;
    const int wid = tid >> 5;
    const int lane = tid & 31;

    const int uc = g_ucount;
    const int j0 = (sp * uc) / NSPLIT;
    const int j1 = ((sp + 1) * uc) / NSPLIT;
    const int cnt = g_ccount[b];

    // key-chunk loop (single iteration when uc <= NSPLIT*KROWS, i.e. always in practice)
    for (int kc = j0, first = 1; kc < j1; kc += KROWS, first = 0) {
        const int nr = min(KROWS, j1 - kc);
        __syncthreads();
        for (int i = tid; i < nr * 16; i += 256) {
            int r = i >> 4, d4 = i & 15;
            int src = g_uniq[kc + r];
            *(float4*)&Kc[r * 68 + 4 * d4] =
                *(const float4*)(K + ((size_t)b * LK + src) * DH + 4 * d4);
        }

        for (int cg = 0; cg < cnt; cg += 128) {
            int ncg = min(128, cnt - cg);
            __syncthreads();
            for (int i = tid; i < ncg * 16; i += 256) {
                int c = i >> 4, d4 = i & 15;
                int qi = g_cand[b * CANDMAX + cg + c];
                *(float4*)&Qc[c * 68 + 4 * d4] =
                    *(const float4*)(q + ((size_t)(b * LQ) + qi) * DH + 4 * d4);
            }
            __syncthreads();
            for (int c = wid; c < ncg; c += 8) {
                const float* qr = &Qc[c * 68];
                float mx = -INFINITY;
                for (int r = lane; r < nr; r += 32) {
                    const float* kr = &Kc[r * 68];
                    float a0 = 0.f, a1 = 0.f, a2 = 0.f, a3 = 0.f;
#pragma unroll
                    for (int d4 = 0; d4 < 16; ++d4) {
                        float4 kv = *(const float4*)&kr[4 * d4];
                        float4 qv = *(const float4*)&qr[4 * d4];
                        a0 += qv.x * kv.x;
                        a1 += qv.y * kv.y;
                        a2 += qv.z * kv.z;
                        a3 += qv.w * kv.w;
                    }
                    mx = fmaxf(mx, (a0 + a1) + (a2 + a3));
                }
#pragma unroll
                for (int off = 16; off > 0; off >>= 1)
                    mx = fmaxf(mx, __shfl_xor_sync(0xffffffffu, mx, off));
                if (lane == 0) {
                    float* slot = &g_candP[((size_t)(b * CANDMAX) + cg + c) * NSPLIT + sp];
                    *slot = first ? mx : fmaxf(*slot, mx);
                }
            }
        }
    }
}

// ---------------- kernel 6: finalize exact M + top-45 selection ------------
__global__ __launch_bounds__(256) void k_select(const float* __restrict__ q) {
    const int b = blockIdx.x;
    const int tid = threadIdx.x;
    __shared__ float cv[CANDMAX];
    __shared__ int   ci[CANDMAX];
    __shared__ float ksumS[64];
    const int cnt = g_ccount[b];

    if (tid < 64) ksumS[tid] = g_Ksum[b * DH + tid];
    __syncthreads();

    for (int c = tid; c < CANDMAX; c += 256) {
        if (c < cnt) {
            float mx = -INFINITY;
#pragma unroll
            for (int s = 0; s < NSPLIT; ++s)
                mx = fmaxf(mx, g_candP[((size_t)(b * CANDMAX) + c) * NSPLIT + s]);
            int qi = g_cand[b * CANDMAX + c];
            const float* qp = q + ((size_t)(b * LQ) + qi) * DH;
            float dot = 0.f;
            for (int d = 0; d < 64; ++d) dot += qp[d] * ksumS[d];
            cv[c] = mx - dot * (1.0f / (float)LKS);
            ci[c] = qi;
        } else {
            cv[c] = INFINITY;
            ci[c] = 1 << 30;
        }
    }
    __syncthreads();

    if (tid < 32) {
        for (int it = 0; it < NU; ++it) {
            float best = INFINITY; int bidx = 1 << 30; int bslot = 0;
            for (int j = tid; j < CANDMAX; j += 32) {
                float v = cv[j]; int qi2 = ci[j];
                if (v < best || (v == best && qi2 < bidx)) { best = v; bidx = qi2; bslot = j; }
            }
#pragma unroll
            for (int off = 16; off > 0; off >>= 1) {
                float v2 = __shfl_xor_sync(0xffffffffu, best, off);
                int   i2 = __shfl_xor_sync(0xffffffffu, bidx, off);
                int   s2 = __shfl_xor_sync(0xffffffffu, bslot, off);
                if (v2 < best || (v2 == best && i2 < bidx)) { best = v2; bidx = i2; bslot = s2; }
            }
            if (tid == 0) { g_top[b * NUP + it] = bidx; cv[bslot] = INFINITY; }
            __syncwarp();
        }
        if (tid < NUP - NU) g_top[b * NUP + NU + tid] = 0;
    }
}

// ---------------- kernel 7: bf16x2-Karatsuba mma attention (single wave) ---
__global__ __launch_bounds__(256, 3) void k_attn(const float* __restrict__ q,
                                                 const float* __restrict__ K,
                                                 const float* __restrict__ V,
                                                 float* __restrict__ out_s) {
    extern __shared__ char smc[];
    __nv_bfloat16* Qh = (__nv_bfloat16*)smc;            // 48*72
    __nv_bfloat16* Ql = Qh + 48 * 72;
    __nv_bfloat16* Kh = Ql + 48 * 72;                   // 64*72
    __nv_bfloat16* Kl = Kh + 64 * 72;
    __nv_bfloat16* Vh = Kl + 64 * 72;                   // 64*72 rows=key
    __nv_bfloat16* Vl = Vh + 64 * 72;
    char* Ub = (char*)(Vl + 64 * 72);                   // union, 13824 B
    float* SP = (float*)Ub;                             // [48][68] f32
    __nv_bfloat16* Ph = (__nv_bfloat16*)Ub;             // [48][72]
    __nv_bfloat16* Pl = Ph + 48 * 72;
    float* fS = (float*)(Ub + 13824);                   // [48]

    const uint32_t sQh = (uint32_t)__cvta_generic_to_shared(Qh);
    const uint32_t sQl = (uint32_t)__cvta_generic_to_shared(Ql);
    const uint32_t sKh = (uint32_t)__cvta_generic_to_shared(Kh);
    const uint32_t sKl = (uint32_t)__cvta_generic_to_shared(Kl);
    const uint32_t sVh = (uint32_t)__cvta_generic_to_shared(Vh);
    const uint32_t sVl = (uint32_t)__cvta_generic_to_shared(Vl);
    const uint32_t sPh = (uint32_t)__cvta_generic_to_shared(Ph);
    const uint32_t sPl = (uint32_t)__cvta_generic_to_shared(Pl);

    const int tid = threadIdx.x;
    const int ty = tid >> 5;
    const int tx = tid & 31;
    const int gid = tx >> 2;
    const int tig = tx & 3;
    const int b = blockIdx.y;
    const int chunk = blockIdx.x;
    const int t0 = (chunk * NTILES) / NCHUNK;
    const int t1 = ((chunk + 1) * NTILES) / NCHUNK;

#pragma unroll
    for (int i = 0; i < 3; ++i) {
        int fidx = tid + 256 * i;
        int u    = fidx >> 4;
        int d4   = fidx & 15;
        float4 v = make_float4(0.f, 0.f, 0.f, 0.f);
        if (u < NU) {
            int qi = g_top[b * NUP + u];
            v = *(const float4*)(q + ((size_t)(b * LQ + qi)) * DH + 4 * d4);
        }
        uint32_t h0, l0, h1, l1;
        bfsplit2(v.x, v.y, h0, l0);
        bfsplit2(v.z, v.w, h1, l1);
        *(uint32_t*)(Qh + u * 72 + 4 * d4)     = h0;
        *(uint32_t*)(Qh + u * 72 + 4 * d4 + 2) = h1;
        *(uint32_t*)(Ql + u * 72 + 4 * d4)     = l0;
        *(uint32_t*)(Ql + u * 72 + 4 * d4 + 2) = l1;
    }

    float mrun[6], lrun[6];
#pragma unroll
    for (int i = 0; i < 6; ++i) { mrun[i] = -INFINITY; lrun[i] = 0.f; }
    float oc[3][4];
#pragma unroll
    for (int mt = 0; mt < 3; ++mt)
#pragma unroll
        for (int i = 0; i < 4; ++i) oc[mt][i] = 0.f;

    for (int kt = t0; kt < t1; ++kt) {
        const int kg0 = kt * KT;
        __syncthreads();
#pragma unroll
        for (int i = 0; i < 4; ++i) {
            int fidx = tid + 256 * i;
            int k    = fidx >> 4;
            int d4   = fidx & 15;
            float4 kv = *(const float4*)(K + ((size_t)(b * LK + kg0 + k)) * DH + 4 * d4);
            uint32_t h0, l0, h1, l1;
            bfsplit2(kv.x, kv.y, h0, l0);
            bfsplit2(kv.z, kv.w, h1, l1);
            *(uint32_t*)(Kh + k * 72 + 4 * d4)     = h0;
            *(uint32_t*)(Kh + k * 72 + 4 * d4 + 2) = h1;
            *(uint32_t*)(Kl + k * 72 + 4 * d4)     = l0;
            *(uint32_t*)(Kl + k * 72 + 4 * d4 + 2) = l1;
            float4 vv = *(const float4*)(V + ((size_t)(b * LK + kg0 + k)) * DH + 4 * d4);
            bfsplit2(vv.x, vv.y, h0, l0);
            bfsplit2(vv.z, vv.w, h1, l1);
            *(uint32_t*)(Vh + k * 72 + 4 * d4)     = h0;
            *(uint32_t*)(Vh + k * 72 + 4 * d4 + 2) = h1;
            *(uint32_t*)(Vl + k * 72 + 4 * d4)     = l0;
            *(uint32_t*)(Vl + k * 72 + 4 * d4 + 2) = l1;
        }
        __syncthreads();

        {
            uint32_t bh[8], bl[8];
            uint32_t kaddr = sKh + (uint32_t)((8 * ty + (tx & 7)) * 144 + (tx >> 3) * 16);
            ldsm_x4(bh,     kaddr);
            ldsm_x4(bh + 4, kaddr + 64);
            kaddr = sKl + (uint32_t)((8 * ty + (tx & 7)) * 144 + (tx >> 3) * 16);
            ldsm_x4(bl,     kaddr);
            ldsm_x4(bl + 4, kaddr + 64);

#pragma unroll
            for (int mt = 0; mt < 3; ++mt) {
                float accS[4] = {0.f, 0.f, 0.f, 0.f};
                uint32_t arow = (uint32_t)((mt * 16 + (tx & 15)) * 144 + (tx >> 4) * 16);
#pragma unroll
                for (int ks = 0; ks < 4; ++ks) {
                    uint32_t ah[4], al[4];
                    ldsm_x4(ah, sQh + arow + ks * 32);
                    ldsm_x4(al, sQl + arow + ks * 32);
                    mma_bf16(accS, ah, bh[2 * ks], bh[2 * ks + 1]);
                    mma_bf16(accS, ah, bl[2 * ks], bl[2 * ks + 1]);
                    mma_bf16(accS, al, bh[2 * ks], bh[2 * ks + 1]);
                }
                int r0 = mt * 16 + gid;
                *(float2*)&SP[r0 * 68 + 8 * ty + 2 * tig] =
                    make_float2(accS[0] * 0.125f, accS[1] * 0.125f);
                *(float2*)&SP[(r0 + 8) * 68 + 8 * ty + 2 * tig] =
                    make_float2(accS[2] * 0.125f, accS[3] * 0.125f);
            }
        }
        __syncthreads();

        float pr[6][2], fnew[6];
#pragma unroll
        for (int i = 0; i < 6; ++i) {
            int u = 6 * ty + i;
            float2 sv = *(const float2*)&SP[u * 68 + 2 * tx];
            float mx = fmaxf(sv.x, sv.y);
#pragma unroll
            for (int off = 16; off > 0; off >>= 1)
                mx = fmaxf(mx, __shfl_xor_sync(0xffffffffu, mx, off));
            float mn = fmaxf(mrun[i], mx);
            float f  = __expf(mrun[i] - mn);
            float p0 = __expf(sv.x - mn);
            float p1 = __expf(sv.y - mn);
            float ps = p0 + p1;
#pragma unroll
            for (int off = 16; off > 0; off >>= 1)
                ps += __shfl_xor_sync(0xffffffffu, ps, off);
            lrun[i] = lrun[i] * f + ps;
            mrun[i] = mn;
            fnew[i] = f;
            pr[i][0] = p0; pr[i][1] = p1;
            if (u < NU)
                *(float2*)(out_s + ((size_t)(b * NU + u)) * LK + kg0 + 2 * tx) = sv;
        }
        __syncthreads();

#pragma unroll
        for (int i = 0; i < 6; ++i) {
            int u = 6 * ty + i;
            uint32_t h, l;
            bfsplit2(pr[i][0], pr[i][1], h, l);
            *(uint32_t*)(Ph + u * 72 + 2 * tx) = h;
            *(uint32_t*)(Pl + u * 72 + 2 * tx) = l;
            if (tx == 0) fS[u] = fnew[i];
        }
        __syncthreads();

        {
            uint32_t bh[8], bl[8];
            uint32_t vaddr = sVh + (uint32_t)(tx * 144 + 16 * ty);
            ldsm_x4_t(bh,     vaddr);
            ldsm_x4_t(bh + 4, vaddr + 32 * 144);
            vaddr = sVl + (uint32_t)(tx * 144 + 16 * ty);
            ldsm_x4_t(bl,     vaddr);
            ldsm_x4_t(bl + 4, vaddr + 32 * 144);

#pragma unroll
            for (int mt = 0; mt < 3; ++mt) {
                float f0 = fS[mt * 16 + gid];
                float f1 = fS[mt * 16 + gid + 8];
                oc[mt][0] *= f0; oc[mt][1] *= f0;
                oc[mt][2] *= f1; oc[mt][3] *= f1;
                uint32_t arow = (uint32_t)((mt * 16 + (tx & 15)) * 144 + (tx >> 4) * 16);
#pragma unroll
                for (int ks = 0; ks < 4; ++ks) {
                    uint32_t ph[4], pl2[4];
                    ldsm_x4(ph,  sPh + arow + ks * 32);
                    ldsm_x4(pl2, sPl + arow + ks * 32);
                    mma_bf16(oc[mt], ph,  bh[2 * ks], bh[2 * ks + 1]);
                    mma_bf16(oc[mt], ph,  bl[2 * ks], bl[2 * ks + 1]);
                    mma_bf16(oc[mt], pl2, bh[2 * ks], bh[2 * ks + 1]);
                }
            }
        }
    }

    if (tx == 0) {
#pragma unroll
        for (int i = 0; i < 6; ++i) {
            int u = 6 * ty + i;
            g_pm[(b * NCHUNK + chunk) * NUP + u] = mrun[i];
            g_pl[(b * NCHUNK + chunk) * NUP + u] = lrun[i];
        }
    }
#pragma unroll
    for (int mt = 0; mt < 3; ++mt) {
        int r0 = mt * 16 + gid;
        *(float2*)&g_pacc[((size_t)(b * NCHUNK + chunk) * NUP + r0) * DH + 8 * ty + 2 * tig] =
            make_float2(oc[mt][0], oc[mt][1]);
        *(float2*)&g_pacc[((size_t)(b * NCHUNK + chunk) * NUP + r0 + 8) * DH + 8 * ty + 2 * tig] =
            make_float2(oc[mt][2], oc[mt][3]);
    }
}

// ---------------- kernel 8: combine split-softmax partials ----------------
__global__ void k_combine(float* __restrict__ out_o) {
    int u = blockIdx.x;
    int b = blockIdx.y;
    int d = threadIdx.x;
    float gm = -INFINITY;
    for (int c = 0; c < NCHUNK; ++c)
        gm = fmaxf(gm, g_pm[(b * NCHUNK + c) * NUP + u]);
    float L = 0.f, a = 0.f;
    for (int c = 0; c < NCHUNK; ++c) {
        float w = __expf(g_pm[(b * NCHUNK + c) * NUP + u] - gm);
        L += g_pl[(b * NCHUNK + c) * NUP + u] * w;
        a += g_pacc[((size_t)(b * NCHUNK + c) * NUP + u) * DH + d] * w;
    }
    out_o[(b * NU + u) * DH + d] = a / L;
}

// ---------------- launch ----------------
extern "C" void kernel_launch(void* const* d_in, const int* in_sizes, int n_in,
                              void* d_out, int out_size) {
    const float* q  = (const float*)d_in[0];
    const float* K  = (const float*)d_in[1];
    const float* V  = (const float*)d_in[2];
    const int* idx  = (const int*)d_in[3];
    float* out_o = (float*)d_out;                  // attn_output [8,45,64]
    float* out_s = out_o + NB * NU * DH;           // attn_scores [8,45,32768]

    (void)in_sizes; (void)n_in; (void)out_size;

    const int smem_attn  = 48 * 72 * 2 * 2 + 64 * 72 * 2 * 2 * 2 + 13824 + 192;  // 64704
    const int smem_exact = (KROWS * 68 + 128 * 68) * 4;                          // 82688
    cudaFuncSetAttribute(k_attn,    cudaFuncAttributeMaxDynamicSharedMemorySize, smem_attn);
    cudaFuncSetAttribute(k_M_exact, cudaFuncAttributeMaxDynamicSharedMemorySize, smem_exact);

    k_dedup<<<1, 1024>>>(idx);
    k_gather<<<NB * GPB, 256>>>(K);
    k_ksum2<<<NB, 64>>>();
    k_M_mma<<<dim3(LQ / 128, NB), 256>>>(q);
    k_thresh<<<NB, 512>>>();
    k_M_exact<<<dim3(NSPLIT, NB), 256, smem_exact>>>(q, K);
    k_select<<<NB, 256>>>(q);
    k_attn<<<dim3(NCHUNK, NB), 256, smem_attn>>>(q, K, V, out_s);
    k_combine<<<dim3(NU, NB), 64>>>(out_o);
}